// round 9
// baseline (speedup 1.0000x reference)
#include <cuda_runtime.h>
#include <math.h>
#include <stdint.h>

// -------- problem constants --------
#define BSZ   16384
#define INDIM 64
#define DENC  512
#define NE    2048
#define PBAS  12
#define BP    (BSZ*PBAS)          /* 196608 */
#define ZDIM  (INDIM*PBAS)        /* 768    */

// output layout: [loss, x_hat(B*64), perplexity, idx(BP), coeff(BP)]
#define OFF_LOSS  0
#define OFF_XHAT  1
#define OFF_PERP  (1 + BSZ*INDIM)
#define OFF_IDX   (OFF_PERP + 1)
#define OFF_COEFF (OFF_IDX + BP)

// -------- device scratch (static; referenced ONLY from device code) --------
__device__ __align__(16) float  g_h[BSZ*DENC];
__device__ __align__(16) float  g_t[BSZ*DENC];
__device__ __align__(16) float  g_z[BSZ*ZDIM];
__device__ __align__(16) float  g_enorm[NE];
__device__ int    g_idx[BP];
__device__ int    g_counts[NE];
__device__ double g_lossp[2048];

// packed dual-FMA: two independent rn fmas per instruction (bit-exact per lane)
__device__ __forceinline__ void fma2(unsigned long long& acc,
                                     unsigned long long a, unsigned long long b) {
    asm("fma.rn.f32x2 %0, %1, %2, %0;" : "+l"(acc) : "l"(a), "l"(b));
}
__device__ __forceinline__ float2 u2f(unsigned long long u) {
    float2 f;
    asm("mov.b64 {%0, %1}, %2;" : "=f"(f.x), "=f"(f.y) : "l"(u));
    return f;
}

// ======================= zero counts =======================
__global__ void k_zero() {
    int t = blockIdx.x * blockDim.x + threadIdx.x;
    if (t < NE) g_counts[t] = 0;
}

// ======================= GEMM: C = A(MxK)@B(KxN) + bias (f32x2) ============
// MODE 0: A = arg (x), C = g_h ; MODE 1: A = g_h, C = g_t ; MODE 2: A = g_h, C = g_z
// 128x128 tile, k-tile 32, 256 threads, 8x8 micro-tile via 32 fma.rn.f32x2.
// A stored DUPLICATED in smem ({a,a} pairs) so no packing MOVs are needed.
#define GA 264   /* dup A row stride (256 + 8 pad) */
#define GB 132
#define GEMM_SMEM ((32*GA + 32*GB) * 4)
template<int MODE>
__global__ __launch_bounds__(256, 2)
void k_gemm(const float* __restrict__ Ain, const float* __restrict__ Bm,
            const float* __restrict__ bias, int N, int K) {
    const float* A = (MODE == 0) ? Ain : g_h;
    float*       C = (MODE == 0) ? g_h : ((MODE == 1) ? g_t : g_z);

    extern __shared__ __align__(16) float smg[];
    float* sAd = smg;              // [32][GA]  dup pairs: col 2m, 2m+1
    float* sB  = smg + 32*GA;      // [32][GB]

    const int tid = threadIdx.x;
    const int tx = tid & 15, ty = tid >> 4;
    const int m0 = blockIdx.y * 128;
    const int n0 = blockIdx.x * 128;

    unsigned long long acc2[8][4];
#pragma unroll
    for (int i = 0; i < 8; i++)
#pragma unroll
        for (int j = 0; j < 4; j++) acc2[i][j] = 0ull;

    for (int kt = 0; kt < K; kt += 32) {
        {   // A tile -> transposed + duplicated
            int r  = tid >> 3;
            int kq = (tid & 7) << 2;
#pragma unroll
            for (int p = 0; p < 4; p++) {
                const float4 v = *(const float4*)(A + (size_t)(m0 + p*32 + r) * K + kt + kq);
                int c = 2*(p*32 + r);
                *(float2*)(&sAd[(kq+0)*GA + c]) = make_float2(v.x, v.x);
                *(float2*)(&sAd[(kq+1)*GA + c]) = make_float2(v.y, v.y);
                *(float2*)(&sAd[(kq+2)*GA + c]) = make_float2(v.z, v.z);
                *(float2*)(&sAd[(kq+3)*GA + c]) = make_float2(v.w, v.w);
            }
        }
        {   // B tile sB[k][n]
            int r  = tid >> 5;
            int cq = (tid & 31) << 2;
#pragma unroll
            for (int p = 0; p < 4; p++) {
                const float4 v = *(const float4*)(Bm + (size_t)(kt + p*8 + r) * N + n0 + cq);
                *(float4*)(&sB[(p*8 + r)*GB + cq]) = v;
            }
        }
        __syncthreads();
#pragma unroll 8
        for (int kk = 0; kk < 32; kk++) {
            const ulonglong2* ap = (const ulonglong2*)(&sAd[kk*GA + ty*16]);
            ulonglong2 A0 = ap[0], A1 = ap[1], A2 = ap[2], A3 = ap[3];
            const ulonglong2* bp = (const ulonglong2*)(&sB[kk*GB + tx*8]);
            ulonglong2 B0 = bp[0], B1 = bp[1];
            unsigned long long ad[8] = {A0.x, A0.y, A1.x, A1.y, A2.x, A2.y, A3.x, A3.y};
            unsigned long long bd[4] = {B0.x, B0.y, B1.x, B1.y};
#pragma unroll
            for (int i = 0; i < 8; i++)
#pragma unroll
                for (int j = 0; j < 4; j++)
                    fma2(acc2[i][j], ad[i], bd[j]);
        }
        __syncthreads();
    }
#pragma unroll
    for (int i = 0; i < 8; i++) {
        int m = m0 + ty*8 + i;
#pragma unroll
        for (int j = 0; j < 4; j++) {
            int n = n0 + tx*8 + 2*j;
            float2 v = u2f(acc2[i][j]);
            C[(size_t)m * N + n]     = __fadd_rn(v.x, bias[n]);
            C[(size_t)m * N + n + 1] = __fadd_rn(v.y, bias[n + 1]);
        }
    }
}

// ======================= h = h + relu(LN(t)*g + beta) =======================
__global__ void k_ln(const float* __restrict__ gw, const float* __restrict__ bw) {
    __shared__ float red[128];
    const int row = blockIdx.x, tid = threadIdx.x;
    const float* tr = g_t + (size_t)row * DENC;
    float*       hr = g_h + (size_t)row * DENC;

    float v[4], hv[4];
#pragma unroll
    for (int c = 0; c < 4; c++) { v[c] = tr[tid + c*128]; hv[c] = hr[tid + c*128]; }

    float s = (v[0] + v[1]) + (v[2] + v[3]);
    red[tid] = s; __syncthreads();
#pragma unroll
    for (int o = 64; o > 0; o >>= 1) { if (tid < o) red[tid] += red[tid + o]; __syncthreads(); }
    float mu = red[0] * (1.0f / 512.0f);
    __syncthreads();

    float s2 = 0.0f;
#pragma unroll
    for (int c = 0; c < 4; c++) { float d = v[c] - mu; s2 = __fadd_rn(s2, __fmul_rn(d, d)); }
    red[tid] = s2; __syncthreads();
#pragma unroll
    for (int o = 64; o > 0; o >>= 1) { if (tid < o) red[tid] += red[tid + o]; __syncthreads(); }
    float var  = red[0] * (1.0f / 512.0f);
    float rstd = 1.0f / sqrtf(__fadd_rn(var, 1e-5f));

#pragma unroll
    for (int c = 0; c < 4; c++) {
        int col = tid + c*128;
        float o = __fadd_rn(__fmul_rn(__fmul_rn(__fsub_rn(v[c], mu), rstd), gw[col]), bw[col]);
        hr[col] = __fadd_rn(hv[c], fmaxf(o, 0.0f));
    }
}

// ======================= codebook squared norms =======================
__global__ void k_enorm(const float* __restrict__ emb) {
    int k = blockIdx.x * blockDim.x + threadIdx.x;
    if (k < NE) {
        const float* e = emb + (size_t)k * 64;
        float s = 0.0f;
        for (int i = 0; i < 64; i++) s = __fadd_rn(s, __fmul_rn(e[i], e[i]));
        g_enorm[k] = s;
    }
}

// ======================= fused distance + argmin (f32x2) =======================
// d = fl( fl(zn + en) - 2*dot ), dot = strictly k-ascending chain (per lane).
// z-tile duplicated in smem; per-thread register minima + u64 shfl reduction.
#define DZD 264   /* dup z row stride */
#define DE  132
#define DIST_SMEM ((64*DZD + 64*DE + 256) * 4)
__global__ __launch_bounds__(256, 2)
void k_dist(const float* __restrict__ emb, float* __restrict__ out) {
    extern __shared__ __align__(16) float smd[];
    float* sZd = smd;                  // [64][DZD] dup pairs
    float* sE  = smd + 64*DZD;         // [64][DE]
    float* zn  = sE + 64*DE;           // [128]
    float* en  = zn + 128;             // [128]

    const int tid = threadIdx.x;
    const int tx = tid & 15, ty = tid >> 4;
    const int m0 = blockIdx.x * 128;

    // load z tile transposed + duplicated: sZd[k][2r],[2r+1]
    {
        int r4 = tid >> 2, q = tid & 3;
#pragma unroll
        for (int p = 0; p < 2; p++) {
            int r = p*64 + r4;
            const float4* src = (const float4*)(g_z + (size_t)(m0 + r) * 64) + q*4;
#pragma unroll
            for (int s = 0; s < 4; s++) {
                float4 v = src[s];
                int k = q*16 + s*4;
                int c = 2*r;
                *(float2*)(&sZd[(k+0)*DZD + c]) = make_float2(v.x, v.x);
                *(float2*)(&sZd[(k+1)*DZD + c]) = make_float2(v.y, v.y);
                *(float2*)(&sZd[(k+2)*DZD + c]) = make_float2(v.z, v.z);
                *(float2*)(&sZd[(k+3)*DZD + c]) = make_float2(v.w, v.w);
            }
        }
    }
    __syncthreads();
    if (tid < 128) {
        float s = 0.0f;
        for (int k = 0; k < 64; k++) {
            float zv = sZd[k*DZD + 2*tid];
            s = __fadd_rn(s, __fmul_rn(zv, zv));
        }
        zn[tid] = s;
    }

    unsigned long long best[8];
#pragma unroll
    for (int i = 0; i < 8; i++) best[i] = 0xFFFFFFFFFFFFFFFFull;

    for (int ch = 0; ch < 16; ch++) {
        __syncthreads();
        const int c0 = ch * 128;
        {   // e tile transposed: sE[k][r]
            int r4 = tid >> 2, q = tid & 3;
#pragma unroll
            for (int p = 0; p < 2; p++) {
                int r = p*64 + r4;
                const float4* src = (const float4*)(emb + (size_t)(c0 + r) * 64) + q*4;
#pragma unroll
                for (int s = 0; s < 4; s++) {
                    float4 v = src[s];
                    int k = q*16 + s*4;
                    sE[(k+0)*DE + r] = v.x; sE[(k+1)*DE + r] = v.y;
                    sE[(k+2)*DE + r] = v.z; sE[(k+3)*DE + r] = v.w;
                }
            }
            if (tid < 128) en[tid] = g_enorm[c0 + tid];
        }
        __syncthreads();

        unsigned long long acc2[8][4];
#pragma unroll
        for (int i = 0; i < 8; i++)
#pragma unroll
            for (int j = 0; j < 4; j++) acc2[i][j] = 0ull;

#pragma unroll 4
        for (int kk = 0; kk < 64; kk++) {
            const ulonglong2* ap = (const ulonglong2*)(&sZd[kk*DZD + ty*16]);
            ulonglong2 A0 = ap[0], A1 = ap[1], A2 = ap[2], A3 = ap[3];
            const ulonglong2* bp = (const ulonglong2*)(&sE[kk*DE + tx*8]);
            ulonglong2 B0 = bp[0], B1 = bp[1];
            unsigned long long ad[8] = {A0.x, A0.y, A1.x, A1.y, A2.x, A2.y, A3.x, A3.y};
            unsigned long long bd[4] = {B0.x, B0.y, B1.x, B1.y};
#pragma unroll
            for (int i = 0; i < 8; i++)
#pragma unroll
                for (int j = 0; j < 4; j++)
                    fma2(acc2[i][j], ad[i], bd[j]);
        }

        // fold chunk minima into register best (keys: packed d|index, lowest wins)
#pragma unroll
        for (int i = 0; i < 8; i++) {
            float znr = zn[ty*8 + i];
#pragma unroll
            for (int j = 0; j < 4; j++) {
                float2 dot = u2f(acc2[i][j]);
                int cj = c0 + tx*8 + 2*j;
                float S0 = __fadd_rn(znr, en[tx*8 + 2*j]);
                float S1 = __fadd_rn(znr, en[tx*8 + 2*j + 1]);
                float d0 = __fsub_rn(S0, __fmul_rn(2.0f, dot.x));
                float d1 = __fsub_rn(S1, __fmul_rn(2.0f, dot.y));
                unsigned long long k0 =
                    ((unsigned long long)__float_as_uint(d0) << 32) | (unsigned)cj;
                unsigned long long k1 =
                    ((unsigned long long)__float_as_uint(d1) << 32) | (unsigned)(cj + 1);
                if (k0 < best[i]) best[i] = k0;
                if (k1 < best[i]) best[i] = k1;
            }
        }
    }

    // reduce across the 16 tx lanes (xor offsets stay within each 16-lane half)
#pragma unroll
    for (int i = 0; i < 8; i++) {
#pragma unroll
        for (int o = 8; o > 0; o >>= 1) {
            unsigned long long other = __shfl_xor_sync(0xffffffffu, best[i], o, 32);
            if (other < best[i]) best[i] = other;
        }
    }
    if (tx == 0) {
#pragma unroll
        for (int i = 0; i < 8; i++) {
            int row = ty*8 + i;
            int w = (int)(best[i] & 0xFFFFFFFFull);
            g_idx[m0 + row] = w;
            out[OFF_IDX + m0 + row] = (float)w;
            atomicAdd(&g_counts[w], 1);
        }
    }
}

// ======================= per-block pinv solve (warp per block) =======================
__global__ __launch_bounds__(256)
void k_solve(const float* __restrict__ emb, const float* __restrict__ x,
             float* __restrict__ out) {
    __shared__ float  sA[8][12][64];
    __shared__ float  sx[8][64];
    __shared__ double sG[8][12][12];
    __shared__ double sr[8][12];
    __shared__ double sy[8][12];
    __shared__ double sc[8][12];
    __shared__ int    sidx[8][12], sgrp[8][12], smult[8][12], scol[8][12];
    __shared__ int    su[8];
    __shared__ double wls[8];

    const int lane = threadIdx.x & 31;
    const int w    = threadIdx.x >> 5;
    const size_t b = (size_t)blockIdx.x * 8 + w;

    if (lane < 12) sidx[w][lane] = g_idx[b*12 + lane];
    __syncwarp();
    if (lane == 0) {   // dedup (serial, tiny)
        int u = 0;
        for (int j = 0; j < 12; j++) {
            int v = sidx[w][j], q = -1;
            for (int t = 0; t < u; t++)
                if (sidx[w][scol[w][t]] == v) { q = t; break; }
            if (q < 0) { q = u; scol[w][u] = j; smult[w][u] = 0; u++; }
            sgrp[w][j] = q; smult[w][q]++;
        }
        su[w] = u;
    }
    __syncwarp();

    // gather: STE columns A = fl(z + fl(zq - z)); loss from pre-STE zq vs z
    {
        double ls = 0.0;
        const float* zr = g_z + b * 768;
        for (int t = lane; t < 768; t += 32) {
            int j = t >> 6, i = t & 63;
            float a = emb[(size_t)sidx[w][j]*64 + i];
            float z = zr[t];
            double df = (double)a - (double)z;
            ls += df*df;
            sA[w][j][i] = __fadd_rn(z, __fsub_rn(a, z));
        }
#pragma unroll
        for (int o = 16; o; o >>= 1) ls += __shfl_down_sync(0xffffffffu, ls, o);
        if (lane == 0) wls[w] = ls;
    }
    for (int t = lane; t < 64; t += 32) sx[w][t] = x[b*64 + t];
    __syncwarp();

    const int u = su[w];
    const int npair = u*(u+1)/2;
    for (int t = lane; t < npair + u; t += 32) {
        if (t < npair) {
            int qa = 0, rem = t;
            while (rem >= u - qa) { rem -= (u - qa); qa++; }
            int qb = qa + rem;
            const float* ca = sA[w][scol[w][qa]];
            const float* cb = sA[w][scol[w][qb]];
            double s = 0.0;
            for (int k = 0; k < 64; k++) s = fma((double)ca[k], (double)cb[k], s);
            sG[w][qa][qb] = s; sG[w][qb][qa] = s;
        } else {
            int q = t - npair;
            const float* ca = sA[w][scol[w][q]];
            double s = 0.0;
            for (int k = 0; k < 64; k++) s = fma((double)ca[k], (double)sx[w][k], s);
            sr[w][q] = s;
        }
    }
    __syncwarp();

    // fp64 Cholesky (lower, in place)
    for (int p = 0; p < u; p++) {
        if (lane == 0) sG[w][p][p] = sqrt(sG[w][p][p]);
        __syncwarp();
        double lpp = sG[w][p][p];
        if (lane > p && lane < u) sG[w][lane][p] /= lpp;
        __syncwarp();
        int m = u - p - 1;
        int tot = m*(m+1)/2;
        for (int t = lane; t < tot; t += 32) {
            int a = 0, rem = t;
            while (rem >= m - a) { rem -= (m - a); a++; }
            int j = p + 1 + a;
            int i = j + rem;
            sG[w][i][j] -= sG[w][i][p]*sG[w][j][p];
        }
        __syncwarp();
    }
    if (lane == 0) {   // triangular solves (tiny)
        for (int p = 0; p < u; p++) {
            double s = sr[w][p];
            for (int t = 0; t < p; t++) s -= sG[w][p][t]*sy[w][t];
            sy[w][p] = s / sG[w][p][p];
        }
        for (int p = u - 1; p >= 0; p--) {
            double s = sy[w][p];
            for (int t = p + 1; t < u; t++) s -= sG[w][t][p]*sy[w][t];
            sy[w][p] = s / sG[w][p][p];
        }
    }
    __syncwarp();
    // min-norm split across duplicates -> coeff
    if (lane < 12) {
        int q = sgrp[w][lane];
        double c = sy[w][q] / (double)smult[w][q];
        out[OFF_COEFF + b*12 + lane] = (float)c;
        sc[w][lane] = c;
    }
    __syncwarp();
    // x_hat = A @ coeff
    for (int i = lane; i < 64; i += 32) {
        double s = 0.0;
#pragma unroll
        for (int j = 0; j < 12; j++) s = fma((double)sA[w][j][i], sc[w][j], s);
        out[OFF_XHAT + b*64 + i] = (float)s;
    }

    __syncthreads();
    if (threadIdx.x == 0) {
        double s = 0.0;
        for (int k = 0; k < 8; k++) s += wls[k];
        g_lossp[blockIdx.x] = s;
    }
}

// ======================= scalars: loss, perplexity =======================
__global__ void k_final(float* __restrict__ out) {
    __shared__ double red[256];
    const int tid = threadIdx.x;
    double s = 0.0;
    for (int k = tid; k < NE; k += 256) {
        double p = (double)g_counts[k] / (double)BP;
        s += p * log(p + 1e-10);
    }
    red[tid] = s; __syncthreads();
    for (int o = 128; o; o >>= 1) { if (tid < o) red[tid] += red[tid + o]; __syncthreads(); }
    double perp = exp(-red[0]);
    __syncthreads();

    double ls = 0.0;
    for (int k = tid; k < 2048; k += 256) ls += g_lossp[k];
    red[tid] = ls; __syncthreads();
    for (int o = 128; o; o >>= 1) { if (tid < o) red[tid] += red[tid + o]; __syncthreads(); }

    if (tid == 0) {
        out[OFF_PERP] = (float)perp;
        out[OFF_LOSS] = (float)(red[0] * 1.25 / ((double)BP * 64.0));
    }
}

// ======================= launch =======================
extern "C" void kernel_launch(void* const* d_in, const int* in_sizes, int n_in,
                              void* d_out, int out_size) {
    const float* x      = (const float*)d_in[0];
    const float* enc_w1 = (const float*)d_in[1];
    const float* enc_b1 = (const float*)d_in[2];
    const float* res_w  = (const float*)d_in[3];
    const float* res_b  = (const float*)d_in[4];
    const float* res_g  = (const float*)d_in[5];
    const float* res_bt = (const float*)d_in[6];
    const float* enc_w2 = (const float*)d_in[7];
    const float* enc_b2 = (const float*)d_in[8];
    const float* emb    = (const float*)d_in[9];
    float* out = (float*)d_out;

    cudaFuncSetAttribute(k_gemm<0>, cudaFuncAttributeMaxDynamicSharedMemorySize, GEMM_SMEM);
    cudaFuncSetAttribute(k_gemm<1>, cudaFuncAttributeMaxDynamicSharedMemorySize, GEMM_SMEM);
    cudaFuncSetAttribute(k_gemm<2>, cudaFuncAttributeMaxDynamicSharedMemorySize, GEMM_SMEM);
    cudaFuncSetAttribute(k_dist,    cudaFuncAttributeMaxDynamicSharedMemorySize, DIST_SMEM);

    k_zero<<<(NE + 255)/256, 256>>>();

    // encoder: Linear(64->512) -> 2x shared ResBlock -> Linear(512->768)
    k_gemm<0><<<dim3(4, 128), 256, GEMM_SMEM>>>(x, enc_w1, enc_b1, DENC, INDIM);
    for (int r = 0; r < 2; r++) {
        k_gemm<1><<<dim3(4, 128), 256, GEMM_SMEM>>>(nullptr, res_w, res_b, DENC, DENC);
        k_ln<<<BSZ, 128>>>(res_g, res_bt);
    }
    k_gemm<2><<<dim3(6, 128), 256, GEMM_SMEM>>>(nullptr, enc_w2, enc_b2, ZDIM, DENC);

    k_enorm<<<NE/128, 128>>>(emb);
    k_dist<<<BP/128, 256, DIST_SMEM>>>(emb, out);
    k_solve<<<BSZ/8, 256>>>(emb, x, out);
    k_final<<<1, 256>>>(out);
}

// round 10
// speedup vs baseline: 1.1064x; 1.1064x over previous
#include <cuda_runtime.h>
#include <math.h>
#include <stdint.h>

// -------- problem constants --------
#define BSZ   16384
#define INDIM 64
#define DENC  512
#define NE    2048
#define PBAS  12
#define BP    (BSZ*PBAS)          /* 196608 */
#define ZDIM  (INDIM*PBAS)        /* 768    */

// output layout: [loss, x_hat(B*64), perplexity, idx(BP), coeff(BP)]
#define OFF_LOSS  0
#define OFF_XHAT  1
#define OFF_PERP  (1 + BSZ*INDIM)
#define OFF_IDX   (OFF_PERP + 1)
#define OFF_COEFF (OFF_IDX + BP)

// -------- device scratch (static; referenced ONLY from device code) --------
__device__ __align__(16) float  g_h[BSZ*DENC];
__device__ __align__(16) float  g_t[BSZ*DENC];
__device__ __align__(16) float  g_z[BSZ*ZDIM];
__device__ __align__(16) float  g_enorm[NE];
__device__ unsigned long long   g_key[BP];
__device__ int    g_idx[BP];
__device__ int    g_counts[NE];
__device__ double g_lossp[2048];

// ======================= init: counts + keys =======================
__global__ void k_init() {
    int t = blockIdx.x * blockDim.x + threadIdx.x;
    if (t < NE) g_counts[t] = 0;
    if (t < BP) g_key[t] = 0xFFFFFFFFFFFFFFFFull;
}

// ======================= GEMM: C = A(MxK)@B(KxN) + bias =======================
// MODE 0: A = arg (x), C = g_h ; MODE 1: A = g_h, C = g_t ; MODE 2: A = g_h, C = g_z
// 128x128 tile, k-tile 32, 256 threads, 8x8 micro-tile. Single k-ascending
// fmaf accumulator per output (bit-exact vs reference). Register prefetch of
// the next k-tile overlaps LDG latency with current-tile compute.
template<int MODE>
__global__ __launch_bounds__(256, 2)
void k_gemm(const float* __restrict__ Ain, const float* __restrict__ Bm,
            const float* __restrict__ bias, int N, int K) {
    const float* A = (MODE == 0) ? Ain : g_h;
    float*       C = (MODE == 0) ? g_h : ((MODE == 1) ? g_t : g_z);

    __shared__ __align__(16) float sA[32][132];
    __shared__ __align__(16) float sB[32][132];
    const int tid = threadIdx.x;
    const int tx = tid & 15, ty = tid >> 4;
    const int m0 = blockIdx.y * 128;
    const int n0 = blockIdx.x * 128;

    const int ra  = tid >> 3;          // A: row group 0..31
    const int kq  = (tid & 7) << 2;    // A: k quad
    const int rb  = tid >> 5;          // B: k row 0..7
    const int cq  = (tid & 31) << 2;   // B: col quad

    float acc[8][8];
#pragma unroll
    for (int i = 0; i < 8; i++)
#pragma unroll
        for (int j = 0; j < 8; j++) acc[i][j] = 0.0f;

    // prefetch k-tile 0
    float4 va[4], vb[4];
#pragma unroll
    for (int p = 0; p < 4; p++)
        va[p] = *(const float4*)(A + (size_t)(m0 + p*32 + ra) * K + kq);
#pragma unroll
    for (int p = 0; p < 4; p++)
        vb[p] = *(const float4*)(Bm + (size_t)(p*8 + rb) * N + n0 + cq);

    for (int kt = 0; kt < K; kt += 32) {
        // store prefetched tile
#pragma unroll
        for (int p = 0; p < 4; p++) {
            int m = p*32 + ra;
            sA[kq+0][m] = va[p].x; sA[kq+1][m] = va[p].y;
            sA[kq+2][m] = va[p].z; sA[kq+3][m] = va[p].w;
            *(float4*)(&sB[p*8 + rb][cq]) = vb[p];
        }
        // prefetch next k-tile (overlaps with compute below)
        if (kt + 32 < K) {
#pragma unroll
            for (int p = 0; p < 4; p++)
                va[p] = *(const float4*)(A + (size_t)(m0 + p*32 + ra) * K + kt + 32 + kq);
#pragma unroll
            for (int p = 0; p < 4; p++)
                vb[p] = *(const float4*)(Bm + (size_t)(kt + 32 + p*8 + rb) * N + n0 + cq);
        }
        __syncthreads();
#pragma unroll 8
        for (int kk = 0; kk < 32; kk++) {
            float a[8], b[8];
            *(float4*)(a)     = *(const float4*)(&sA[kk][ty*8]);
            *(float4*)(a + 4) = *(const float4*)(&sA[kk][ty*8 + 4]);
            *(float4*)(b)     = *(const float4*)(&sB[kk][tx*8]);
            *(float4*)(b + 4) = *(const float4*)(&sB[kk][tx*8 + 4]);
#pragma unroll
            for (int i = 0; i < 8; i++)
#pragma unroll
                for (int j = 0; j < 8; j++)
                    acc[i][j] = __fmaf_rn(a[i], b[j], acc[i][j]);
        }
        __syncthreads();
    }
#pragma unroll
    for (int i = 0; i < 8; i++) {
        int m = m0 + ty*8 + i;
#pragma unroll
        for (int j = 0; j < 8; j++) {
            int n = n0 + tx*8 + j;
            C[(size_t)m * N + n] = __fadd_rn(acc[i][j], bias[n]);
        }
    }
}

// ======================= h = h + relu(LN(t)*g + beta) =======================
__global__ void k_ln(const float* __restrict__ gw, const float* __restrict__ bw) {
    __shared__ float red[128];
    const int row = blockIdx.x, tid = threadIdx.x;
    const float* tr = g_t + (size_t)row * DENC;
    float*       hr = g_h + (size_t)row * DENC;

    float v[4], hv[4];
#pragma unroll
    for (int c = 0; c < 4; c++) { v[c] = tr[tid + c*128]; hv[c] = hr[tid + c*128]; }

    float s = (v[0] + v[1]) + (v[2] + v[3]);
    red[tid] = s; __syncthreads();
#pragma unroll
    for (int o = 64; o > 0; o >>= 1) { if (tid < o) red[tid] += red[tid + o]; __syncthreads(); }
    float mu = red[0] * (1.0f / 512.0f);
    __syncthreads();

    float s2 = 0.0f;
#pragma unroll
    for (int c = 0; c < 4; c++) { float d = v[c] - mu; s2 = __fadd_rn(s2, __fmul_rn(d, d)); }
    red[tid] = s2; __syncthreads();
#pragma unroll
    for (int o = 64; o > 0; o >>= 1) { if (tid < o) red[tid] += red[tid + o]; __syncthreads(); }
    float var  = red[0] * (1.0f / 512.0f);
    float rstd = 1.0f / sqrtf(__fadd_rn(var, 1e-5f));

#pragma unroll
    for (int c = 0; c < 4; c++) {
        int col = tid + c*128;
        float o = __fadd_rn(__fmul_rn(__fmul_rn(__fsub_rn(v[c], mu), rstd), gw[col]), bw[col]);
        hr[col] = __fadd_rn(hv[c], fmaxf(o, 0.0f));
    }
}

// ======================= codebook squared norms =======================
__global__ void k_enorm(const float* __restrict__ emb) {
    int k = blockIdx.x * blockDim.x + threadIdx.x;
    if (k < NE) {
        const float* e = emb + (size_t)k * 64;
        float s = 0.0f;
        for (int i = 0; i < 64; i++) s = __fadd_rn(s, __fmul_rn(e[i], e[i]));
        g_enorm[k] = s;
    }
}

// ======================= fused distance + argmin (code-split halves) ==========
// grid 3072: bx>>1 = row tile (128 rows), bx&1 = code half (1024 codes, 8 chunks).
// d = fl( fl(zn + en) - 2*dot ), dot = strictly k-ascending fmaf chain.
// Halves merged via atomicMin on packed u64 keys (order-independent min ==
// exact jnp.argmin with lowest-index tie-break).
#define DN 132
#define DIST_SMEM (((64*DN*2 + 256) * 4) + 128*16*8)
__global__ __launch_bounds__(256, 2)
void k_dist(const float* __restrict__ emb) {
    extern __shared__ __align__(16) unsigned char smraw[];
    float* sZ = (float*)smraw;                     // [64][DN]
    float* sE = sZ + 64*DN;                        // [64][DN]
    float* zn = sE + 64*DN;                        // [128]
    float* en = zn + 128;                          // [128]
    unsigned long long* skey = (unsigned long long*)(en + 128); // [128][16]

    const int tid = threadIdx.x;
    const int tx = tid & 15, ty = tid >> 4;
    const int m0    = (blockIdx.x >> 1) * 128;
    const int cbase = (blockIdx.x & 1) * 1024;

    const int r4 = tid >> 2, q = tid & 3;

    // load z tile transposed: sZ[k][r]
#pragma unroll
    for (int p = 0; p < 2; p++) {
        int r = p*64 + r4;
        const float4* src = (const float4*)(g_z + (size_t)(m0 + r) * 64) + q*4;
#pragma unroll
        for (int s = 0; s < 4; s++) {
            float4 v = src[s];
            int k = q*16 + s*4;
            sZ[(k+0)*DN + r] = v.x; sZ[(k+1)*DN + r] = v.y;
            sZ[(k+2)*DN + r] = v.z; sZ[(k+3)*DN + r] = v.w;
        }
    }
    // init per-(row, tx) min slot
#pragma unroll
    for (int i = 0; i < 8; i++)
        skey[(ty*8 + i)*16 + tx] = 0xFFFFFFFFFFFFFFFFull;

    // prefetch E chunk 0 into registers
    float4 ve[8];
#pragma unroll
    for (int p = 0; p < 2; p++) {
        const float4* src = (const float4*)(emb + (size_t)(cbase + p*64 + r4) * 64) + q*4;
#pragma unroll
        for (int s = 0; s < 4; s++) ve[p*4 + s] = src[s];
    }
    __syncthreads();
    if (tid < 128) {
        float s = 0.0f;
        for (int k = 0; k < 64; k++) {
            float zv = sZ[k*DN + tid];
            s = __fadd_rn(s, __fmul_rn(zv, zv));
        }
        zn[tid] = s;
    }

    for (int ch = 0; ch < 8; ch++) {
        const int c0 = cbase + ch * 128;
        // store prefetched E tile transposed: sE[k][r]
#pragma unroll
        for (int p = 0; p < 2; p++) {
            int r = p*64 + r4;
#pragma unroll
            for (int s = 0; s < 4; s++) {
                float4 v = ve[p*4 + s];
                int k = q*16 + s*4;
                sE[(k+0)*DN + r] = v.x; sE[(k+1)*DN + r] = v.y;
                sE[(k+2)*DN + r] = v.z; sE[(k+3)*DN + r] = v.w;
            }
        }
        if (tid < 128) en[tid] = g_enorm[c0 + tid];
        // prefetch next chunk (overlaps with compute below)
        if (ch < 7) {
#pragma unroll
            for (int p = 0; p < 2; p++) {
                const float4* src =
                    (const float4*)(emb + (size_t)(c0 + 128 + p*64 + r4) * 64) + q*4;
#pragma unroll
                for (int s = 0; s < 4; s++) ve[p*4 + s] = src[s];
            }
        }
        __syncthreads();

        float acc[8][8];
#pragma unroll
        for (int i = 0; i < 8; i++)
#pragma unroll
            for (int j = 0; j < 8; j++) acc[i][j] = 0.0f;

#pragma unroll 8
        for (int kk = 0; kk < 64; kk++) {
            float a[8], b[8];
            *(float4*)(a)     = *(const float4*)(sZ + kk*DN + ty*8);
            *(float4*)(a + 4) = *(const float4*)(sZ + kk*DN + ty*8 + 4);
            *(float4*)(b)     = *(const float4*)(sE + kk*DN + tx*8);
            *(float4*)(b + 4) = *(const float4*)(sE + kk*DN + tx*8 + 4);
#pragma unroll
            for (int i = 0; i < 8; i++)
#pragma unroll
                for (int j = 0; j < 8; j++)
                    acc[i][j] = __fmaf_rn(a[i], b[j], acc[i][j]);
        }

        float enr[8];
#pragma unroll
        for (int j = 0; j < 8; j++) enr[j] = en[tx*8 + j];
#pragma unroll
        for (int i = 0; i < 8; i++) {
            float znr = zn[ty*8 + i];
            unsigned long long k1 = 0xFFFFFFFFFFFFFFFFull;
#pragma unroll
            for (int j = 0; j < 8; j++) {
                float S = __fadd_rn(znr, enr[j]);                     // fl(zn+en)
                float d = __fsub_rn(S, __fmul_rn(2.0f, acc[i][j]));   // fl(S-2*dot)
                unsigned long long key =
                    ((unsigned long long)__float_as_uint(d) << 32) | (unsigned)(c0 + tx*8 + j);
                if (key < k1) k1 = key;
            }
            unsigned long long* sp = &skey[(ty*8 + i)*16 + tx];
            if (k1 < *sp) *sp = k1;
        }
        __syncthreads();
    }

    // per-row reduce over 16 slots, merge across halves via atomicMin
    if (tid < 128) {
        int row = tid;
        unsigned long long a1 = 0xFFFFFFFFFFFFFFFFull;
#pragma unroll
        for (int s = 0; s < 16; s++) {
            unsigned long long k = skey[row*16 + s];
            if (k < a1) a1 = k;
        }
        atomicMin(&g_key[m0 + row], a1);
    }
}

// ======================= key -> idx, counts, out =======================
__global__ void k_extract(float* __restrict__ out) {
    int t = blockIdx.x * blockDim.x + threadIdx.x;
    if (t < BP) {
        int w = (int)(g_key[t] & 0xFFFFFFFFull);
        g_idx[t] = w;
        out[OFF_IDX + t] = (float)w;
        atomicAdd(&g_counts[w], 1);
    }
}

// ======================= per-block pinv solve (warp per block) =======================
__global__ __launch_bounds__(256)
void k_solve(const float* __restrict__ emb, const float* __restrict__ x,
             float* __restrict__ out) {
    __shared__ float  sA[8][12][64];
    __shared__ float  sx[8][64];
    __shared__ double sG[8][12][12];
    __shared__ double sr[8][12];
    __shared__ double sy[8][12];
    __shared__ double sc[8][12];
    __shared__ int    sidx[8][12], sgrp[8][12], smult[8][12], scol[8][12];
    __shared__ int    su[8];
    __shared__ double wls[8];

    const int lane = threadIdx.x & 31;
    const int w    = threadIdx.x >> 5;
    const size_t b = (size_t)blockIdx.x * 8 + w;

    if (lane < 12) sidx[w][lane] = g_idx[b*12 + lane];
    __syncwarp();
    if (lane == 0) {   // dedup (serial, tiny)
        int u = 0;
        for (int j = 0; j < 12; j++) {
            int v = sidx[w][j], q = -1;
            for (int t = 0; t < u; t++)
                if (sidx[w][scol[w][t]] == v) { q = t; break; }
            if (q < 0) { q = u; scol[w][u] = j; smult[w][u] = 0; u++; }
            sgrp[w][j] = q; smult[w][q]++;
        }
        su[w] = u;
    }
    __syncwarp();

    // gather: STE columns A = fl(z + fl(zq - z)); loss from pre-STE zq vs z
    {
        double ls = 0.0;
        const float* zr = g_z + b * 768;
        for (int t = lane; t < 768; t += 32) {
            int j = t >> 6, i = t & 63;
            float a = emb[(size_t)sidx[w][j]*64 + i];
            float z = zr[t];
            double df = (double)a - (double)z;
            ls += df*df;
            sA[w][j][i] = __fadd_rn(z, __fsub_rn(a, z));
        }
#pragma unroll
        for (int o = 16; o; o >>= 1) ls += __shfl_down_sync(0xffffffffu, ls, o);
        if (lane == 0) wls[w] = ls;
    }
    for (int t = lane; t < 64; t += 32) sx[w][t] = x[b*64 + t];
    __syncwarp();

    const int u = su[w];
    const int npair = u*(u+1)/2;
    for (int t = lane; t < npair + u; t += 32) {
        if (t < npair) {
            int qa = 0, rem = t;
            while (rem >= u - qa) { rem -= (u - qa); qa++; }
            int qb = qa + rem;
            const float* ca = sA[w][scol[w][qa]];
            const float* cb = sA[w][scol[w][qb]];
            double s = 0.0;
            for (int k = 0; k < 64; k++) s = fma((double)ca[k], (double)cb[k], s);
            sG[w][qa][qb] = s; sG[w][qb][qa] = s;
        } else {
            int q2 = t - npair;
            const float* ca = sA[w][scol[w][q2]];
            double s = 0.0;
            for (int k = 0; k < 64; k++) s = fma((double)ca[k], (double)sx[w][k], s);
            sr[w][q2] = s;
        }
    }
    __syncwarp();

    // fp64 Cholesky (lower, in place)
    for (int p = 0; p < u; p++) {
        if (lane == 0) sG[w][p][p] = sqrt(sG[w][p][p]);
        __syncwarp();
        double lpp = sG[w][p][p];
        if (lane > p && lane < u) sG[w][lane][p] /= lpp;
        __syncwarp();
        int m = u - p - 1;
        int tot = m*(m+1)/2;
        for (int t = lane; t < tot; t += 32) {
            int a = 0, rem = t;
            while (rem >= m - a) { rem -= (m - a); a++; }
            int j = p + 1 + a;
            int i = j + rem;
            sG[w][i][j] -= sG[w][i][p]*sG[w][j][p];
        }
        __syncwarp();
    }
    if (lane == 0) {   // triangular solves (tiny)
        for (int p = 0; p < u; p++) {
            double s = sr[w][p];
            for (int t = 0; t < p; t++) s -= sG[w][p][t]*sy[w][t];
            sy[w][p] = s / sG[w][p][p];
        }
        for (int p = u - 1; p >= 0; p--) {
            double s = sy[w][p];
            for (int t = p + 1; t < u; t++) s -= sG[w][t][p]*sy[w][t];
            sy[w][p] = s / sG[w][p][p];
        }
    }
    __syncwarp();
    // min-norm split across duplicates -> coeff
    if (lane < 12) {
        int q2 = sgrp[w][lane];
        double c = sy[w][q2] / (double)smult[w][q2];
        out[OFF_COEFF + b*12 + lane] = (float)c;
        sc[w][lane] = c;
    }
    __syncwarp();
    // x_hat = A @ coeff
    for (int i = lane; i < 64; i += 32) {
        double s = 0.0;
#pragma unroll
        for (int j = 0; j < 12; j++) s = fma((double)sA[w][j][i], sc[w][j], s);
        out[OFF_XHAT + b*64 + i] = (float)s;
    }

    __syncthreads();
    if (threadIdx.x == 0) {
        double s = 0.0;
        for (int k = 0; k < 8; k++) s += wls[k];
        g_lossp[blockIdx.x] = s;
    }
}

// ======================= scalars: loss, perplexity =======================
__global__ void k_final(float* __restrict__ out) {
    __shared__ double red[256];
    const int tid = threadIdx.x;
    double s = 0.0;
    for (int k = tid; k < NE; k += 256) {
        double p = (double)g_counts[k] / (double)BP;
        s += p * log(p + 1e-10);
    }
    red[tid] = s; __syncthreads();
    for (int o = 128; o; o >>= 1) { if (tid < o) red[tid] += red[tid + o]; __syncthreads(); }
    double perp = exp(-red[0]);
    __syncthreads();

    double ls = 0.0;
    for (int k = tid; k < 2048; k += 256) ls += g_lossp[k];
    red[tid] = ls; __syncthreads();
    for (int o = 128; o; o >>= 1) { if (tid < o) red[tid] += red[tid + o]; __syncthreads(); }

    if (tid == 0) {
        out[OFF_PERP] = (float)perp;
        out[OFF_LOSS] = (float)(red[0] * 1.25 / ((double)BP * 64.0));
    }
}

// ======================= launch =======================
extern "C" void kernel_launch(void* const* d_in, const int* in_sizes, int n_in,
                              void* d_out, int out_size) {
    const float* x      = (const float*)d_in[0];
    const float* enc_w1 = (const float*)d_in[1];
    const float* enc_b1 = (const float*)d_in[2];
    const float* res_w  = (const float*)d_in[3];
    const float* res_b  = (const float*)d_in[4];
    const float* res_g  = (const float*)d_in[5];
    const float* res_bt = (const float*)d_in[6];
    const float* enc_w2 = (const float*)d_in[7];
    const float* enc_b2 = (const float*)d_in[8];
    const float* emb    = (const float*)d_in[9];
    float* out = (float*)d_out;

    cudaFuncSetAttribute(k_dist, cudaFuncAttributeMaxDynamicSharedMemorySize, DIST_SMEM);

    k_init<<<(BP + 255)/256, 256>>>();

    // encoder: Linear(64->512) -> 2x shared ResBlock -> Linear(512->768)
    k_gemm<0><<<dim3(4, 128), 256>>>(x, enc_w1, enc_b1, DENC, INDIM);
    for (int r = 0; r < 2; r++) {
        k_gemm<1><<<dim3(4, 128), 256>>>(nullptr, res_w, res_b, DENC, DENC);
        k_ln<<<BSZ, 128>>>(res_g, res_bt);
    }
    k_gemm<2><<<dim3(6, 128), 256>>>(nullptr, enc_w2, enc_b2, ZDIM, DENC);

    k_enorm<<<NE/128, 128>>>(emb);
    k_dist<<<(BP/128)*2, 256, DIST_SMEM>>>(emb);
    k_extract<<<(BP + 255)/256, 256>>>(out);
    k_solve<<<BSZ/8, 256>>>(emb, x, out);
    k_final<<<1, 256>>>(out);
}

// round 11
// speedup vs baseline: 1.4479x; 1.3087x over previous
#include <cuda_runtime.h>
#include <math.h>
#include <stdint.h>

// -------- problem constants --------
#define BSZ   16384
#define INDIM 64
#define DENC  512
#define NE    2048
#define PBAS  12
#define BP    (BSZ*PBAS)          /* 196608 */
#define ZDIM  (INDIM*PBAS)        /* 768    */

// output layout: [loss, x_hat(B*64), perplexity, idx(BP), coeff(BP)]
#define OFF_LOSS  0
#define OFF_XHAT  1
#define OFF_PERP  (1 + BSZ*INDIM)
#define OFF_IDX   (OFF_PERP + 1)
#define OFF_COEFF (OFF_IDX + BP)

// -------- device scratch (static; referenced ONLY from device code) --------
__device__ __align__(16) float  g_h[BSZ*DENC];
__device__ __align__(16) float  g_t[BSZ*DENC];
__device__ __align__(16) float  g_z[BSZ*ZDIM];
__device__ __align__(16) float  g_enorm[NE];
__device__ unsigned long long   g_key[BP];
__device__ int    g_idx[BP];
__device__ int    g_counts[NE];
__device__ double g_lossp[2048];

// ======================= init: counts + keys =======================
__global__ void k_init() {
    int t = blockIdx.x * blockDim.x + threadIdx.x;
    if (t < NE) g_counts[t] = 0;
    if (t < BP) g_key[t] = 0xFFFFFFFFFFFFFFFFull;
}

// ======================= GEMM: C = A(MxK)@B(KxN) + bias =======================
// MODE 0: A = arg (x), C = g_h ; MODE 1: A = g_h, C = g_t ; MODE 2: A = g_h, C = g_z
// 128x128 tile, k-tile 32, 256 threads, 8x8 micro-tile. Single k-ascending
// fmaf accumulator per output (bit-exact vs reference).
template<int MODE>
__global__ __launch_bounds__(256, 2)
void k_gemm(const float* __restrict__ Ain, const float* __restrict__ Bm,
            const float* __restrict__ bias, int N, int K) {
    const float* A = (MODE == 0) ? Ain : g_h;
    float*       C = (MODE == 0) ? g_h : ((MODE == 1) ? g_t : g_z);

    __shared__ __align__(16) float sA[32][132];
    __shared__ __align__(16) float sB[32][132];
    const int tid = threadIdx.x;
    const int tx = tid & 15, ty = tid >> 4;
    const int m0 = blockIdx.y * 128;
    const int n0 = blockIdx.x * 128;

    const int ra  = tid >> 3;          // A: row group 0..31
    const int kq  = (tid & 7) << 2;    // A: k quad
    const int rb  = tid >> 5;          // B: k row 0..7
    const int cq  = (tid & 31) << 2;   // B: col quad

    float acc[8][8];
#pragma unroll
    for (int i = 0; i < 8; i++)
#pragma unroll
        for (int j = 0; j < 8; j++) acc[i][j] = 0.0f;

    // prefetch k-tile 0
    float4 va[4], vb[4];
#pragma unroll
    for (int p = 0; p < 4; p++)
        va[p] = *(const float4*)(A + (size_t)(m0 + p*32 + ra) * K + kq);
#pragma unroll
    for (int p = 0; p < 4; p++)
        vb[p] = *(const float4*)(Bm + (size_t)(p*8 + rb) * N + n0 + cq);

    for (int kt = 0; kt < K; kt += 32) {
        // store prefetched tile
#pragma unroll
        for (int p = 0; p < 4; p++) {
            int m = p*32 + ra;
            sA[kq+0][m] = va[p].x; sA[kq+1][m] = va[p].y;
            sA[kq+2][m] = va[p].z; sA[kq+3][m] = va[p].w;
            *(float4*)(&sB[p*8 + rb][cq]) = vb[p];
        }
        // prefetch next k-tile (overlaps with compute below)
        if (kt + 32 < K) {
#pragma unroll
            for (int p = 0; p < 4; p++)
                va[p] = *(const float4*)(A + (size_t)(m0 + p*32 + ra) * K + kt + 32 + kq);
#pragma unroll
            for (int p = 0; p < 4; p++)
                vb[p] = *(const float4*)(Bm + (size_t)(kt + 32 + p*8 + rb) * N + n0 + cq);
        }
        __syncthreads();
#pragma unroll 8
        for (int kk = 0; kk < 32; kk++) {
            float a[8], b[8];
            *(float4*)(a)     = *(const float4*)(&sA[kk][ty*8]);
            *(float4*)(a + 4) = *(const float4*)(&sA[kk][ty*8 + 4]);
            *(float4*)(b)     = *(const float4*)(&sB[kk][tx*8]);
            *(float4*)(b + 4) = *(const float4*)(&sB[kk][tx*8 + 4]);
#pragma unroll
            for (int i = 0; i < 8; i++)
#pragma unroll
                for (int j = 0; j < 8; j++)
                    acc[i][j] = __fmaf_rn(a[i], b[j], acc[i][j]);
        }
        __syncthreads();
    }
#pragma unroll
    for (int i = 0; i < 8; i++) {
        int m = m0 + ty*8 + i;
#pragma unroll
        for (int j = 0; j < 8; j++) {
            int n = n0 + tx*8 + j;
            C[(size_t)m * N + n] = __fadd_rn(acc[i][j], bias[n]);
        }
    }
}

// ======================= h = h + relu(LN(t)*g + beta) =======================
__global__ void k_ln(const float* __restrict__ gw, const float* __restrict__ bw) {
    __shared__ float red[128];
    const int row = blockIdx.x, tid = threadIdx.x;
    const float* tr = g_t + (size_t)row * DENC;
    float*       hr = g_h + (size_t)row * DENC;

    float v[4], hv[4];
#pragma unroll
    for (int c = 0; c < 4; c++) { v[c] = tr[tid + c*128]; hv[c] = hr[tid + c*128]; }

    float s = (v[0] + v[1]) + (v[2] + v[3]);
    red[tid] = s; __syncthreads();
#pragma unroll
    for (int o = 64; o > 0; o >>= 1) { if (tid < o) red[tid] += red[tid + o]; __syncthreads(); }
    float mu = red[0] * (1.0f / 512.0f);
    __syncthreads();

    float s2 = 0.0f;
#pragma unroll
    for (int c = 0; c < 4; c++) { float d = v[c] - mu; s2 = __fadd_rn(s2, __fmul_rn(d, d)); }
    red[tid] = s2; __syncthreads();
#pragma unroll
    for (int o = 64; o > 0; o >>= 1) { if (tid < o) red[tid] += red[tid + o]; __syncthreads(); }
    float var  = red[0] * (1.0f / 512.0f);
    float rstd = 1.0f / sqrtf(__fadd_rn(var, 1e-5f));

#pragma unroll
    for (int c = 0; c < 4; c++) {
        int col = tid + c*128;
        float o = __fadd_rn(__fmul_rn(__fmul_rn(__fsub_rn(v[c], mu), rstd), gw[col]), bw[col]);
        hr[col] = __fadd_rn(hv[c], fmaxf(o, 0.0f));
    }
}

// ======================= codebook squared norms =======================
__global__ void k_enorm(const float* __restrict__ emb) {
    int k = blockIdx.x * blockDim.x + threadIdx.x;
    if (k < NE) {
        const float* e = emb + (size_t)k * 64;
        float s = 0.0f;
        for (int i = 0; i < 64; i++) s = __fadd_rn(s, __fmul_rn(e[i], e[i]));
        g_enorm[k] = s;
    }
}

// ======================= fused distance + argmin (code-split halves) ==========
// grid 3072: bx>>1 = row tile (128 rows), bx&1 = code half (1024 codes, 8 chunks).
// d = fl( fl(zn + en) - 2*dot ), dot = strictly k-ascending fmaf chain.
// Per-thread register (d, idx) minima with strict-< ascending scan (lowest-index
// tie-break), lexicographic lane merge, atomicMin on packed u64 across halves.
// All d > 0 (zn ~ 13 dominates), so float-bit ordering inside the key is valid.
#define DN 132
#define DIST_SMEM ((64*DN*2 + 256) * 4)
__global__ __launch_bounds__(256, 2)
void k_dist(const float* __restrict__ emb) {
    extern __shared__ __align__(16) float smd[];
    float* sZ = smd;                   // [64][DN]
    float* sE = smd + 64*DN;           // [64][DN]
    float* zn = sE + 64*DN;            // [128]
    float* en = zn + 128;              // [128]

    const int tid = threadIdx.x;
    const int tx = tid & 15, ty = tid >> 4;
    const int m0    = (blockIdx.x >> 1) * 128;
    const int cbase = (blockIdx.x & 1) * 1024;

    const int r4 = tid >> 2, q = tid & 3;

    // load z tile transposed: sZ[k][r]
#pragma unroll
    for (int p = 0; p < 2; p++) {
        int r = p*64 + r4;
        const float4* src = (const float4*)(g_z + (size_t)(m0 + r) * 64) + q*4;
#pragma unroll
        for (int s = 0; s < 4; s++) {
            float4 v = src[s];
            int k = q*16 + s*4;
            sZ[(k+0)*DN + r] = v.x; sZ[(k+1)*DN + r] = v.y;
            sZ[(k+2)*DN + r] = v.z; sZ[(k+3)*DN + r] = v.w;
        }
    }
    __syncthreads();
    if (tid < 128) {
        float s = 0.0f;
        for (int k = 0; k < 64; k++) {
            float zv = sZ[k*DN + tid];
            s = __fadd_rn(s, __fmul_rn(zv, zv));
        }
        zn[tid] = s;
    }

    float bd[8]; int bi[8];
#pragma unroll
    for (int i = 0; i < 8; i++) { bd[i] = __int_as_float(0x7f800000); bi[i] = 0; }

    for (int ch = 0; ch < 8; ch++) {
        if (ch) __syncthreads();
        const int c0 = cbase + ch * 128;
        // e tile transposed: sE[k][r]
#pragma unroll
        for (int p = 0; p < 2; p++) {
            int r = p*64 + r4;
            const float4* src = (const float4*)(emb + (size_t)(c0 + r) * 64) + q*4;
#pragma unroll
            for (int s = 0; s < 4; s++) {
                float4 v = src[s];
                int k = q*16 + s*4;
                sE[(k+0)*DN + r] = v.x; sE[(k+1)*DN + r] = v.y;
                sE[(k+2)*DN + r] = v.z; sE[(k+3)*DN + r] = v.w;
            }
        }
        if (tid < 128) en[tid] = g_enorm[c0 + tid];
        __syncthreads();

        float acc[8][8];
#pragma unroll
        for (int i = 0; i < 8; i++)
#pragma unroll
            for (int j = 0; j < 8; j++) acc[i][j] = 0.0f;

#pragma unroll 8
        for (int kk = 0; kk < 64; kk++) {
            float a[8], b[8];
            *(float4*)(a)     = *(const float4*)(sZ + kk*DN + ty*8);
            *(float4*)(a + 4) = *(const float4*)(sZ + kk*DN + ty*8 + 4);
            *(float4*)(b)     = *(const float4*)(sE + kk*DN + tx*8);
            *(float4*)(b + 4) = *(const float4*)(sE + kk*DN + tx*8 + 4);
#pragma unroll
            for (int i = 0; i < 8; i++)
#pragma unroll
                for (int j = 0; j < 8; j++)
                    acc[i][j] = __fmaf_rn(a[i], b[j], acc[i][j]);
        }

        float enr[8];
#pragma unroll
        for (int j = 0; j < 8; j++) enr[j] = en[tx*8 + j];
#pragma unroll
        for (int i = 0; i < 8; i++) {
            float znr = zn[ty*8 + i];
#pragma unroll
            for (int j = 0; j < 8; j++) {
                float S = __fadd_rn(znr, enr[j]);                     // fl(zn+en)
                float d = __fsub_rn(S, __fmul_rn(2.0f, acc[i][j]));   // fl(S-2*dot)
                if (d < bd[i]) { bd[i] = d; bi[i] = c0 + tx*8 + j; }  // ascending scan
            }
        }
    }

    // lexicographic reduce across the 16 tx lanes, then merge halves
#pragma unroll
    for (int i = 0; i < 8; i++) {
        float d = bd[i]; int ix = bi[i];
#pragma unroll
        for (int o = 8; o > 0; o >>= 1) {
            float od = __shfl_xor_sync(0xffffffffu, d, o, 32);
            int   oi = __shfl_xor_sync(0xffffffffu, ix, o, 32);
            if (od < d || (od == d && oi < ix)) { d = od; ix = oi; }
        }
        if (tx == 0) {
            unsigned long long key =
                ((unsigned long long)__float_as_uint(d) << 32) | (unsigned)ix;
            atomicMin(&g_key[m0 + ty*8 + i], key);
        }
    }
}

// ======================= key -> idx, counts, out =======================
__global__ void k_extract(float* __restrict__ out) {
    int t = blockIdx.x * blockDim.x + threadIdx.x;
    if (t < BP) {
        int w = (int)(g_key[t] & 0xFFFFFFFFull);
        g_idx[t] = w;
        out[OFF_IDX + t] = (float)w;
        atomicAdd(&g_counts[w], 1);
    }
}

// ======================= per-block pinv solve (warp per block) =======================
// Gram/rhs/x_hat in fp32 (cond(G) small -> ~1e-5 rel coeff error, OK vs 1e-3);
// 12x12 Cholesky + triangular solves in fp64 (negligible op count);
// loss accumulation stays fp64.
__global__ __launch_bounds__(256)
void k_solve(const float* __restrict__ emb, const float* __restrict__ x,
             float* __restrict__ out) {
    __shared__ float  sA[8][12][64];
    __shared__ float  sx[8][64];
    __shared__ double sG[8][12][12];
    __shared__ double sr[8][12];
    __shared__ double sy[8][12];
    __shared__ float  sc[8][12];
    __shared__ int    sidx[8][12], sgrp[8][12], smult[8][12], scol[8][12];
    __shared__ int    su[8];
    __shared__ double wls[8];

    const int lane = threadIdx.x & 31;
    const int w    = threadIdx.x >> 5;
    const size_t b = (size_t)blockIdx.x * 8 + w;

    if (lane < 12) sidx[w][lane] = g_idx[b*12 + lane];
    __syncwarp();
    if (lane == 0) {   // dedup (serial, tiny)
        int u = 0;
        for (int j = 0; j < 12; j++) {
            int v = sidx[w][j], q = -1;
            for (int t = 0; t < u; t++)
                if (sidx[w][scol[w][t]] == v) { q = t; break; }
            if (q < 0) { q = u; scol[w][u] = j; smult[w][u] = 0; u++; }
            sgrp[w][j] = q; smult[w][q]++;
        }
        su[w] = u;
    }
    __syncwarp();

    // gather: STE columns A = fl(z + fl(zq - z)); loss from pre-STE zq vs z (fp64)
    {
        double ls = 0.0;
        const float* zr = g_z + b * 768;
        for (int t = lane; t < 768; t += 32) {
            int j = t >> 6, i = t & 63;
            float a = emb[(size_t)sidx[w][j]*64 + i];
            float z = zr[t];
            double df = (double)a - (double)z;
            ls += df*df;
            sA[w][j][i] = __fadd_rn(z, __fsub_rn(a, z));
        }
#pragma unroll
        for (int o = 16; o; o >>= 1) ls += __shfl_down_sync(0xffffffffu, ls, o);
        if (lane == 0) wls[w] = ls;
    }
    for (int t = lane; t < 64; t += 32) sx[w][t] = x[b*64 + t];
    __syncwarp();

    const int u = su[w];
    const int npair = u*(u+1)/2;
    for (int t = lane; t < npair + u; t += 32) {
        if (t < npair) {
            int qa = 0, rem = t;
            while (rem >= u - qa) { rem -= (u - qa); qa++; }
            int qb = qa + rem;
            const float* ca = sA[w][scol[w][qa]];
            const float* cb = sA[w][scol[w][qb]];
            float s = 0.0f;
            for (int k = 0; k < 64; k++) s = __fmaf_rn(ca[k], cb[k], s);
            sG[w][qa][qb] = (double)s; sG[w][qb][qa] = (double)s;
        } else {
            int q2 = t - npair;
            const float* ca = sA[w][scol[w][q2]];
            float s = 0.0f;
            for (int k = 0; k < 64; k++) s = __fmaf_rn(ca[k], sx[w][k], s);
            sr[w][q2] = (double)s;
        }
    }
    __syncwarp();

    // fp64 Cholesky (lower, in place) — tiny op count
    for (int p = 0; p < u; p++) {
        if (lane == 0) sG[w][p][p] = sqrt(sG[w][p][p]);
        __syncwarp();
        double lpp = sG[w][p][p];
        if (lane > p && lane < u) sG[w][lane][p] /= lpp;
        __syncwarp();
        int m = u - p - 1;
        int tot = m*(m+1)/2;
        for (int t = lane; t < tot; t += 32) {
            int a = 0, rem = t;
            while (rem >= m - a) { rem -= (m - a); a++; }
            int j = p + 1 + a;
            int i = j + rem;
            sG[w][i][j] -= sG[w][i][p]*sG[w][j][p];
        }
        __syncwarp();
    }
    if (lane == 0) {   // triangular solves (tiny)
        for (int p = 0; p < u; p++) {
            double s = sr[w][p];
            for (int t = 0; t < p; t++) s -= sG[w][p][t]*sy[w][t];
            sy[w][p] = s / sG[w][p][p];
        }
        for (int p = u - 1; p >= 0; p--) {
            double s = sy[w][p];
            for (int t = p + 1; t < u; t++) s -= sG[w][t][p]*sy[w][t];
            sy[w][p] = s / sG[w][p][p];
        }
    }
    __syncwarp();
    // min-norm split across duplicates -> coeff
    if (lane < 12) {
        int q2 = sgrp[w][lane];
        float c = (float)(sy[w][q2] / (double)smult[w][q2]);
        out[OFF_COEFF + b*12 + lane] = c;
        sc[w][lane] = c;
    }
    __syncwarp();
    // x_hat = A @ coeff (fp32)
    for (int i = lane; i < 64; i += 32) {
        float s = 0.0f;
#pragma unroll
        for (int j = 0; j < 12; j++) s = __fmaf_rn(sA[w][j][i], sc[w][j], s);
        out[OFF_XHAT + b*64 + i] = s;
    }

    __syncthreads();
    if (threadIdx.x == 0) {
        double s = 0.0;
        for (int k = 0; k < 8; k++) s += wls[k];
        g_lossp[blockIdx.x] = s;
    }
}

// ======================= scalars: loss, perplexity =======================
__global__ void k_final(float* __restrict__ out) {
    __shared__ double red[256];
    const int tid = threadIdx.x;
    double s = 0.0;
    for (int k = tid; k < NE; k += 256) {
        double p = (double)g_counts[k] / (double)BP;
        s += p * log(p + 1e-10);
    }
    red[tid] = s; __syncthreads();
    for (int o = 128; o; o >>= 1) { if (tid < o) red[tid] += red[tid + o]; __syncthreads(); }
    double perp = exp(-red[0]);
    __syncthreads();

    double ls = 0.0;
    for (int k = tid; k < 2048; k += 256) ls += g_lossp[k];
    red[tid] = ls; __syncthreads();
    for (int o = 128; o; o >>= 1) { if (tid < o) red[tid] += red[tid + o]; __syncthreads(); }

    if (tid == 0) {
        out[OFF_PERP] = (float)perp;
        out[OFF_LOSS] = (float)(red[0] * 1.25 / ((double)BP * 64.0));
    }
}

// ======================= launch =======================
extern "C" void kernel_launch(void* const* d_in, const int* in_sizes, int n_in,
                              void* d_out, int out_size) {
    const float* x      = (const float*)d_in[0];
    const float* enc_w1 = (const float*)d_in[1];
    const float* enc_b1 = (const float*)d_in[2];
    const float* res_w  = (const float*)d_in[3];
    const float* res_b  = (const float*)d_in[4];
    const float* res_g  = (const float*)d_in[5];
    const float* res_bt = (const float*)d_in[6];
    const float* enc_w2 = (const float*)d_in[7];
    const float* enc_b2 = (const float*)d_in[8];
    const float* emb    = (const float*)d_in[9];
    float* out = (float*)d_out;

    cudaFuncSetAttribute(k_dist, cudaFuncAttributeMaxDynamicSharedMemorySize, DIST_SMEM);

    k_init<<<(BP + 255)/256, 256>>>();

    // encoder: Linear(64->512) -> 2x shared ResBlock -> Linear(512->768)
    k_gemm<0><<<dim3(4, 128), 256>>>(x, enc_w1, enc_b1, DENC, INDIM);
    for (int r = 0; r < 2; r++) {
        k_gemm<1><<<dim3(4, 128), 256>>>(nullptr, res_w, res_b, DENC, DENC);
        k_ln<<<BSZ, 128>>>(res_g, res_bt);
    }
    k_gemm<2><<<dim3(6, 128), 256>>>(nullptr, enc_w2, enc_b2, ZDIM, DENC);

    k_enorm<<<NE/128, 128>>>(emb);
    k_dist<<<(BP/128)*2, 256, DIST_SMEM>>>(emb);
    k_extract<<<(BP + 255)/256, 256>>>(out);
    k_solve<<<BSZ/8, 256>>>(emb, x, out);
    k_final<<<1, 256>>>(out);
}

// round 12
// speedup vs baseline: 1.7211x; 1.1887x over previous
#include <cuda_runtime.h>
#include <math.h>
#include <stdint.h>

// -------- problem constants --------
#define BSZ   16384
#define INDIM 64
#define DENC  512
#define NE    2048
#define PBAS  12
#define BP    (BSZ*PBAS)          /* 196608 */
#define ZDIM  (INDIM*PBAS)        /* 768    */

// output layout: [loss, x_hat(B*64), perplexity, idx(BP), coeff(BP)]
#define OFF_LOSS  0
#define OFF_XHAT  1
#define OFF_PERP  (1 + BSZ*INDIM)
#define OFF_IDX   (OFF_PERP + 1)
#define OFF_COEFF (OFF_IDX + BP)

// -------- device scratch (static; referenced ONLY from device code) --------
__device__ __align__(16) float    g_h[BSZ*DENC];
__device__ __align__(16) float    g_t[BSZ*DENC];
__device__ __align__(16) float    g_z[BSZ*ZDIM];
__device__ __align__(16) float    g_enorm[NE];
__device__ __align__(16) unsigned g_etf[NE*64];      // emb in tf32 bits
__device__ __align__(16) float    g_cmin[(size_t)BP*16];
__device__ int      g_lcnt[16];
__device__ int      g_list[16*BP];
__device__ unsigned g_me;
__device__ unsigned long long g_key[BP];
__device__ int      g_idx[BP];
__device__ int      g_counts[NE];
__device__ double   g_lossp[2048];

// ======================= init =======================
__global__ void k_init() {
    int t = blockIdx.x * blockDim.x + threadIdx.x;
    if (t < NE) g_counts[t] = 0;
    if (t < BP) g_key[t] = 0xFFFFFFFFFFFFFFFFull;
    if (t < 16) g_lcnt[t] = 0;
    if (t == 16) g_me = 0u;
}

// ======================= GEMM: C = A(MxK)@B(KxN) + bias =======================
// Bit-exact vs reference: single k-ascending fmaf accumulator per output.
template<int MODE>
__global__ __launch_bounds__(256, 2)
void k_gemm(const float* __restrict__ Ain, const float* __restrict__ Bm,
            const float* __restrict__ bias, int N, int K) {
    const float* A = (MODE == 0) ? Ain : g_h;
    float*       C = (MODE == 0) ? g_h : ((MODE == 1) ? g_t : g_z);

    __shared__ __align__(16) float sA[32][132];
    __shared__ __align__(16) float sB[32][132];
    const int tid = threadIdx.x;
    const int tx = tid & 15, ty = tid >> 4;
    const int m0 = blockIdx.y * 128;
    const int n0 = blockIdx.x * 128;

    const int ra  = tid >> 3;
    const int kq  = (tid & 7) << 2;
    const int rb  = tid >> 5;
    const int cq  = (tid & 31) << 2;

    float acc[8][8];
#pragma unroll
    for (int i = 0; i < 8; i++)
#pragma unroll
        for (int j = 0; j < 8; j++) acc[i][j] = 0.0f;

    float4 va[4], vb[4];
#pragma unroll
    for (int p = 0; p < 4; p++)
        va[p] = *(const float4*)(A + (size_t)(m0 + p*32 + ra) * K + kq);
#pragma unroll
    for (int p = 0; p < 4; p++)
        vb[p] = *(const float4*)(Bm + (size_t)(p*8 + rb) * N + n0 + cq);

    for (int kt = 0; kt < K; kt += 32) {
#pragma unroll
        for (int p = 0; p < 4; p++) {
            int m = p*32 + ra;
            sA[kq+0][m] = va[p].x; sA[kq+1][m] = va[p].y;
            sA[kq+2][m] = va[p].z; sA[kq+3][m] = va[p].w;
            *(float4*)(&sB[p*8 + rb][cq]) = vb[p];
        }
        if (kt + 32 < K) {
#pragma unroll
            for (int p = 0; p < 4; p++)
                va[p] = *(const float4*)(A + (size_t)(m0 + p*32 + ra) * K + kt + 32 + kq);
#pragma unroll
            for (int p = 0; p < 4; p++)
                vb[p] = *(const float4*)(Bm + (size_t)(kt + 32 + p*8 + rb) * N + n0 + cq);
        }
        __syncthreads();
#pragma unroll 8
        for (int kk = 0; kk < 32; kk++) {
            float a[8], b[8];
            *(float4*)(a)     = *(const float4*)(&sA[kk][ty*8]);
            *(float4*)(a + 4) = *(const float4*)(&sA[kk][ty*8 + 4]);
            *(float4*)(b)     = *(const float4*)(&sB[kk][tx*8]);
            *(float4*)(b + 4) = *(const float4*)(&sB[kk][tx*8 + 4]);
#pragma unroll
            for (int i = 0; i < 8; i++)
#pragma unroll
                for (int j = 0; j < 8; j++)
                    acc[i][j] = __fmaf_rn(a[i], b[j], acc[i][j]);
        }
        __syncthreads();
    }
#pragma unroll
    for (int i = 0; i < 8; i++) {
        int m = m0 + ty*8 + i;
#pragma unroll
        for (int j = 0; j < 8; j++) {
            int n = n0 + tx*8 + j;
            C[(size_t)m * N + n] = __fadd_rn(acc[i][j], bias[n]);
        }
    }
}

// ======================= h = h + relu(LN(t)*g + beta) =======================
__global__ void k_ln(const float* __restrict__ gw, const float* __restrict__ bw) {
    __shared__ float red[128];
    const int row = blockIdx.x, tid = threadIdx.x;
    const float* tr = g_t + (size_t)row * DENC;
    float*       hr = g_h + (size_t)row * DENC;

    float v[4], hv[4];
#pragma unroll
    for (int c = 0; c < 4; c++) { v[c] = tr[tid + c*128]; hv[c] = hr[tid + c*128]; }

    float s = (v[0] + v[1]) + (v[2] + v[3]);
    red[tid] = s; __syncthreads();
#pragma unroll
    for (int o = 64; o > 0; o >>= 1) { if (tid < o) red[tid] += red[tid + o]; __syncthreads(); }
    float mu = red[0] * (1.0f / 512.0f);
    __syncthreads();

    float s2 = 0.0f;
#pragma unroll
    for (int c = 0; c < 4; c++) { float d = v[c] - mu; s2 = __fadd_rn(s2, __fmul_rn(d, d)); }
    red[tid] = s2; __syncthreads();
#pragma unroll
    for (int o = 64; o > 0; o >>= 1) { if (tid < o) red[tid] += red[tid + o]; __syncthreads(); }
    float var  = red[0] * (1.0f / 512.0f);
    float rstd = 1.0f / sqrtf(__fadd_rn(var, 1e-5f));

#pragma unroll
    for (int c = 0; c < 4; c++) {
        int col = tid + c*128;
        float o = __fadd_rn(__fmul_rn(__fmul_rn(__fsub_rn(v[c], mu), rstd), gw[col]), bw[col]);
        hr[col] = __fadd_rn(hv[c], fmaxf(o, 0.0f));
    }
}

// ======================= codebook norms + tf32 copy + max norm ==============
__global__ void k_enorm(const float* __restrict__ emb) {
    int k = blockIdx.x * blockDim.x + threadIdx.x;
    if (k < NE) {
        const float* e = emb + (size_t)k * 64;
        float s = 0.0f;
        for (int i = 0; i < 64; i++) s = __fadd_rn(s, __fmul_rn(e[i], e[i]));
        g_enorm[k] = s;
        atomicMax(&g_me, __float_as_uint(sqrtf(s)));
        for (int i = 0; i < 64; i++) {
            unsigned u;
            asm("cvt.rna.tf32.f32 %0, %1;" : "=r"(u) : "f"(e[i]));
            g_etf[(size_t)k*64 + i] = u;
        }
    }
}

// ======================= TF32 tensor-core screening pass =======================
// Per CTA: 128 z-rows vs all 2048 codes; s = en - 2*dot_tf32; per-(row, chunk)
// min stored to g_cmin. mma.sync m16n8k8: warp owns 16 rows (A frags in regs).
#define ZT 68
__global__ __launch_bounds__(256)
void k_tc() {
    __shared__ unsigned sZt[128*ZT];
    __shared__ unsigned sEt[128*ZT];
    __shared__ float    sen[128];
    const int tid = threadIdx.x;
    const int lane = tid & 31, wid = tid >> 5;
    const int g = lane >> 2, t = lane & 3;
    const int m0 = blockIdx.x * 128;

    {   // load + cvt z rows (row-major, stride ZT)
        int r = tid >> 1, h = (tid & 1) * 32;
        const float4* src = (const float4*)(g_z + (size_t)(m0 + r) * 64 + h);
#pragma unroll
        for (int j = 0; j < 8; j++) {
            float4 v = src[j];
            unsigned u0, u1, u2, u3;
            asm("cvt.rna.tf32.f32 %0, %1;" : "=r"(u0) : "f"(v.x));
            asm("cvt.rna.tf32.f32 %0, %1;" : "=r"(u1) : "f"(v.y));
            asm("cvt.rna.tf32.f32 %0, %1;" : "=r"(u2) : "f"(v.z));
            asm("cvt.rna.tf32.f32 %0, %1;" : "=r"(u3) : "f"(v.w));
            int k = h + j*4;
            sZt[r*ZT + k]   = u0; sZt[r*ZT + k+1] = u1;
            sZt[r*ZT + k+2] = u2; sZt[r*ZT + k+3] = u3;
        }
    }
    __syncthreads();

    // A fragments: rows rlo/rhi, k = ks*8 + t (+4); held for whole kernel
    unsigned A0[8], A1[8], A2[8], A3[8];
    const int rlo = wid*16 + g, rhi = rlo + 8;
#pragma unroll
    for (int ks = 0; ks < 8; ks++) {
        A0[ks] = sZt[rlo*ZT + ks*8 + t];
        A1[ks] = sZt[rhi*ZT + ks*8 + t];
        A2[ks] = sZt[rlo*ZT + ks*8 + t + 4];
        A3[ks] = sZt[rhi*ZT + ks*8 + t + 4];
    }

    for (int ch = 0; ch < 16; ch++) {
        __syncthreads();
        {   // load e chunk (tf32 bits, code-major stride ZT) + en
            int r = tid >> 1, h = (tid & 1) * 32;
            const uint4* src = (const uint4*)(g_etf + (size_t)(ch*128 + r)*64 + h);
#pragma unroll
            for (int j = 0; j < 8; j++) {
                uint4 v = src[j];
                int k = h + j*4;
                sEt[r*ZT + k]   = v.x; sEt[r*ZT + k+1] = v.y;
                sEt[r*ZT + k+2] = v.z; sEt[r*ZT + k+3] = v.w;
            }
            if (tid < 128) sen[tid] = g_enorm[ch*128 + tid];
        }
        __syncthreads();

        float acc[16][4];
#pragma unroll
        for (int nt = 0; nt < 16; nt++) {
            acc[nt][0] = 0.f; acc[nt][1] = 0.f; acc[nt][2] = 0.f; acc[nt][3] = 0.f;
        }
#pragma unroll
        for (int nt = 0; nt < 16; nt++) {
#pragma unroll
            for (int ks = 0; ks < 8; ks++) {
                unsigned b0 = sEt[(nt*8 + g)*ZT + ks*8 + t];
                unsigned b1 = sEt[(nt*8 + g)*ZT + ks*8 + t + 4];
                asm("mma.sync.aligned.m16n8k8.row.col.f32.tf32.tf32.f32 "
                    "{%0,%1,%2,%3}, {%4,%5,%6,%7}, {%8,%9}, {%0,%1,%2,%3};"
                    : "+f"(acc[nt][0]), "+f"(acc[nt][1]),
                      "+f"(acc[nt][2]), "+f"(acc[nt][3])
                    : "r"(A0[ks]), "r"(A1[ks]), "r"(A2[ks]), "r"(A3[ks]),
                      "r"(b0), "r"(b1));
            }
        }

        // per-row chunk min of s = en - 2*dot  (cols 2t, 2t+1 per n-tile)
        float mlo = __int_as_float(0x7f800000), mhi = mlo;
#pragma unroll
        for (int nt = 0; nt < 16; nt++) {
            float2 en2 = *(const float2*)&sen[nt*8 + 2*t];
            float s0 = en2.x - 2.0f*acc[nt][0]; if (s0 < mlo) mlo = s0;
            float s1 = en2.y - 2.0f*acc[nt][1]; if (s1 < mlo) mlo = s1;
            float s2 = en2.x - 2.0f*acc[nt][2]; if (s2 < mhi) mhi = s2;
            float s3 = en2.y - 2.0f*acc[nt][3]; if (s3 < mhi) mhi = s3;
        }
#pragma unroll
        for (int o = 1; o <= 2; o <<= 1) {
            float x = __shfl_xor_sync(0xffffffffu, mlo, o, 32); if (x < mlo) mlo = x;
            float y = __shfl_xor_sync(0xffffffffu, mhi, o, 32); if (y < mhi) mhi = y;
        }
        if (t == 0) {
            g_cmin[(size_t)(m0 + rlo)*16 + ch] = mlo;
            g_cmin[(size_t)(m0 + rhi)*16 + ch] = mhi;
        }
    }
}

// ======================= flag chunks within margin of row min ===============
__global__ void k_flag() {
    int row = blockIdx.x * blockDim.x + threadIdx.x;
    if (row >= BP) return;
    const float4* zr = (const float4*)(g_z + (size_t)row * 64);
    float zn = 0.0f;
#pragma unroll
    for (int j = 0; j < 16; j++) {
        float4 v = zr[j];
        zn += v.x*v.x + v.y*v.y + v.z*v.z + v.w*v.w;
    }
    float c[16];
    float m = __int_as_float(0x7f800000);
#pragma unroll
    for (int ch = 0; ch < 16; ch++) {
        c[ch] = g_cmin[(size_t)row*16 + ch];
        if (c[ch] < m) m = c[ch];
    }
    float me = __uint_as_float(g_me);
    // sound bound: 2*2^-10*||z||*me; use 2^-7 (8x headroom) + ulp(zn) slack
    float thr = m + sqrtf(zn)*me*(1.0f/128.0f) + zn*2e-6f + 1e-7f;
#pragma unroll
    for (int ch = 0; ch < 16; ch++) {
        if (c[ch] <= thr) {
            int p = atomicAdd(&g_lcnt[ch], 1);
            g_list[ch*BP + p] = row;
        }
    }
}

// ======================= exact pass on flagged (row, chunk) pairs ===========
// Bit-exact reference sequence: d = fl(fl(zn+en) - 2*dot), k-ascending fmaf,
// lowest-index tie-break, u64 atomicMin merge across chunks.
#define DN 132
#define EX_SMEM ((64*DN*2 + 256)*4 + 128*4)
__global__ __launch_bounds__(256, 2)
void k_exact(const float* __restrict__ emb) {
    extern __shared__ __align__(16) float smd[];
    float* sZ = smd;
    float* sE = smd + 64*DN;
    float* zn = sE + 64*DN;
    float* en = zn + 128;
    int* srows = (int*)(en + 128);

    const int tid = threadIdx.x;
    const int tx = tid & 15, ty = tid >> 4;
    const int ch = blockIdx.x, grp = blockIdx.y;
    const int cnt = g_lcnt[ch];
    if (grp * 128 >= cnt) return;

    if (tid < 128) {
        int ii = grp*128 + tid;
        srows[tid] = g_list[ch*BP + (ii < cnt ? ii : grp*128)];
    }
    __syncthreads();

    const int c0 = ch * 128;
    const int r4 = tid >> 2, q = tid & 3;
#pragma unroll
    for (int p = 0; p < 2; p++) {
        int r = p*64 + r4;
        const float4* srcz = (const float4*)(g_z + (size_t)srows[r] * 64) + q*4;
        const float4* srce = (const float4*)(emb + (size_t)(c0 + r) * 64) + q*4;
#pragma unroll
        for (int s = 0; s < 4; s++) {
            float4 v = srcz[s];
            int k = q*16 + s*4;
            sZ[(k+0)*DN + r] = v.x; sZ[(k+1)*DN + r] = v.y;
            sZ[(k+2)*DN + r] = v.z; sZ[(k+3)*DN + r] = v.w;
            float4 w = srce[s];
            sE[(k+0)*DN + r] = w.x; sE[(k+1)*DN + r] = w.y;
            sE[(k+2)*DN + r] = w.z; sE[(k+3)*DN + r] = w.w;
        }
    }
    if (tid < 128) en[tid] = g_enorm[c0 + tid];
    __syncthreads();
    if (tid < 128) {
        float s = 0.0f;
        for (int k = 0; k < 64; k++) {
            float zv = sZ[k*DN + tid];
            s = __fadd_rn(s, __fmul_rn(zv, zv));
        }
        zn[tid] = s;
    }
    __syncthreads();

    float acc[8][8];
#pragma unroll
    for (int i = 0; i < 8; i++)
#pragma unroll
        for (int j = 0; j < 8; j++) acc[i][j] = 0.0f;

#pragma unroll 8
    for (int kk = 0; kk < 64; kk++) {
        float a[8], b[8];
        *(float4*)(a)     = *(const float4*)(sZ + kk*DN + ty*8);
        *(float4*)(a + 4) = *(const float4*)(sZ + kk*DN + ty*8 + 4);
        *(float4*)(b)     = *(const float4*)(sE + kk*DN + tx*8);
        *(float4*)(b + 4) = *(const float4*)(sE + kk*DN + tx*8 + 4);
#pragma unroll
        for (int i = 0; i < 8; i++)
#pragma unroll
            for (int j = 0; j < 8; j++)
                acc[i][j] = __fmaf_rn(a[i], b[j], acc[i][j]);
    }

    float enr[8];
#pragma unroll
    for (int j = 0; j < 8; j++) enr[j] = en[tx*8 + j];
#pragma unroll
    for (int i = 0; i < 8; i++) {
        float znr = zn[ty*8 + i];
        float bd = __int_as_float(0x7f800000); int bi = 0;
#pragma unroll
        for (int j = 0; j < 8; j++) {
            float S = __fadd_rn(znr, enr[j]);
            float d = __fsub_rn(S, __fmul_rn(2.0f, acc[i][j]));
            if (d < bd) { bd = d; bi = c0 + tx*8 + j; }
        }
#pragma unroll
        for (int o = 8; o > 0; o >>= 1) {
            float od = __shfl_xor_sync(0xffffffffu, bd, o, 32);
            int   oi = __shfl_xor_sync(0xffffffffu, bi, o, 32);
            if (od < bd || (od == bd && oi < bi)) { bd = od; bi = oi; }
        }
        if (tx == 0) {
            unsigned long long key =
                ((unsigned long long)__float_as_uint(bd) << 32) | (unsigned)bi;
            atomicMin(&g_key[srows[ty*8 + i]], key);
        }
    }
}

// ======================= key -> idx, counts, out =======================
__global__ void k_extract(float* __restrict__ out) {
    int t = blockIdx.x * blockDim.x + threadIdx.x;
    if (t < BP) {
        int w = (int)(g_key[t] & 0xFFFFFFFFull);
        g_idx[t] = w;
        out[OFF_IDX + t] = (float)w;
        atomicAdd(&g_counts[w], 1);
    }
}

// ======================= per-block pinv solve (warp per block) ==============
__global__ __launch_bounds__(256)
void k_solve(const float* __restrict__ emb, const float* __restrict__ x,
             float* __restrict__ out) {
    __shared__ float  sA[8][12][64];
    __shared__ float  sx[8][64];
    __shared__ double sG[8][12][12];
    __shared__ double sr[8][12];
    __shared__ double sy[8][12];
    __shared__ float  sc[8][12];
    __shared__ int    sidx[8][12], sgrp[8][12], smult[8][12], scol[8][12];
    __shared__ int    su[8];
    __shared__ double wls[8];

    const int lane = threadIdx.x & 31;
    const int w    = threadIdx.x >> 5;
    const size_t b = (size_t)blockIdx.x * 8 + w;

    if (lane < 12) sidx[w][lane] = g_idx[b*12 + lane];
    __syncwarp();
    if (lane == 0) {
        int u = 0;
        for (int j = 0; j < 12; j++) {
            int v = sidx[w][j], q = -1;
            for (int t = 0; t < u; t++)
                if (sidx[w][scol[w][t]] == v) { q = t; break; }
            if (q < 0) { q = u; scol[w][u] = j; smult[w][u] = 0; u++; }
            sgrp[w][j] = q; smult[w][q]++;
        }
        su[w] = u;
    }
    __syncwarp();

    {
        double ls = 0.0;
        const float* zr = g_z + b * 768;
        for (int t = lane; t < 768; t += 32) {
            int j = t >> 6, i = t & 63;
            float a = emb[(size_t)sidx[w][j]*64 + i];
            float z = zr[t];
            double df = (double)a - (double)z;
            ls += df*df;
            sA[w][j][i] = __fadd_rn(z, __fsub_rn(a, z));
        }
#pragma unroll
        for (int o = 16; o; o >>= 1) ls += __shfl_down_sync(0xffffffffu, ls, o);
        if (lane == 0) wls[w] = ls;
    }
    for (int t = lane; t < 64; t += 32) sx[w][t] = x[b*64 + t];
    __syncwarp();

    const int u = su[w];
    const int npair = u*(u+1)/2;
    for (int t = lane; t < npair + u; t += 32) {
        if (t < npair) {
            int qa = 0, rem = t;
            while (rem >= u - qa) { rem -= (u - qa); qa++; }
            int qb = qa + rem;
            const float* ca = sA[w][scol[w][qa]];
            const float* cb = sA[w][scol[w][qb]];
            float s = 0.0f;
            for (int k = 0; k < 64; k++) s = __fmaf_rn(ca[k], cb[k], s);
            sG[w][qa][qb] = (double)s; sG[w][qb][qa] = (double)s;
        } else {
            int q2 = t - npair;
            const float* ca = sA[w][scol[w][q2]];
            float s = 0.0f;
            for (int k = 0; k < 64; k++) s = __fmaf_rn(ca[k], sx[w][k], s);
            sr[w][q2] = (double)s;
        }
    }
    __syncwarp();

    for (int p = 0; p < u; p++) {
        if (lane == 0) sG[w][p][p] = sqrt(sG[w][p][p]);
        __syncwarp();
        double lpp = sG[w][p][p];
        if (lane > p && lane < u) sG[w][lane][p] /= lpp;
        __syncwarp();
        int m = u - p - 1;
        int tot = m*(m+1)/2;
        for (int t = lane; t < tot; t += 32) {
            int a = 0, rem = t;
            while (rem >= m - a) { rem -= (m - a); a++; }
            int j = p + 1 + a;
            int i = j + rem;
            sG[w][i][j] -= sG[w][i][p]*sG[w][j][p];
        }
        __syncwarp();
    }
    if (lane == 0) {
        for (int p = 0; p < u; p++) {
            double s = sr[w][p];
            for (int t = 0; t < p; t++) s -= sG[w][p][t]*sy[w][t];
            sy[w][p] = s / sG[w][p][p];
        }
        for (int p = u - 1; p >= 0; p--) {
            double s = sy[w][p];
            for (int t = p + 1; t < u; t++) s -= sG[w][t][p]*sy[w][t];
            sy[w][p] = s / sG[w][p][p];
        }
    }
    __syncwarp();
    if (lane < 12) {
        int q2 = sgrp[w][lane];
        float c = (float)(sy[w][q2] / (double)smult[w][q2]);
        out[OFF_COEFF + b*12 + lane] = c;
        sc[w][lane] = c;
    }
    __syncwarp();
    for (int i = lane; i < 64; i += 32) {
        float s = 0.0f;
#pragma unroll
        for (int j = 0; j < 12; j++) s = __fmaf_rn(sA[w][j][i], sc[w][j], s);
        out[OFF_XHAT + b*64 + i] = s;
    }

    __syncthreads();
    if (threadIdx.x == 0) {
        double s = 0.0;
        for (int k = 0; k < 8; k++) s += wls[k];
        g_lossp[blockIdx.x] = s;
    }
}

// ======================= scalars: loss, perplexity =======================
__global__ void k_final(float* __restrict__ out) {
    __shared__ double red[256];
    const int tid = threadIdx.x;
    double s = 0.0;
    for (int k = tid; k < NE; k += 256) {
        double p = (double)g_counts[k] / (double)BP;
        s += p * log(p + 1e-10);
    }
    red[tid] = s; __syncthreads();
    for (int o = 128; o; o >>= 1) { if (tid < o) red[tid] += red[tid + o]; __syncthreads(); }
    double perp = exp(-red[0]);
    __syncthreads();

    double ls = 0.0;
    for (int k = tid; k < 2048; k += 256) ls += g_lossp[k];
    red[tid] = ls; __syncthreads();
    for (int o = 128; o; o >>= 1) { if (tid < o) red[tid] += red[tid + o]; __syncthreads(); }

    if (tid == 0) {
        out[OFF_PERP] = (float)perp;
        out[OFF_LOSS] = (float)(red[0] * 1.25 / ((double)BP * 64.0));
    }
}

// ======================= launch =======================
extern "C" void kernel_launch(void* const* d_in, const int* in_sizes, int n_in,
                              void* d_out, int out_size) {
    const float* x      = (const float*)d_in[0];
    const float* enc_w1 = (const float*)d_in[1];
    const float* enc_b1 = (const float*)d_in[2];
    const float* res_w  = (const float*)d_in[3];
    const float* res_b  = (const float*)d_in[4];
    const float* res_g  = (const float*)d_in[5];
    const float* res_bt = (const float*)d_in[6];
    const float* enc_w2 = (const float*)d_in[7];
    const float* enc_b2 = (const float*)d_in[8];
    const float* emb    = (const float*)d_in[9];
    float* out = (float*)d_out;

    cudaFuncSetAttribute(k_exact, cudaFuncAttributeMaxDynamicSharedMemorySize, EX_SMEM);

    k_init<<<(BP + 255)/256, 256>>>();
    k_enorm<<<NE/128, 128>>>(emb);

    // encoder: Linear(64->512) -> 2x shared ResBlock -> Linear(512->768)
    k_gemm<0><<<dim3(4, 128), 256>>>(x, enc_w1, enc_b1, DENC, INDIM);
    for (int r = 0; r < 2; r++) {
        k_gemm<1><<<dim3(4, 128), 256>>>(nullptr, res_w, res_b, DENC, DENC);
        k_ln<<<BSZ, 128>>>(res_g, res_bt);
    }
    k_gemm<2><<<dim3(6, 128), 256>>>(nullptr, enc_w2, enc_b2, ZDIM, DENC);

    k_tc<<<BP/128, 256>>>();
    k_flag<<<BP/256, 256>>>();
    k_exact<<<dim3(16, BP/128), 256, EX_SMEM>>>(emb);
    k_extract<<<(BP + 255)/256, 256>>>(out);
    k_solve<<<BSZ/8, 256>>>(emb, x, out);
    k_final<<<1, 256>>>(out);
}

// round 13
// speedup vs baseline: 2.0889x; 1.2137x over previous
#include <cuda_runtime.h>
#include <math.h>
#include <stdint.h>

// -------- problem constants --------
#define BSZ   16384
#define INDIM 64
#define DENC  512
#define NE    2048
#define PBAS  12
#define BP    (BSZ*PBAS)          /* 196608 */
#define ZDIM  (INDIM*PBAS)        /* 768    */

// output layout: [loss, x_hat(B*64), perplexity, idx(BP), coeff(BP)]
#define OFF_LOSS  0
#define OFF_XHAT  1
#define OFF_PERP  (1 + BSZ*INDIM)
#define OFF_IDX   (OFF_PERP + 1)
#define OFF_COEFF (OFF_IDX + BP)

// -------- device scratch (static; referenced ONLY from device code) --------
__device__ __align__(16) float    g_h[BSZ*DENC];
__device__ __align__(16) float    g_t[BSZ*DENC];
__device__ __align__(16) float    g_z[BSZ*ZDIM];
__device__ __align__(16) float    g_enorm[NE];
__device__ __align__(16) unsigned g_etf[NE*64];      // emb tf32 bits, k-pair-permuted
__device__ __align__(16) float    g_cmin[(size_t)BP*16];
__device__ int      g_lcnt[16];
__device__ int      g_list[16*BP];
__device__ int      g_ibase[17];
__device__ int      g_wq;
__device__ unsigned g_me;
__device__ unsigned long long g_key[BP];
__device__ int      g_idx[BP];
__device__ int      g_counts[NE];
__device__ double   g_lossp[2048];

// ======================= init =======================
__global__ void k_init() {
    int t = blockIdx.x * blockDim.x + threadIdx.x;
    if (t < NE) g_counts[t] = 0;
    if (t < BP) g_key[t] = 0xFFFFFFFFFFFFFFFFull;
    if (t < 16) g_lcnt[t] = 0;
    if (t == 16) g_me = 0u;
    if (t == 17) g_wq = 0;
}

// ======================= GEMM: C = A(MxK)@B(KxN) + bias =======================
// Bit-exact vs reference: single k-ascending fmaf accumulator per output.
template<int MODE>
__global__ __launch_bounds__(256, 2)
void k_gemm(const float* __restrict__ Ain, const float* __restrict__ Bm,
            const float* __restrict__ bias, int N, int K) {
    const float* A = (MODE == 0) ? Ain : g_h;
    float*       C = (MODE == 0) ? g_h : ((MODE == 1) ? g_t : g_z);

    __shared__ __align__(16) float sA[32][132];
    __shared__ __align__(16) float sB[32][132];
    const int tid = threadIdx.x;
    const int tx = tid & 15, ty = tid >> 4;
    const int m0 = blockIdx.y * 128;
    const int n0 = blockIdx.x * 128;

    const int ra  = tid >> 3;
    const int kq  = (tid & 7) << 2;
    const int rb  = tid >> 5;
    const int cq  = (tid & 31) << 2;

    float acc[8][8];
#pragma unroll
    for (int i = 0; i < 8; i++)
#pragma unroll
        for (int j = 0; j < 8; j++) acc[i][j] = 0.0f;

    float4 va[4], vb[4];
#pragma unroll
    for (int p = 0; p < 4; p++)
        va[p] = *(const float4*)(A + (size_t)(m0 + p*32 + ra) * K + kq);
#pragma unroll
    for (int p = 0; p < 4; p++)
        vb[p] = *(const float4*)(Bm + (size_t)(p*8 + rb) * N + n0 + cq);

    for (int kt = 0; kt < K; kt += 32) {
#pragma unroll
        for (int p = 0; p < 4; p++) {
            int m = p*32 + ra;
            sA[kq+0][m] = va[p].x; sA[kq+1][m] = va[p].y;
            sA[kq+2][m] = va[p].z; sA[kq+3][m] = va[p].w;
            *(float4*)(&sB[p*8 + rb][cq]) = vb[p];
        }
        if (kt + 32 < K) {
#pragma unroll
            for (int p = 0; p < 4; p++)
                va[p] = *(const float4*)(A + (size_t)(m0 + p*32 + ra) * K + kt + 32 + kq);
#pragma unroll
            for (int p = 0; p < 4; p++)
                vb[p] = *(const float4*)(Bm + (size_t)(kt + 32 + p*8 + rb) * N + n0 + cq);
        }
        __syncthreads();
#pragma unroll 8
        for (int kk = 0; kk < 32; kk++) {
            float a[8], b[8];
            *(float4*)(a)     = *(const float4*)(&sA[kk][ty*8]);
            *(float4*)(a + 4) = *(const float4*)(&sA[kk][ty*8 + 4]);
            *(float4*)(b)     = *(const float4*)(&sB[kk][tx*8]);
            *(float4*)(b + 4) = *(const float4*)(&sB[kk][tx*8 + 4]);
#pragma unroll
            for (int i = 0; i < 8; i++)
#pragma unroll
                for (int j = 0; j < 8; j++)
                    acc[i][j] = __fmaf_rn(a[i], b[j], acc[i][j]);
        }
        __syncthreads();
    }
#pragma unroll
    for (int i = 0; i < 8; i++) {
        int m = m0 + ty*8 + i;
#pragma unroll
        for (int j = 0; j < 8; j++) {
            int n = n0 + tx*8 + j;
            C[(size_t)m * N + n] = __fadd_rn(acc[i][j], bias[n]);
        }
    }
}

// ======================= h = h + relu(LN(t)*g + beta) =======================
__global__ void k_ln(const float* __restrict__ gw, const float* __restrict__ bw) {
    __shared__ float red[128];
    const int row = blockIdx.x, tid = threadIdx.x;
    const float* tr = g_t + (size_t)row * DENC;
    float*       hr = g_h + (size_t)row * DENC;

    float v[4], hv[4];
#pragma unroll
    for (int c = 0; c < 4; c++) { v[c] = tr[tid + c*128]; hv[c] = hr[tid + c*128]; }

    float s = (v[0] + v[1]) + (v[2] + v[3]);
    red[tid] = s; __syncthreads();
#pragma unroll
    for (int o = 64; o > 0; o >>= 1) { if (tid < o) red[tid] += red[tid + o]; __syncthreads(); }
    float mu = red[0] * (1.0f / 512.0f);
    __syncthreads();

    float s2 = 0.0f;
#pragma unroll
    for (int c = 0; c < 4; c++) { float d = v[c] - mu; s2 = __fadd_rn(s2, __fmul_rn(d, d)); }
    red[tid] = s2; __syncthreads();
#pragma unroll
    for (int o = 64; o > 0; o >>= 1) { if (tid < o) red[tid] += red[tid + o]; __syncthreads(); }
    float var  = red[0] * (1.0f / 512.0f);
    float rstd = 1.0f / sqrtf(__fadd_rn(var, 1e-5f));

#pragma unroll
    for (int c = 0; c < 4; c++) {
        int col = tid + c*128;
        float o = __fadd_rn(__fmul_rn(__fmul_rn(__fsub_rn(v[c], mu), rstd), gw[col]), bw[col]);
        hr[col] = __fadd_rn(hv[c], fmaxf(o, 0.0f));
    }
}

// ======================= codebook norms + permuted tf32 copy ================
// g_etf row layout: element k stored at pos = (k>>3)*8 + (k&3)*2 + ((k&7)>>2)
// so the mma B fragment pair (k, k+4) sits in adjacent words -> one LDS.64.
__global__ void k_enorm(const float* __restrict__ emb) {
    int k = blockIdx.x * blockDim.x + threadIdx.x;
    if (k < NE) {
        const float* e = emb + (size_t)k * 64;
        float s = 0.0f;
        for (int i = 0; i < 64; i++) s = __fadd_rn(s, __fmul_rn(e[i], e[i]));
        g_enorm[k] = s;
        atomicMax(&g_me, __float_as_uint(sqrtf(s)));
        for (int i = 0; i < 64; i++) {
            unsigned u;
            asm("cvt.rna.tf32.f32 %0, %1;" : "=r"(u) : "f"(e[i]));
            int pos = ((i >> 3) << 3) + ((i & 3) << 1) + ((i & 7) >> 2);
            g_etf[(size_t)k*64 + pos] = u;
        }
    }
}

// ======================= TF32 tensor-core screening pass =======================
// 128 z-rows vs all 2048 codes; s = en - 2*dot_tf32; per-(row, 128-chunk) min.
#define ZT 68
#define ZE 72
__global__ __launch_bounds__(256)
void k_tc() {
    __shared__ unsigned sZt[128*ZT];
    __shared__ unsigned sEt[128*ZE];
    __shared__ float    sen[128];
    const int tid = threadIdx.x;
    const int lane = tid & 31, wid = tid >> 5;
    const int g = lane >> 2, t = lane & 3;
    const int m0 = blockIdx.x * 128;

    {   // load + cvt z rows (row-major, stride ZT, natural k order)
        int r = tid >> 1, h = (tid & 1) * 32;
        const float4* src = (const float4*)(g_z + (size_t)(m0 + r) * 64 + h);
#pragma unroll
        for (int j = 0; j < 8; j++) {
            float4 v = src[j];
            unsigned u0, u1, u2, u3;
            asm("cvt.rna.tf32.f32 %0, %1;" : "=r"(u0) : "f"(v.x));
            asm("cvt.rna.tf32.f32 %0, %1;" : "=r"(u1) : "f"(v.y));
            asm("cvt.rna.tf32.f32 %0, %1;" : "=r"(u2) : "f"(v.z));
            asm("cvt.rna.tf32.f32 %0, %1;" : "=r"(u3) : "f"(v.w));
            int k = h + j*4;
            sZt[r*ZT + k]   = u0; sZt[r*ZT + k+1] = u1;
            sZt[r*ZT + k+2] = u2; sZt[r*ZT + k+3] = u3;
        }
    }
    __syncthreads();

    // A fragments held in regs for the whole kernel
    unsigned A0[8], A1[8], A2[8], A3[8];
    const int rlo = wid*16 + g, rhi = rlo + 8;
#pragma unroll
    for (int ks = 0; ks < 8; ks++) {
        A0[ks] = sZt[rlo*ZT + ks*8 + t];
        A1[ks] = sZt[rhi*ZT + ks*8 + t];
        A2[ks] = sZt[rlo*ZT + ks*8 + t + 4];
        A3[ks] = sZt[rhi*ZT + ks*8 + t + 4];
    }

    for (int ch = 0; ch < 16; ch++) {
        __syncthreads();
        {   // load e chunk (pre-permuted tf32 bits) + en — contiguous copy
            int r = tid >> 1, h = (tid & 1) * 32;
            const uint4* src = (const uint4*)(g_etf + (size_t)(ch*128 + r)*64 + h);
#pragma unroll
            for (int j = 0; j < 8; j++) {
                uint4 v = src[j];
                int k = h + j*4;
                sEt[r*ZE + k]   = v.x; sEt[r*ZE + k+1] = v.y;
                sEt[r*ZE + k+2] = v.z; sEt[r*ZE + k+3] = v.w;
            }
            if (tid < 128) sen[tid] = g_enorm[ch*128 + tid];
        }
        __syncthreads();

        float acc[16][4];
#pragma unroll
        for (int nt = 0; nt < 16; nt++) {
            acc[nt][0] = 0.f; acc[nt][1] = 0.f; acc[nt][2] = 0.f; acc[nt][3] = 0.f;
        }
#pragma unroll
        for (int nt = 0; nt < 16; nt++) {
#pragma unroll
            for (int ks = 0; ks < 8; ks++) {
                uint2 bb = *(const uint2*)(&sEt[(nt*8 + g)*ZE + ks*8 + 2*t]);
                asm("mma.sync.aligned.m16n8k8.row.col.f32.tf32.tf32.f32 "
                    "{%0,%1,%2,%3}, {%4,%5,%6,%7}, {%8,%9}, {%0,%1,%2,%3};"
                    : "+f"(acc[nt][0]), "+f"(acc[nt][1]),
                      "+f"(acc[nt][2]), "+f"(acc[nt][3])
                    : "r"(A0[ks]), "r"(A1[ks]), "r"(A2[ks]), "r"(A3[ks]),
                      "r"(bb.x), "r"(bb.y));
            }
        }

        float mlo = __int_as_float(0x7f800000), mhi = mlo;
#pragma unroll
        for (int nt = 0; nt < 16; nt++) {
            float2 en2 = *(const float2*)&sen[nt*8 + 2*t];
            float s0 = en2.x - 2.0f*acc[nt][0]; if (s0 < mlo) mlo = s0;
            float s1 = en2.y - 2.0f*acc[nt][1]; if (s1 < mlo) mlo = s1;
            float s2 = en2.x - 2.0f*acc[nt][2]; if (s2 < mhi) mhi = s2;
            float s3 = en2.y - 2.0f*acc[nt][3]; if (s3 < mhi) mhi = s3;
        }
#pragma unroll
        for (int o = 1; o <= 2; o <<= 1) {
            float x = __shfl_xor_sync(0xffffffffu, mlo, o, 32); if (x < mlo) mlo = x;
            float y = __shfl_xor_sync(0xffffffffu, mhi, o, 32); if (y < mhi) mhi = y;
        }
        if (t == 0) {
            g_cmin[(size_t)(m0 + rlo)*16 + ch] = mlo;
            g_cmin[(size_t)(m0 + rhi)*16 + ch] = mhi;
        }
    }
}

// ======================= flag chunks within margin of row min ===============
__global__ void k_flag() {
    int row = blockIdx.x * blockDim.x + threadIdx.x;
    if (row >= BP) return;
    const float4* zr = (const float4*)(g_z + (size_t)row * 64);
    float zn = 0.0f;
#pragma unroll
    for (int j = 0; j < 16; j++) {
        float4 v = zr[j];
        zn += v.x*v.x + v.y*v.y + v.z*v.z + v.w*v.w;
    }
    float c[16];
    float m = __int_as_float(0x7f800000);
#pragma unroll
    for (int ch = 0; ch < 16; ch++) {
        c[ch] = g_cmin[(size_t)row*16 + ch];
        if (c[ch] < m) m = c[ch];
    }
    float me = __uint_as_float(g_me);
    float thr = m + sqrtf(zn)*me*(1.0f/128.0f) + zn*2e-6f + 1e-7f;
#pragma unroll
    for (int ch = 0; ch < 16; ch++) {
        if (c[ch] <= thr) {
            int p = atomicAdd(&g_lcnt[ch], 1);
            g_list[ch*BP + p] = row;
        }
    }
}

// ======================= build work-item prefix =======================
__global__ void k_items() {
    if (threadIdx.x == 0) {
        int acc = 0;
        for (int ch = 0; ch < 16; ch++) {
            g_ibase[ch] = acc;
            acc += (g_lcnt[ch] + 127) >> 7;
        }
        g_ibase[16] = acc;
    }
}

// ======================= exact pass: persistent CTAs + work queue ===========
// Bit-exact reference sequence: d = fl(fl(zn+en) - 2*dot), k-ascending fmaf,
// lowest-index tie-break, u64 atomicMin merge.
#define DN 132
#define EX_SMEM ((64*DN*2 + 256)*4 + 128*4)
__global__ __launch_bounds__(256, 2)
void k_exact(const float* __restrict__ emb) {
    extern __shared__ __align__(16) float smd[];
    float* sZ = smd;
    float* sE = smd + 64*DN;
    float* zn = sE + 64*DN;
    float* en = zn + 128;
    int* srows = (int*)(en + 128);

    __shared__ int sbase[17];
    __shared__ int sitem;

    const int tid = threadIdx.x;
    const int tx = tid & 15, ty = tid >> 4;
    if (tid < 17) sbase[tid] = g_ibase[tid];

    for (;;) {
        if (tid == 0) sitem = atomicAdd(&g_wq, 1);
        __syncthreads();
        const int item = sitem;
        if (item >= sbase[16]) return;

        int ch = 0;
#pragma unroll
        for (int c = 1; c < 16; c++) if (sbase[c] <= item) ch = c;
        const int grp = item - sbase[ch];
        const int cnt = g_lcnt[ch];

        if (tid < 128) {
            int ii = grp*128 + tid;
            srows[tid] = g_list[ch*BP + (ii < cnt ? ii : grp*128)];
        }
        __syncthreads();

        const int c0 = ch * 128;
        const int r4 = tid >> 2, q = tid & 3;
#pragma unroll
        for (int p = 0; p < 2; p++) {
            int r = p*64 + r4;
            const float4* srcz = (const float4*)(g_z + (size_t)srows[r] * 64) + q*4;
            const float4* srce = (const float4*)(emb + (size_t)(c0 + r) * 64) + q*4;
#pragma unroll
            for (int s = 0; s < 4; s++) {
                float4 v = srcz[s];
                int k = q*16 + s*4;
                sZ[(k+0)*DN + r] = v.x; sZ[(k+1)*DN + r] = v.y;
                sZ[(k+2)*DN + r] = v.z; sZ[(k+3)*DN + r] = v.w;
                float4 w = srce[s];
                sE[(k+0)*DN + r] = w.x; sE[(k+1)*DN + r] = w.y;
                sE[(k+2)*DN + r] = w.z; sE[(k+3)*DN + r] = w.w;
            }
        }
        if (tid < 128) en[tid] = g_enorm[c0 + tid];
        __syncthreads();
        if (tid < 128) {
            float s = 0.0f;
            for (int k = 0; k < 64; k++) {
                float zv = sZ[k*DN + tid];
                s = __fadd_rn(s, __fmul_rn(zv, zv));
            }
            zn[tid] = s;
        }
        __syncthreads();

        float acc[8][8];
#pragma unroll
        for (int i = 0; i < 8; i++)
#pragma unroll
            for (int j = 0; j < 8; j++) acc[i][j] = 0.0f;

#pragma unroll 8
        for (int kk = 0; kk < 64; kk++) {
            float a[8], b[8];
            *(float4*)(a)     = *(const float4*)(sZ + kk*DN + ty*8);
            *(float4*)(a + 4) = *(const float4*)(sZ + kk*DN + ty*8 + 4);
            *(float4*)(b)     = *(const float4*)(sE + kk*DN + tx*8);
            *(float4*)(b + 4) = *(const float4*)(sE + kk*DN + tx*8 + 4);
#pragma unroll
            for (int i = 0; i < 8; i++)
#pragma unroll
                for (int j = 0; j < 8; j++)
                    acc[i][j] = __fmaf_rn(a[i], b[j], acc[i][j]);
        }

        float enr[8];
#pragma unroll
        for (int j = 0; j < 8; j++) enr[j] = en[tx*8 + j];
#pragma unroll
        for (int i = 0; i < 8; i++) {
            float znr = zn[ty*8 + i];
            float bd = __int_as_float(0x7f800000); int bi = 0;
#pragma unroll
            for (int j = 0; j < 8; j++) {
                float S = __fadd_rn(znr, enr[j]);
                float d = __fsub_rn(S, __fmul_rn(2.0f, acc[i][j]));
                if (d < bd) { bd = d; bi = c0 + tx*8 + j; }
            }
#pragma unroll
            for (int o = 8; o > 0; o >>= 1) {
                float od = __shfl_xor_sync(0xffffffffu, bd, o, 32);
                int   oi = __shfl_xor_sync(0xffffffffu, bi, o, 32);
                if (od < bd || (od == bd && oi < bi)) { bd = od; bi = oi; }
            }
            if (tx == 0) {
                unsigned long long key =
                    ((unsigned long long)__float_as_uint(bd) << 32) | (unsigned)bi;
                atomicMin(&g_key[srows[ty*8 + i]], key);
            }
        }
        __syncthreads();
    }
}

// ======================= key -> idx, counts, out =======================
__global__ void k_extract(float* __restrict__ out) {
    int t = blockIdx.x * blockDim.x + threadIdx.x;
    if (t < BP) {
        int w = (int)(g_key[t] & 0xFFFFFFFFull);
        g_idx[t] = w;
        out[OFF_IDX + t] = (float)w;
        atomicAdd(&g_counts[w], 1);
    }
}

// ======================= per-block pinv solve (warp per block, fp32) ========
__global__ __launch_bounds__(256)
void k_solve(const float* __restrict__ emb, const float* __restrict__ x,
             float* __restrict__ out) {
    __shared__ float  sA[8][12][64];
    __shared__ float  sx[8][64];
    __shared__ float  sG[8][12][12];
    __shared__ float  sr[8][12];
    __shared__ float  sy[8][12];
    __shared__ float  sc[8][12];
    __shared__ int    sidx[8][12], sgrp[8][12], smult[8][12], scol[8][12];
    __shared__ int    su[8];
    __shared__ double wls[8];

    const int lane = threadIdx.x & 31;
    const int w    = threadIdx.x >> 5;
    const size_t b = (size_t)blockIdx.x * 8 + w;

    if (lane < 12) sidx[w][lane] = g_idx[b*12 + lane];
    __syncwarp();
    if (lane == 0) {
        int u = 0;
        for (int j = 0; j < 12; j++) {
            int v = sidx[w][j], q = -1;
            for (int t = 0; t < u; t++)
                if (sidx[w][scol[w][t]] == v) { q = t; break; }
            if (q < 0) { q = u; scol[w][u] = j; smult[w][u] = 0; u++; }
            sgrp[w][j] = q; smult[w][q]++;
        }
        su[w] = u;
    }
    __syncwarp();

    {
        double ls = 0.0;
        const float* zr = g_z + b * 768;
        for (int t = lane; t < 768; t += 32) {
            int j = t >> 6, i = t & 63;
            float a = emb[(size_t)sidx[w][j]*64 + i];
            float z = zr[t];
            double df = (double)a - (double)z;
            ls += df*df;
            sA[w][j][i] = __fadd_rn(z, __fsub_rn(a, z));
        }
#pragma unroll
        for (int o = 16; o; o >>= 1) ls += __shfl_down_sync(0xffffffffu, ls, o);
        if (lane == 0) wls[w] = ls;
    }
    for (int t = lane; t < 64; t += 32) sx[w][t] = x[b*64 + t];
    __syncwarp();

    const int u = su[w];
    const int npair = u*(u+1)/2;
    for (int t = lane; t < npair + u; t += 32) {
        if (t < npair) {
            int qa = 0, rem = t;
            while (rem >= u - qa) { rem -= (u - qa); qa++; }
            int qb = qa + rem;
            const float* ca = sA[w][scol[w][qa]];
            const float* cb = sA[w][scol[w][qb]];
            float s = 0.0f;
            for (int k = 0; k < 64; k++) s = __fmaf_rn(ca[k], cb[k], s);
            sG[w][qa][qb] = s; sG[w][qb][qa] = s;
        } else {
            int q2 = t - npair;
            const float* ca = sA[w][scol[w][q2]];
            float s = 0.0f;
            for (int k = 0; k < 64; k++) s = __fmaf_rn(ca[k], sx[w][k], s);
            sr[w][q2] = s;
        }
    }
    __syncwarp();

    // fp32 Cholesky (cond(G) small; coeff err ~1e-5 << 1e-3 budget)
    for (int p = 0; p < u; p++) {
        if (lane == 0) sG[w][p][p] = sqrtf(sG[w][p][p]);
        __syncwarp();
        float lpp = sG[w][p][p];
        if (lane > p && lane < u) sG[w][lane][p] /= lpp;
        __syncwarp();
        int m = u - p - 1;
        int tot = m*(m+1)/2;
        for (int t = lane; t < tot; t += 32) {
            int a = 0, rem = t;
            while (rem >= m - a) { rem -= (m - a); a++; }
            int j = p + 1 + a;
            int i = j + rem;
            sG[w][i][j] -= sG[w][i][p]*sG[w][j][p];
        }
        __syncwarp();
    }
    if (lane == 0) {
        for (int p = 0; p < u; p++) {
            float s = sr[w][p];
            for (int t = 0; t < p; t++) s -= sG[w][p][t]*sy[w][t];
            sy[w][p] = s / sG[w][p][p];
        }
        for (int p = u - 1; p >= 0; p--) {
            float s = sy[w][p];
            for (int t = p + 1; t < u; t++) s -= sG[w][t][p]*sy[w][t];
            sy[w][p] = s / sG[w][p][p];
        }
    }
    __syncwarp();
    if (lane < 12) {
        int q2 = sgrp[w][lane];
        float c = sy[w][q2] / (float)smult[w][q2];
        out[OFF_COEFF + b*12 + lane] = c;
        sc[w][lane] = c;
    }
    __syncwarp();
    for (int i = lane; i < 64; i += 32) {
        float s = 0.0f;
#pragma unroll
        for (int j = 0; j < 12; j++) s = __fmaf_rn(sA[w][j][i], sc[w][j], s);
        out[OFF_XHAT + b*64 + i] = s;
    }

    __syncthreads();
    if (threadIdx.x == 0) {
        double s = 0.0;
        for (int k = 0; k < 8; k++) s += wls[k];
        g_lossp[blockIdx.x] = s;
    }
}

// ======================= scalars: loss, perplexity =======================
__global__ void k_final(float* __restrict__ out) {
    __shared__ double red[256];
    const int tid = threadIdx.x;
    double s = 0.0;
    for (int k = tid; k < NE; k += 256) {
        double p = (double)g_counts[k] / (double)BP;
        s += p * log(p + 1e-10);
    }
    red[tid] = s; __syncthreads();
    for (int o = 128; o; o >>= 1) { if (tid < o) red[tid] += red[tid + o]; __syncthreads(); }
    double perp = exp(-red[0]);
    __syncthreads();

    double ls = 0.0;
    for (int k = tid; k < 2048; k += 256) ls += g_lossp[k];
    red[tid] = ls; __syncthreads();
    for (int o = 128; o; o >>= 1) { if (tid < o) red[tid] += red[tid + o]; __syncthreads(); }

    if (tid == 0) {
        out[OFF_PERP] = (float)perp;
        out[OFF_LOSS] = (float)(red[0] * 1.25 / ((double)BP * 64.0));
    }
}

// ======================= launch =======================
extern "C" void kernel_launch(void* const* d_in, const int* in_sizes, int n_in,
                              void* d_out, int out_size) {
    const float* x      = (const float*)d_in[0];
    const float* enc_w1 = (const float*)d_in[1];
    const float* enc_b1 = (const float*)d_in[2];
    const float* res_w  = (const float*)d_in[3];
    const float* res_b  = (const float*)d_in[4];
    const float* res_g  = (const float*)d_in[5];
    const float* res_bt = (const float*)d_in[6];
    const float* enc_w2 = (const float*)d_in[7];
    const float* enc_b2 = (const float*)d_in[8];
    const float* emb    = (const float*)d_in[9];
    float* out = (float*)d_out;

    cudaFuncSetAttribute(k_exact, cudaFuncAttributeMaxDynamicSharedMemorySize, EX_SMEM);

    k_init<<<(BP + 255)/256, 256>>>();
    k_enorm<<<NE/128, 128>>>(emb);

    // encoder: Linear(64->512) -> 2x shared ResBlock -> Linear(512->768)
    k_gemm<0><<<dim3(4, 128), 256>>>(x, enc_w1, enc_b1, DENC, INDIM);
    for (int r = 0; r < 2; r++) {
        k_gemm<1><<<dim3(4, 128), 256>>>(nullptr, res_w, res_b, DENC, DENC);
        k_ln<<<BSZ, 128>>>(res_g, res_bt);
    }
    k_gemm<2><<<dim3(6, 128), 256>>>(nullptr, enc_w2, enc_b2, ZDIM, DENC);

    k_tc<<<BP/128, 256>>>();
    k_flag<<<BP/256, 256>>>();
    k_items<<<1, 32>>>();
    k_exact<<<296, 256, EX_SMEM>>>(emb);
    k_extract<<<(BP + 255)/256, 256>>>(out);
    k_solve<<<BSZ/8, 256>>>(emb, x, out);
    k_final<<<1, 256>>>(out);
}

// round 14
// speedup vs baseline: 2.0940x; 1.0024x over previous
#include <cuda_runtime.h>
#include <math.h>
#include <stdint.h>

// -------- problem constants --------
#define BSZ   16384
#define INDIM 64
#define DENC  512
#define NE    2048
#define PBAS  12
#define BP    (BSZ*PBAS)          /* 196608 */
#define ZDIM  (INDIM*PBAS)        /* 768    */

// output layout: [loss, x_hat(B*64), perplexity, idx(BP), coeff(BP)]
#define OFF_LOSS  0
#define OFF_XHAT  1
#define OFF_PERP  (1 + BSZ*INDIM)
#define OFF_IDX   (OFF_PERP + 1)
#define OFF_COEFF (OFF_IDX + BP)

// -------- device scratch (static; referenced ONLY from device code) --------
__device__ __align__(16) float    g_h[BSZ*DENC];
__device__ __align__(16) float    g_t[BSZ*DENC];
__device__ __align__(16) float    g_z[BSZ*ZDIM];
__device__ __align__(16) float    g_enorm[NE];
__device__ __align__(16) unsigned g_etf[NE*64];      // emb tf32 bits, k-pair-permuted
__device__ __align__(16) float    g_cmin[(size_t)BP*16];
__device__ int      g_lcnt[16];
__device__ int      g_list[16*BP];
__device__ int      g_ibase[17];
__device__ int      g_wq;
__device__ unsigned g_me;
__device__ unsigned long long g_key[BP];
__device__ int      g_idx[BP];
__device__ int      g_counts[NE];
__device__ double   g_lossp[2048];

// ======================= init =======================
__global__ void k_init() {
    int t = blockIdx.x * blockDim.x + threadIdx.x;
    if (t < NE) g_counts[t] = 0;
    if (t < BP) g_key[t] = 0xFFFFFFFFFFFFFFFFull;
    if (t < 16) g_lcnt[t] = 0;
    if (t == 16) g_me = 0u;
    if (t == 17) g_wq = 0;
}

// ======================= GEMM: C = A(MxK)@B(KxN) + bias =======================
// Bit-exact vs reference: single k-ascending fmaf accumulator per output.
template<int MODE>
__global__ __launch_bounds__(256, 2)
void k_gemm(const float* __restrict__ Ain, const float* __restrict__ Bm,
            const float* __restrict__ bias, int N, int K) {
    const float* A = (MODE == 0) ? Ain : g_h;
    float*       C = (MODE == 0) ? g_h : ((MODE == 1) ? g_t : g_z);

    __shared__ __align__(16) float sA[32][132];
    __shared__ __align__(16) float sB[32][132];
    const int tid = threadIdx.x;
    const int tx = tid & 15, ty = tid >> 4;
    const int m0 = blockIdx.y * 128;
    const int n0 = blockIdx.x * 128;

    const int ra  = tid >> 3;
    const int kq  = (tid & 7) << 2;
    const int rb  = tid >> 5;
    const int cq  = (tid & 31) << 2;

    float acc[8][8];
#pragma unroll
    for (int i = 0; i < 8; i++)
#pragma unroll
        for (int j = 0; j < 8; j++) acc[i][j] = 0.0f;

    float4 va[4], vb[4];
#pragma unroll
    for (int p = 0; p < 4; p++)
        va[p] = *(const float4*)(A + (size_t)(m0 + p*32 + ra) * K + kq);
#pragma unroll
    for (int p = 0; p < 4; p++)
        vb[p] = *(const float4*)(Bm + (size_t)(p*8 + rb) * N + n0 + cq);

    for (int kt = 0; kt < K; kt += 32) {
#pragma unroll
        for (int p = 0; p < 4; p++) {
            int m = p*32 + ra;
            sA[kq+0][m] = va[p].x; sA[kq+1][m] = va[p].y;
            sA[kq+2][m] = va[p].z; sA[kq+3][m] = va[p].w;
            *(float4*)(&sB[p*8 + rb][cq]) = vb[p];
        }
        if (kt + 32 < K) {
#pragma unroll
            for (int p = 0; p < 4; p++)
                va[p] = *(const float4*)(A + (size_t)(m0 + p*32 + ra) * K + kt + 32 + kq);
#pragma unroll
            for (int p = 0; p < 4; p++)
                vb[p] = *(const float4*)(Bm + (size_t)(kt + 32 + p*8 + rb) * N + n0 + cq);
        }
        __syncthreads();
#pragma unroll 8
        for (int kk = 0; kk < 32; kk++) {
            float a[8], b[8];
            *(float4*)(a)     = *(const float4*)(&sA[kk][ty*8]);
            *(float4*)(a + 4) = *(const float4*)(&sA[kk][ty*8 + 4]);
            *(float4*)(b)     = *(const float4*)(&sB[kk][tx*8]);
            *(float4*)(b + 4) = *(const float4*)(&sB[kk][tx*8 + 4]);
#pragma unroll
            for (int i = 0; i < 8; i++)
#pragma unroll
                for (int j = 0; j < 8; j++)
                    acc[i][j] = __fmaf_rn(a[i], b[j], acc[i][j]);
        }
        __syncthreads();
    }
#pragma unroll
    for (int i = 0; i < 8; i++) {
        int m = m0 + ty*8 + i;
#pragma unroll
        for (int j = 0; j < 8; j++) {
            int n = n0 + tx*8 + j;
            C[(size_t)m * N + n] = __fadd_rn(acc[i][j], bias[n]);
        }
    }
}

// ======================= h = h + relu(LN(t)*g + beta) =======================
__global__ void k_ln(const float* __restrict__ gw, const float* __restrict__ bw) {
    __shared__ float red[128];
    const int row = blockIdx.x, tid = threadIdx.x;
    const float* tr = g_t + (size_t)row * DENC;
    float*       hr = g_h + (size_t)row * DENC;

    float v[4], hv[4];
#pragma unroll
    for (int c = 0; c < 4; c++) { v[c] = tr[tid + c*128]; hv[c] = hr[tid + c*128]; }

    float s = (v[0] + v[1]) + (v[2] + v[3]);
    red[tid] = s; __syncthreads();
#pragma unroll
    for (int o = 64; o > 0; o >>= 1) { if (tid < o) red[tid] += red[tid + o]; __syncthreads(); }
    float mu = red[0] * (1.0f / 512.0f);
    __syncthreads();

    float s2 = 0.0f;
#pragma unroll
    for (int c = 0; c < 4; c++) { float d = v[c] - mu; s2 = __fadd_rn(s2, __fmul_rn(d, d)); }
    red[tid] = s2; __syncthreads();
#pragma unroll
    for (int o = 64; o > 0; o >>= 1) { if (tid < o) red[tid] += red[tid + o]; __syncthreads(); }
    float var  = red[0] * (1.0f / 512.0f);
    float rstd = 1.0f / sqrtf(__fadd_rn(var, 1e-5f));

#pragma unroll
    for (int c = 0; c < 4; c++) {
        int col = tid + c*128;
        float o = __fadd_rn(__fmul_rn(__fmul_rn(__fsub_rn(v[c], mu), rstd), gw[col]), bw[col]);
        hr[col] = __fadd_rn(hv[c], fmaxf(o, 0.0f));
    }
}

// ======================= codebook norms + permuted tf32 copy ================
// g_etf row layout: element k stored at pos = (k>>3)*8 + (k&3)*2 + ((k&7)>>2)
// so the mma B fragment pair (k, k+4) sits in adjacent words -> one LDS.64.
__global__ void k_enorm(const float* __restrict__ emb) {
    int k = blockIdx.x * blockDim.x + threadIdx.x;
    if (k < NE) {
        const float* e = emb + (size_t)k * 64;
        float s = 0.0f;
        for (int i = 0; i < 64; i++) s = __fadd_rn(s, __fmul_rn(e[i], e[i]));
        g_enorm[k] = s;
        atomicMax(&g_me, __float_as_uint(sqrtf(s)));
        for (int i = 0; i < 64; i++) {
            unsigned u;
            asm("cvt.rna.tf32.f32 %0, %1;" : "=r"(u) : "f"(e[i]));
            int pos = ((i >> 3) << 3) + ((i & 3) << 1) + ((i & 7) >> 2);
            g_etf[(size_t)k*64 + pos] = u;
        }
    }
}

// ======================= TF32 tensor-core screening pass =======================
// 128 z-rows vs all 2048 codes; s = en - 2*dot_tf32; per-(row, 128-chunk) min.
// Min folded per nt-pair: only 8 accumulator regs live -> low pressure, occ 3.
#define ZT 68
#define ZE 72
__global__ __launch_bounds__(256, 3)
void k_tc() {
    __shared__ unsigned sZt[128*ZT];
    __shared__ unsigned sEt[128*ZE];
    __shared__ float    sen[128];
    const int tid = threadIdx.x;
    const int lane = tid & 31, wid = tid >> 5;
    const int g = lane >> 2, t = lane & 3;
    const int m0 = blockIdx.x * 128;

    {   // load + cvt z rows (row-major, stride ZT, natural k order)
        int r = tid >> 1, h = (tid & 1) * 32;
        const float4* src = (const float4*)(g_z + (size_t)(m0 + r) * 64 + h);
#pragma unroll
        for (int j = 0; j < 8; j++) {
            float4 v = src[j];
            unsigned u0, u1, u2, u3;
            asm("cvt.rna.tf32.f32 %0, %1;" : "=r"(u0) : "f"(v.x));
            asm("cvt.rna.tf32.f32 %0, %1;" : "=r"(u1) : "f"(v.y));
            asm("cvt.rna.tf32.f32 %0, %1;" : "=r"(u2) : "f"(v.z));
            asm("cvt.rna.tf32.f32 %0, %1;" : "=r"(u3) : "f"(v.w));
            int k = h + j*4;
            sZt[r*ZT + k]   = u0; sZt[r*ZT + k+1] = u1;
            sZt[r*ZT + k+2] = u2; sZt[r*ZT + k+3] = u3;
        }
    }
    __syncthreads();

    // A fragments held in regs for the whole kernel
    unsigned A0[8], A1[8], A2[8], A3[8];
    const int rlo = wid*16 + g, rhi = rlo + 8;
#pragma unroll
    for (int ks = 0; ks < 8; ks++) {
        A0[ks] = sZt[rlo*ZT + ks*8 + t];
        A1[ks] = sZt[rhi*ZT + ks*8 + t];
        A2[ks] = sZt[rlo*ZT + ks*8 + t + 4];
        A3[ks] = sZt[rhi*ZT + ks*8 + t + 4];
    }

    for (int ch = 0; ch < 16; ch++) {
        __syncthreads();
        {   // load e chunk (pre-permuted tf32 bits) + en — contiguous copy
            int r = tid >> 1, h = (tid & 1) * 32;
            const uint4* src = (const uint4*)(g_etf + (size_t)(ch*128 + r)*64 + h);
#pragma unroll
            for (int j = 0; j < 8; j++) {
                uint4 v = src[j];
                int k = h + j*4;
                sEt[r*ZE + k]   = v.x; sEt[r*ZE + k+1] = v.y;
                sEt[r*ZE + k+2] = v.z; sEt[r*ZE + k+3] = v.w;
            }
            if (tid < 128) sen[tid] = g_enorm[ch*128 + tid];
        }
        __syncthreads();

        float mlo = __int_as_float(0x7f800000), mhi = mlo;
#pragma unroll
        for (int nt = 0; nt < 16; nt += 2) {
            // two independent mma chains for ILP; only 8 acc regs live
            float a0[4] = {0.f, 0.f, 0.f, 0.f};
            float a1[4] = {0.f, 0.f, 0.f, 0.f};
#pragma unroll
            for (int ks = 0; ks < 8; ks++) {
                uint2 b0 = *(const uint2*)(&sEt[(nt*8 + g)*ZE + ks*8 + 2*t]);
                uint2 b1 = *(const uint2*)(&sEt[((nt+1)*8 + g)*ZE + ks*8 + 2*t]);
                asm("mma.sync.aligned.m16n8k8.row.col.f32.tf32.tf32.f32 "
                    "{%0,%1,%2,%3}, {%4,%5,%6,%7}, {%8,%9}, {%0,%1,%2,%3};"
                    : "+f"(a0[0]), "+f"(a0[1]), "+f"(a0[2]), "+f"(a0[3])
                    : "r"(A0[ks]), "r"(A1[ks]), "r"(A2[ks]), "r"(A3[ks]),
                      "r"(b0.x), "r"(b0.y));
                asm("mma.sync.aligned.m16n8k8.row.col.f32.tf32.tf32.f32 "
                    "{%0,%1,%2,%3}, {%4,%5,%6,%7}, {%8,%9}, {%0,%1,%2,%3};"
                    : "+f"(a1[0]), "+f"(a1[1]), "+f"(a1[2]), "+f"(a1[3])
                    : "r"(A0[ks]), "r"(A1[ks]), "r"(A2[ks]), "r"(A3[ks]),
                      "r"(b1.x), "r"(b1.y));
            }
            float2 e0 = *(const float2*)&sen[nt*8 + 2*t];
            float2 e1 = *(const float2*)&sen[(nt+1)*8 + 2*t];
            float s;
            s = e0.x - 2.0f*a0[0]; if (s < mlo) mlo = s;
            s = e0.y - 2.0f*a0[1]; if (s < mlo) mlo = s;
            s = e0.x - 2.0f*a0[2]; if (s < mhi) mhi = s;
            s = e0.y - 2.0f*a0[3]; if (s < mhi) mhi = s;
            s = e1.x - 2.0f*a1[0]; if (s < mlo) mlo = s;
            s = e1.y - 2.0f*a1[1]; if (s < mlo) mlo = s;
            s = e1.x - 2.0f*a1[2]; if (s < mhi) mhi = s;
            s = e1.y - 2.0f*a1[3]; if (s < mhi) mhi = s;
        }
#pragma unroll
        for (int o = 1; o <= 2; o <<= 1) {
            float x = __shfl_xor_sync(0xffffffffu, mlo, o, 32); if (x < mlo) mlo = x;
            float y = __shfl_xor_sync(0xffffffffu, mhi, o, 32); if (y < mhi) mhi = y;
        }
        if (t == 0) {
            g_cmin[(size_t)(m0 + rlo)*16 + ch] = mlo;
            g_cmin[(size_t)(m0 + rhi)*16 + ch] = mhi;
        }
    }
}

// ======================= flag chunks within margin of row min ===============
__global__ void k_flag() {
    int row = blockIdx.x * blockDim.x + threadIdx.x;
    if (row >= BP) return;
    const float4* zr = (const float4*)(g_z + (size_t)row * 64);
    float zn = 0.0f;
#pragma unroll
    for (int j = 0; j < 16; j++) {
        float4 v = zr[j];
        zn += v.x*v.x + v.y*v.y + v.z*v.z + v.w*v.w;
    }
    float c[16];
    float m = __int_as_float(0x7f800000);
#pragma unroll
    for (int ch = 0; ch < 16; ch++) {
        c[ch] = g_cmin[(size_t)row*16 + ch];
        if (c[ch] < m) m = c[ch];
    }
    float me = __uint_as_float(g_me);
    float thr = m + sqrtf(zn)*me*(1.0f/128.0f) + zn*2e-6f + 1e-7f;
#pragma unroll
    for (int ch = 0; ch < 16; ch++) {
        if (c[ch] <= thr) {
            int p = atomicAdd(&g_lcnt[ch], 1);
            g_list[ch*BP + p] = row;
        }
    }
}

// ======================= build work-item prefix =======================
__global__ void k_items() {
    if (threadIdx.x == 0) {
        int acc = 0;
        for (int ch = 0; ch < 16; ch++) {
            g_ibase[ch] = acc;
            acc += (g_lcnt[ch] + 127) >> 7;
        }
        g_ibase[16] = acc;
    }
}

// ======================= exact pass: persistent CTAs + work queue ===========
// Bit-exact reference sequence: d = fl(fl(zn+en) - 2*dot), k-ascending fmaf,
// lowest-index tie-break, u64 atomicMin merge.
#define DN 132
#define EX_SMEM ((64*DN*2 + 256)*4 + 128*4)
__global__ __launch_bounds__(256, 2)
void k_exact(const float* __restrict__ emb) {
    extern __shared__ __align__(16) float smd[];
    float* sZ = smd;
    float* sE = smd + 64*DN;
    float* zn = sE + 64*DN;
    float* en = zn + 128;
    int* srows = (int*)(en + 128);

    __shared__ int sbase[17];
    __shared__ int sitem;

    const int tid = threadIdx.x;
    const int tx = tid & 15, ty = tid >> 4;
    if (tid < 17) sbase[tid] = g_ibase[tid];

    for (;;) {
        if (tid == 0) sitem = atomicAdd(&g_wq, 1);
        __syncthreads();
        const int item = sitem;
        if (item >= sbase[16]) return;

        int ch = 0;
#pragma unroll
        for (int c = 1; c < 16; c++) if (sbase[c] <= item) ch = c;
        const int grp = item - sbase[ch];
        const int cnt = g_lcnt[ch];

        if (tid < 128) {
            int ii = grp*128 + tid;
            srows[tid] = g_list[ch*BP + (ii < cnt ? ii : grp*128)];
        }
        __syncthreads();

        const int c0 = ch * 128;
        const int r4 = tid >> 2, q = tid & 3;
#pragma unroll
        for (int p = 0; p < 2; p++) {
            int r = p*64 + r4;
            const float4* srcz = (const float4*)(g_z + (size_t)srows[r] * 64) + q*4;
            const float4* srce = (const float4*)(emb + (size_t)(c0 + r) * 64) + q*4;
#pragma unroll
            for (int s = 0; s < 4; s++) {
                float4 v = srcz[s];
                int k = q*16 + s*4;
                sZ[(k+0)*DN + r] = v.x; sZ[(k+1)*DN + r] = v.y;
                sZ[(k+2)*DN + r] = v.z; sZ[(k+3)*DN + r] = v.w;
                float4 w = srce[s];
                sE[(k+0)*DN + r] = w.x; sE[(k+1)*DN + r] = w.y;
                sE[(k+2)*DN + r] = w.z; sE[(k+3)*DN + r] = w.w;
            }
        }
        if (tid < 128) en[tid] = g_enorm[c0 + tid];
        __syncthreads();
        if (tid < 128) {
            float s = 0.0f;
            for (int k = 0; k < 64; k++) {
                float zv = sZ[k*DN + tid];
                s = __fadd_rn(s, __fmul_rn(zv, zv));
            }
            zn[tid] = s;
        }
        __syncthreads();

        float acc[8][8];
#pragma unroll
        for (int i = 0; i < 8; i++)
#pragma unroll
            for (int j = 0; j < 8; j++) acc[i][j] = 0.0f;

#pragma unroll 8
        for (int kk = 0; kk < 64; kk++) {
            float a[8], b[8];
            *(float4*)(a)     = *(const float4*)(sZ + kk*DN + ty*8);
            *(float4*)(a + 4) = *(const float4*)(sZ + kk*DN + ty*8 + 4);
            *(float4*)(b)     = *(const float4*)(sE + kk*DN + tx*8);
            *(float4*)(b + 4) = *(const float4*)(sE + kk*DN + tx*8 + 4);
#pragma unroll
            for (int i = 0; i < 8; i++)
#pragma unroll
                for (int j = 0; j < 8; j++)
                    acc[i][j] = __fmaf_rn(a[i], b[j], acc[i][j]);
        }

        float enr[8];
#pragma unroll
        for (int j = 0; j < 8; j++) enr[j] = en[tx*8 + j];
#pragma unroll
        for (int i = 0; i < 8; i++) {
            float znr = zn[ty*8 + i];
            float bd = __int_as_float(0x7f800000); int bi = 0;
#pragma unroll
            for (int j = 0; j < 8; j++) {
                float S = __fadd_rn(znr, enr[j]);
                float d = __fsub_rn(S, __fmul_rn(2.0f, acc[i][j]));
                if (d < bd) { bd = d; bi = c0 + tx*8 + j; }
            }
#pragma unroll
            for (int o = 8; o > 0; o >>= 1) {
                float od = __shfl_xor_sync(0xffffffffu, bd, o, 32);
                int   oi = __shfl_xor_sync(0xffffffffu, bi, o, 32);
                if (od < bd || (od == bd && oi < bi)) { bd = od; bi = oi; }
            }
            if (tx == 0) {
                unsigned long long key =
                    ((unsigned long long)__float_as_uint(bd) << 32) | (unsigned)bi;
                atomicMin(&g_key[srows[ty*8 + i]], key);
            }
        }
        __syncthreads();
    }
}

// ======================= key -> idx, counts, out =======================
__global__ void k_extract(float* __restrict__ out) {
    int t = blockIdx.x * blockDim.x + threadIdx.x;
    if (t < BP) {
        int w = (int)(g_key[t] & 0xFFFFFFFFull);
        g_idx[t] = w;
        out[OFF_IDX + t] = (float)w;
        atomicAdd(&g_counts[w], 1);
    }
}

// ======================= per-block pinv solve (warp per block, fp32) ========
__global__ __launch_bounds__(256)
void k_solve(const float* __restrict__ emb, const float* __restrict__ x,
             float* __restrict__ out) {
    __shared__ float  sA[8][12][64];
    __shared__ float  sx[8][64];
    __shared__ float  sG[8][12][12];
    __shared__ float  sr[8][12];
    __shared__ float  sy[8][12];
    __shared__ float  sc[8][12];
    __shared__ int    sidx[8][12], sgrp[8][12], smult[8][12], scol[8][12];
    __shared__ int    su[8];
    __shared__ double wls[8];

    const int lane = threadIdx.x & 31;
    const int w    = threadIdx.x >> 5;
    const size_t b = (size_t)blockIdx.x * 8 + w;

    if (lane < 12) sidx[w][lane] = g_idx[b*12 + lane];
    __syncwarp();
    if (lane == 0) {
        int u = 0;
        for (int j = 0; j < 12; j++) {
            int v = sidx[w][j], q = -1;
            for (int t = 0; t < u; t++)
                if (sidx[w][scol[w][t]] == v) { q = t; break; }
            if (q < 0) { q = u; scol[w][u] = j; smult[w][u] = 0; u++; }
            sgrp[w][j] = q; smult[w][q]++;
        }
        su[w] = u;
    }
    __syncwarp();

    {
        double ls = 0.0;
        const float* zr = g_z + b * 768;
        for (int t = lane; t < 768; t += 32) {
            int j = t >> 6, i = t & 63;
            float a = emb[(size_t)sidx[w][j]*64 + i];
            float z = zr[t];
            double df = (double)a - (double)z;
            ls += df*df;
            sA[w][j][i] = __fadd_rn(z, __fsub_rn(a, z));
        }
#pragma unroll
        for (int o = 16; o; o >>= 1) ls += __shfl_down_sync(0xffffffffu, ls, o);
        if (lane == 0) wls[w] = ls;
    }
    for (int t = lane; t < 64; t += 32) sx[w][t] = x[b*64 + t];
    __syncwarp();

    const int u = su[w];
    const int npair = u*(u+1)/2;
    for (int t = lane; t < npair + u; t += 32) {
        if (t < npair) {
            int qa = 0, rem = t;
            while (rem >= u - qa) { rem -= (u - qa); qa++; }
            int qb = qa + rem;
            const float* ca = sA[w][scol[w][qa]];
            const float* cb = sA[w][scol[w][qb]];
            float s = 0.0f;
            for (int k = 0; k < 64; k++) s = __fmaf_rn(ca[k], cb[k], s);
            sG[w][qa][qb] = s; sG[w][qb][qa] = s;
        } else {
            int q2 = t - npair;
            const float* ca = sA[w][scol[w][q2]];
            float s = 0.0f;
            for (int k = 0; k < 64; k++) s = __fmaf_rn(ca[k], sx[w][k], s);
            sr[w][q2] = s;
        }
    }
    __syncwarp();

    // fp32 Cholesky (cond(G) small; coeff err ~1e-5 << 1e-3 budget)
    for (int p = 0; p < u; p++) {
        if (lane == 0) sG[w][p][p] = sqrtf(sG[w][p][p]);
        __syncwarp();
        float lpp = sG[w][p][p];
        if (lane > p && lane < u) sG[w][lane][p] /= lpp;
        __syncwarp();
        int m = u - p - 1;
        int tot = m*(m+1)/2;
        for (int t = lane; t < tot; t += 32) {
            int a = 0, rem = t;
            while (rem >= m - a) { rem -= (m - a); a++; }
            int j = p + 1 + a;
            int i = j + rem;
            sG[w][i][j] -= sG[w][i][p]*sG[w][j][p];
        }
        __syncwarp();
    }
    if (lane == 0) {
        for (int p = 0; p < u; p++) {
            float s = sr[w][p];
            for (int t = 0; t < p; t++) s -= sG[w][p][t]*sy[w][t];
            sy[w][p] = s / sG[w][p][p];
        }
        for (int p = u - 1; p >= 0; p--) {
            float s = sy[w][p];
            for (int t = p + 1; t < u; t++) s -= sG[w][t][p]*sy[w][t];
            sy[w][p] = s / sG[w][p][p];
        }
    }
    __syncwarp();
    if (lane < 12) {
        int q2 = sgrp[w][lane];
        float c = sy[w][q2] / (float)smult[w][q2];
        out[OFF_COEFF + b*12 + lane] = c;
        sc[w][lane] = c;
    }
    __syncwarp();
    for (int i = lane; i < 64; i += 32) {
        float s = 0.0f;
#pragma unroll
        for (int j = 0; j < 12; j++) s = __fmaf_rn(sA[w][j][i], sc[w][j], s);
        out[OFF_XHAT + b*64 + i] = s;
    }

    __syncthreads();
    if (threadIdx.x == 0) {
        double s = 0.0;
        for (int k = 0; k < 8; k++) s += wls[k];
        g_lossp[blockIdx.x] = s;
    }
}

// ======================= scalars: loss, perplexity =======================
__global__ void k_final(float* __restrict__ out) {
    __shared__ double red[256];
    const int tid = threadIdx.x;
    double s = 0.0;
    for (int k = tid; k < NE; k += 256) {
        double p = (double)g_counts[k] / (double)BP;
        s += p * log(p + 1e-10);
    }
    red[tid] = s; __syncthreads();
    for (int o = 128; o; o >>= 1) { if (tid < o) red[tid] += red[tid + o]; __syncthreads(); }
    double perp = exp(-red[0]);
    __syncthreads();

    double ls = 0.0;
    for (int k = tid; k < 2048; k += 256) ls += g_lossp[k];
    red[tid] = ls; __syncthreads();
    for (int o = 128; o; o >>= 1) { if (tid < o) red[tid] += red[tid + o]; __syncthreads(); }

    if (tid == 0) {
        out[OFF_PERP] = (float)perp;
        out[OFF_LOSS] = (float)(red[0] * 1.25 / ((double)BP * 64.0));
    }
}

// ======================= launch =======================
extern "C" void kernel_launch(void* const* d_in, const int* in_sizes, int n_in,
                              void* d_out, int out_size) {
    const float* x      = (const float*)d_in[0];
    const float* enc_w1 = (const float*)d_in[1];
    const float* enc_b1 = (const float*)d_in[2];
    const float* res_w  = (const float*)d_in[3];
    const float* res_b  = (const float*)d_in[4];
    const float* res_g  = (const float*)d_in[5];
    const float* res_bt = (const float*)d_in[6];
    const float* enc_w2 = (const float*)d_in[7];
    const float* enc_b2 = (const float*)d_in[8];
    const float* emb    = (const float*)d_in[9];
    float* out = (float*)d_out;

    cudaFuncSetAttribute(k_exact, cudaFuncAttributeMaxDynamicSharedMemorySize, EX_SMEM);

    k_init<<<(BP + 255)/256, 256>>>();
    k_enorm<<<NE/128, 128>>>(emb);

    // encoder: Linear(64->512) -> 2x shared ResBlock -> Linear(512->768)
    k_gemm<0><<<dim3(4, 128), 256>>>(x, enc_w1, enc_b1, DENC, INDIM);
    for (int r = 0; r < 2; r++) {
        k_gemm<1><<<dim3(4, 128), 256>>>(nullptr, res_w, res_b, DENC, DENC);
        k_ln<<<BSZ, 128>>>(res_g, res_bt);
    }
    k_gemm<2><<<dim3(6, 128), 256>>>(nullptr, enc_w2, enc_b2, ZDIM, DENC);

    k_tc<<<BP/128, 256>>>();
    k_flag<<<BP/256, 256>>>();
    k_items<<<1, 32>>>();
    k_exact<<<296, 256, EX_SMEM>>>(emb);
    k_extract<<<(BP + 255)/256, 256>>>(out);
    k_solve<<<BSZ/8, 256>>>(emb, x, out);
    k_final<<<1, 256>>>(out);
}

// round 15
// speedup vs baseline: 2.1288x; 1.0166x over previous
#include <cuda_runtime.h>
#include <math.h>
#include <stdint.h>

// -------- problem constants --------
#define BSZ   16384
#define INDIM 64
#define DENC  512
#define NE    2048
#define PBAS  12
#define BP    (BSZ*PBAS)          /* 196608 */
#define ZDIM  (INDIM*PBAS)        /* 768    */

// output layout: [loss, x_hat(B*64), perplexity, idx(BP), coeff(BP)]
#define OFF_LOSS  0
#define OFF_XHAT  1
#define OFF_PERP  (1 + BSZ*INDIM)
#define OFF_IDX   (OFF_PERP + 1)
#define OFF_COEFF (OFF_IDX + BP)

// -------- device scratch (static; referenced ONLY from device code) --------
__device__ __align__(16) float    g_h[BSZ*DENC];
__device__ __align__(16) float    g_t[BSZ*DENC];
__device__ __align__(16) float    g_z[BSZ*ZDIM];
__device__ __align__(16) float    g_enorm[NE];
__device__ __align__(16) unsigned g_etf[NE*64];      // emb tf32 bits, k-pair-permuted
__device__ __align__(16) float    g_cmin[(size_t)BP*16];
__device__ int      g_lcnt[16];
__device__ int      g_list[16*BP];
__device__ int      g_ibase[17];
__device__ int      g_wq;
__device__ unsigned g_me;
__device__ unsigned long long g_key[BP];
__device__ int      g_idx[BP];
__device__ int      g_counts[NE];
__device__ double   g_lossp[2048];

// packed dual-FMA: two independent rn fmas per instruction (bit-exact per lane)
__device__ __forceinline__ void fma2(unsigned long long& acc,
                                     unsigned long long a, unsigned long long b) {
    asm("fma.rn.f32x2 %0, %1, %2, %0;" : "+l"(acc) : "l"(a), "l"(b));
}
__device__ __forceinline__ unsigned long long dup2(float a) {
    unsigned long long d;
    asm("mov.b64 %0, {%1, %1};" : "=l"(d) : "f"(a));
    return d;
}
__device__ __forceinline__ float2 u2f(unsigned long long u) {
    float2 f;
    asm("mov.b64 {%0, %1}, %2;" : "=f"(f.x), "=f"(f.y) : "l"(u));
    return f;
}

// ======================= init =======================
__global__ void k_init() {
    int t = blockIdx.x * blockDim.x + threadIdx.x;
    if (t < NE) g_counts[t] = 0;
    if (t < BP) g_key[t] = 0xFFFFFFFFFFFFFFFFull;
    if (t < 16) g_lcnt[t] = 0;
    if (t == 16) g_me = 0u;
    if (t == 17) g_wq = 0;
}

// ======================= GEMM: C = A(MxK)@B(KxN) + bias (f32x2) ============
// Bit-exact vs reference: each output is one k-ascending rn-fma chain (lane of
// fma.rn.f32x2). A packed {a,a} via mov.b64 (reused x4); B pairs via LDS.64.
template<int MODE>
__global__ __launch_bounds__(256, 2)
void k_gemm(const float* __restrict__ Ain, const float* __restrict__ Bm,
            const float* __restrict__ bias, int N, int K) {
    const float* A = (MODE == 0) ? Ain : g_h;
    float*       C = (MODE == 0) ? g_h : ((MODE == 1) ? g_t : g_z);

    __shared__ __align__(16) float sA[32][132];
    __shared__ __align__(16) float sB[32][132];
    const int tid = threadIdx.x;
    const int tx = tid & 15, ty = tid >> 4;
    const int m0 = blockIdx.y * 128;
    const int n0 = blockIdx.x * 128;

    const int ra  = tid >> 3;          // A: row group 0..31
    const int kq  = (tid & 7) << 2;    // A: k quad
    const int rb  = tid >> 5;          // B: k row 0..7
    const int cq  = (tid & 31) << 2;   // B: col quad

    unsigned long long acc2[8][4];
#pragma unroll
    for (int i = 0; i < 8; i++)
#pragma unroll
        for (int j = 0; j < 4; j++) acc2[i][j] = 0ull;

    for (int kt = 0; kt < K; kt += 32) {
#pragma unroll
        for (int p = 0; p < 4; p++) {
            const float4 v = *(const float4*)(A + (size_t)(m0 + p*32 + ra) * K + kt + kq);
            int m = p*32 + ra;
            sA[kq+0][m] = v.x; sA[kq+1][m] = v.y;
            sA[kq+2][m] = v.z; sA[kq+3][m] = v.w;
        }
#pragma unroll
        for (int p = 0; p < 4; p++) {
            const float4 v = *(const float4*)(Bm + (size_t)(kt + p*8 + rb) * N + n0 + cq);
            *(float4*)(&sB[p*8 + rb][cq]) = v;
        }
        __syncthreads();
#pragma unroll 8
        for (int kk = 0; kk < 32; kk++) {
            float a[8];
            *(float4*)(a)     = *(const float4*)(&sA[kk][ty*8]);
            *(float4*)(a + 4) = *(const float4*)(&sA[kk][ty*8 + 4]);
            unsigned long long bp[4];
#pragma unroll
            for (int j = 0; j < 4; j++)
                bp[j] = *(const unsigned long long*)(&sB[kk][tx*8 + 2*j]);
#pragma unroll
            for (int i = 0; i < 8; i++) {
                unsigned long long ap = dup2(a[i]);
#pragma unroll
                for (int j = 0; j < 4; j++)
                    fma2(acc2[i][j], ap, bp[j]);
            }
        }
        __syncthreads();
    }
#pragma unroll
    for (int i = 0; i < 8; i++) {
        int m = m0 + ty*8 + i;
#pragma unroll
        for (int j = 0; j < 4; j++) {
            int n = n0 + tx*8 + 2*j;
            float2 v = u2f(acc2[i][j]);
            C[(size_t)m * N + n]     = __fadd_rn(v.x, bias[n]);
            C[(size_t)m * N + n + 1] = __fadd_rn(v.y, bias[n + 1]);
        }
    }
}

// ======================= h = h + relu(LN(t)*g + beta) =======================
__global__ void k_ln(const float* __restrict__ gw, const float* __restrict__ bw) {
    __shared__ float red[128];
    const int row = blockIdx.x, tid = threadIdx.x;
    const float* tr = g_t + (size_t)row * DENC;
    float*       hr = g_h + (size_t)row * DENC;

    float v[4], hv[4];
#pragma unroll
    for (int c = 0; c < 4; c++) { v[c] = tr[tid + c*128]; hv[c] = hr[tid + c*128]; }

    float s = (v[0] + v[1]) + (v[2] + v[3]);
    red[tid] = s; __syncthreads();
#pragma unroll
    for (int o = 64; o > 0; o >>= 1) { if (tid < o) red[tid] += red[tid + o]; __syncthreads(); }
    float mu = red[0] * (1.0f / 512.0f);
    __syncthreads();

    float s2 = 0.0f;
#pragma unroll
    for (int c = 0; c < 4; c++) { float d = v[c] - mu; s2 = __fadd_rn(s2, __fmul_rn(d, d)); }
    red[tid] = s2; __syncthreads();
#pragma unroll
    for (int o = 64; o > 0; o >>= 1) { if (tid < o) red[tid] += red[tid + o]; __syncthreads(); }
    float var  = red[0] * (1.0f / 512.0f);
    float rstd = 1.0f / sqrtf(__fadd_rn(var, 1e-5f));

#pragma unroll
    for (int c = 0; c < 4; c++) {
        int col = tid + c*128;
        float o = __fadd_rn(__fmul_rn(__fmul_rn(__fsub_rn(v[c], mu), rstd), gw[col]), bw[col]);
        hr[col] = __fadd_rn(hv[c], fmaxf(o, 0.0f));
    }
}

// ======================= codebook norms + permuted tf32 copy ================
// g_etf row layout: element k stored at pos = (k>>3)*8 + (k&3)*2 + ((k&7)>>2)
// so the mma B fragment pair (k, k+4) sits in adjacent words -> one LDS.64.
__global__ void k_enorm(const float* __restrict__ emb) {
    int k = blockIdx.x * blockDim.x + threadIdx.x;
    if (k < NE) {
        const float* e = emb + (size_t)k * 64;
        float s = 0.0f;
        for (int i = 0; i < 64; i++) s = __fadd_rn(s, __fmul_rn(e[i], e[i]));
        g_enorm[k] = s;
        atomicMax(&g_me, __float_as_uint(sqrtf(s)));
        for (int i = 0; i < 64; i++) {
            unsigned u;
            asm("cvt.rna.tf32.f32 %0, %1;" : "=r"(u) : "f"(e[i]));
            int pos = ((i >> 3) << 3) + ((i & 3) << 1) + ((i & 7) >> 2);
            g_etf[(size_t)k*64 + pos] = u;
        }
    }
}

// ======================= TF32 tensor-core screening pass =======================
// 128 z-rows vs all 2048 codes; s = en - 2*dot_tf32; per-(row, 128-chunk) min.
#define ZT 68
#define ZE 72
__global__ __launch_bounds__(256, 3)
void k_tc() {
    __shared__ unsigned sZt[128*ZT];
    __shared__ unsigned sEt[128*ZE];
    __shared__ float    sen[128];
    const int tid = threadIdx.x;
    const int lane = tid & 31, wid = tid >> 5;
    const int g = lane >> 2, t = lane & 3;
    const int m0 = blockIdx.x * 128;

    {   // load + cvt z rows (row-major, stride ZT, natural k order)
        int r = tid >> 1, h = (tid & 1) * 32;
        const float4* src = (const float4*)(g_z + (size_t)(m0 + r) * 64 + h);
#pragma unroll
        for (int j = 0; j < 8; j++) {
            float4 v = src[j];
            unsigned u0, u1, u2, u3;
            asm("cvt.rna.tf32.f32 %0, %1;" : "=r"(u0) : "f"(v.x));
            asm("cvt.rna.tf32.f32 %0, %1;" : "=r"(u1) : "f"(v.y));
            asm("cvt.rna.tf32.f32 %0, %1;" : "=r"(u2) : "f"(v.z));
            asm("cvt.rna.tf32.f32 %0, %1;" : "=r"(u3) : "f"(v.w));
            int k = h + j*4;
            sZt[r*ZT + k]   = u0; sZt[r*ZT + k+1] = u1;
            sZt[r*ZT + k+2] = u2; sZt[r*ZT + k+3] = u3;
        }
    }
    __syncthreads();

    // A fragments held in regs for the whole kernel
    unsigned A0[8], A1[8], A2[8], A3[8];
    const int rlo = wid*16 + g, rhi = rlo + 8;
#pragma unroll
    for (int ks = 0; ks < 8; ks++) {
        A0[ks] = sZt[rlo*ZT + ks*8 + t];
        A1[ks] = sZt[rhi*ZT + ks*8 + t];
        A2[ks] = sZt[rlo*ZT + ks*8 + t + 4];
        A3[ks] = sZt[rhi*ZT + ks*8 + t + 4];
    }

    for (int ch = 0; ch < 16; ch++) {
        __syncthreads();
        {   // load e chunk (pre-permuted tf32 bits) + en — contiguous copy
            int r = tid >> 1, h = (tid & 1) * 32;
            const uint4* src = (const uint4*)(g_etf + (size_t)(ch*128 + r)*64 + h);
#pragma unroll
            for (int j = 0; j < 8; j++) {
                uint4 v = src[j];
                int k = h + j*4;
                sEt[r*ZE + k]   = v.x; sEt[r*ZE + k+1] = v.y;
                sEt[r*ZE + k+2] = v.z; sEt[r*ZE + k+3] = v.w;
            }
            if (tid < 128) sen[tid] = g_enorm[ch*128 + tid];
        }
        __syncthreads();

        float mlo = __int_as_float(0x7f800000), mhi = mlo;
#pragma unroll
        for (int nt = 0; nt < 16; nt += 2) {
            float a0[4] = {0.f, 0.f, 0.f, 0.f};
            float a1[4] = {0.f, 0.f, 0.f, 0.f};
#pragma unroll
            for (int ks = 0; ks < 8; ks++) {
                uint2 b0 = *(const uint2*)(&sEt[(nt*8 + g)*ZE + ks*8 + 2*t]);
                uint2 b1 = *(const uint2*)(&sEt[((nt+1)*8 + g)*ZE + ks*8 + 2*t]);
                asm("mma.sync.aligned.m16n8k8.row.col.f32.tf32.tf32.f32 "
                    "{%0,%1,%2,%3}, {%4,%5,%6,%7}, {%8,%9}, {%0,%1,%2,%3};"
                    : "+f"(a0[0]), "+f"(a0[1]), "+f"(a0[2]), "+f"(a0[3])
                    : "r"(A0[ks]), "r"(A1[ks]), "r"(A2[ks]), "r"(A3[ks]),
                      "r"(b0.x), "r"(b0.y));
                asm("mma.sync.aligned.m16n8k8.row.col.f32.tf32.tf32.f32 "
                    "{%0,%1,%2,%3}, {%4,%5,%6,%7}, {%8,%9}, {%0,%1,%2,%3};"
                    : "+f"(a1[0]), "+f"(a1[1]), "+f"(a1[2]), "+f"(a1[3])
                    : "r"(A0[ks]), "r"(A1[ks]), "r"(A2[ks]), "r"(A3[ks]),
                      "r"(b1.x), "r"(b1.y));
            }
            float2 e0 = *(const float2*)&sen[nt*8 + 2*t];
            float2 e1 = *(const float2*)&sen[(nt+1)*8 + 2*t];
            float s;
            s = e0.x - 2.0f*a0[0]; if (s < mlo) mlo = s;
            s = e0.y - 2.0f*a0[1]; if (s < mlo) mlo = s;
            s = e0.x - 2.0f*a0[2]; if (s < mhi) mhi = s;
            s = e0.y - 2.0f*a0[3]; if (s < mhi) mhi = s;
            s = e1.x - 2.0f*a1[0]; if (s < mlo) mlo = s;
            s = e1.y - 2.0f*a1[1]; if (s < mlo) mlo = s;
            s = e1.x - 2.0f*a1[2]; if (s < mhi) mhi = s;
            s = e1.y - 2.0f*a1[3]; if (s < mhi) mhi = s;
        }
#pragma unroll
        for (int o = 1; o <= 2; o <<= 1) {
            float x = __shfl_xor_sync(0xffffffffu, mlo, o, 32); if (x < mlo) mlo = x;
            float y = __shfl_xor_sync(0xffffffffu, mhi, o, 32); if (y < mhi) mhi = y;
        }
        if (t == 0) {
            g_cmin[(size_t)(m0 + rlo)*16 + ch] = mlo;
            g_cmin[(size_t)(m0 + rhi)*16 + ch] = mhi;
        }
    }
}

// ======================= flag chunks within margin of row min ===============
__global__ void k_flag() {
    int row = blockIdx.x * blockDim.x + threadIdx.x;
    if (row >= BP) return;
    const float4* zr = (const float4*)(g_z + (size_t)row * 64);
    float zn = 0.0f;
#pragma unroll
    for (int j = 0; j < 16; j++) {
        float4 v = zr[j];
        zn += v.x*v.x + v.y*v.y + v.z*v.z + v.w*v.w;
    }
    float c[16];
    float m = __int_as_float(0x7f800000);
#pragma unroll
    for (int ch = 0; ch < 16; ch++) {
        c[ch] = g_cmin[(size_t)row*16 + ch];
        if (c[ch] < m) m = c[ch];
    }
    float me = __uint_as_float(g_me);
    float thr = m + sqrtf(zn)*me*(1.0f/128.0f) + zn*2e-6f + 1e-7f;
#pragma unroll
    for (int ch = 0; ch < 16; ch++) {
        if (c[ch] <= thr) {
            int p = atomicAdd(&g_lcnt[ch], 1);
            g_list[ch*BP + p] = row;
        }
    }
}

// ======================= build work-item prefix =======================
__global__ void k_items() {
    if (threadIdx.x == 0) {
        int acc = 0;
        for (int ch = 0; ch < 16; ch++) {
            g_ibase[ch] = acc;
            acc += (g_lcnt[ch] + 127) >> 7;
        }
        g_ibase[16] = acc;
    }
}

// ======================= exact pass: persistent CTAs + work queue ===========
// Bit-exact reference sequence: d = fl(fl(zn+en) - 2*dot), k-ascending fmaf,
// lowest-index tie-break, u64 atomicMin merge.
#define DN 132
#define EX_SMEM ((64*DN*2 + 256)*4 + 128*4)
__global__ __launch_bounds__(256, 2)
void k_exact(const float* __restrict__ emb) {
    extern __shared__ __align__(16) float smd[];
    float* sZ = smd;
    float* sE = smd + 64*DN;
    float* zn = sE + 64*DN;
    float* en = zn + 128;
    int* srows = (int*)(en + 128);

    __shared__ int sbase[17];
    __shared__ int sitem;

    const int tid = threadIdx.x;
    const int tx = tid & 15, ty = tid >> 4;
    if (tid < 17) sbase[tid] = g_ibase[tid];

    for (;;) {
        if (tid == 0) sitem = atomicAdd(&g_wq, 1);
        __syncthreads();
        const int item = sitem;
        if (item >= sbase[16]) return;

        int ch = 0;
#pragma unroll
        for (int c = 1; c < 16; c++) if (sbase[c] <= item) ch = c;
        const int grp = item - sbase[ch];
        const int cnt = g_lcnt[ch];

        if (tid < 128) {
            int ii = grp*128 + tid;
            srows[tid] = g_list[ch*BP + (ii < cnt ? ii : grp*128)];
        }
        __syncthreads();

        const int c0 = ch * 128;
        const int r4 = tid >> 2, q = tid & 3;
#pragma unroll
        for (int p = 0; p < 2; p++) {
            int r = p*64 + r4;
            const float4* srcz = (const float4*)(g_z + (size_t)srows[r] * 64) + q*4;
            const float4* srce = (const float4*)(emb + (size_t)(c0 + r) * 64) + q*4;
#pragma unroll
            for (int s = 0; s < 4; s++) {
                float4 v = srcz[s];
                int k = q*16 + s*4;
                sZ[(k+0)*DN + r] = v.x; sZ[(k+1)*DN + r] = v.y;
                sZ[(k+2)*DN + r] = v.z; sZ[(k+3)*DN + r] = v.w;
                float4 w = srce[s];
                sE[(k+0)*DN + r] = w.x; sE[(k+1)*DN + r] = w.y;
                sE[(k+2)*DN + r] = w.z; sE[(k+3)*DN + r] = w.w;
            }
        }
        if (tid < 128) en[tid] = g_enorm[c0 + tid];
        __syncthreads();
        if (tid < 128) {
            float s = 0.0f;
            for (int k = 0; k < 64; k++) {
                float zv = sZ[k*DN + tid];
                s = __fadd_rn(s, __fmul_rn(zv, zv));
            }
            zn[tid] = s;
        }
        __syncthreads();

        float acc[8][8];
#pragma unroll
        for (int i = 0; i < 8; i++)
#pragma unroll
            for (int j = 0; j < 8; j++) acc[i][j] = 0.0f;

#pragma unroll 8
        for (int kk = 0; kk < 64; kk++) {
            float a[8], b[8];
            *(float4*)(a)     = *(const float4*)(sZ + kk*DN + ty*8);
            *(float4*)(a + 4) = *(const float4*)(sZ + kk*DN + ty*8 + 4);
            *(float4*)(b)     = *(const float4*)(sE + kk*DN + tx*8);
            *(float4*)(b + 4) = *(const float4*)(sE + kk*DN + tx*8 + 4);
#pragma unroll
            for (int i = 0; i < 8; i++)
#pragma unroll
                for (int j = 0; j < 8; j++)
                    acc[i][j] = __fmaf_rn(a[i], b[j], acc[i][j]);
        }

        float enr[8];
#pragma unroll
        for (int j = 0; j < 8; j++) enr[j] = en[tx*8 + j];
#pragma unroll
        for (int i = 0; i < 8; i++) {
            float znr = zn[ty*8 + i];
            float bd = __int_as_float(0x7f800000); int bi = 0;
#pragma unroll
            for (int j = 0; j < 8; j++) {
                float S = __fadd_rn(znr, enr[j]);
                float d = __fsub_rn(S, __fmul_rn(2.0f, acc[i][j]));
                if (d < bd) { bd = d; bi = c0 + tx*8 + j; }
            }
#pragma unroll
            for (int o = 8; o > 0; o >>= 1) {
                float od = __shfl_xor_sync(0xffffffffu, bd, o, 32);
                int   oi = __shfl_xor_sync(0xffffffffu, bi, o, 32);
                if (od < bd || (od == bd && oi < bi)) { bd = od; bi = oi; }
            }
            if (tx == 0) {
                unsigned long long key =
                    ((unsigned long long)__float_as_uint(bd) << 32) | (unsigned)bi;
                atomicMin(&g_key[srows[ty*8 + i]], key);
            }
        }
        __syncthreads();
    }
}

// ======================= key -> idx, counts, out =======================
__global__ void k_extract(float* __restrict__ out) {
    int t = blockIdx.x * blockDim.x + threadIdx.x;
    if (t < BP) {
        int w = (int)(g_key[t] & 0xFFFFFFFFull);
        g_idx[t] = w;
        out[OFF_IDX + t] = (float)w;
        atomicAdd(&g_counts[w], 1);
    }
}

// ======================= per-block pinv solve (warp per block, fp32) ========
__global__ __launch_bounds__(256)
void k_solve(const float* __restrict__ emb, const float* __restrict__ x,
             float* __restrict__ out) {
    __shared__ float  sA[8][12][64];
    __shared__ float  sx[8][64];
    __shared__ float  sG[8][12][12];
    __shared__ float  sr[8][12];
    __shared__ float  sy[8][12];
    __shared__ float  sc[8][12];
    __shared__ int    sidx[8][12], sgrp[8][12], smult[8][12], scol[8][12];
    __shared__ int    su[8];
    __shared__ double wls[8];

    const int lane = threadIdx.x & 31;
    const int w    = threadIdx.x >> 5;
    const size_t b = (size_t)blockIdx.x * 8 + w;

    if (lane < 12) sidx[w][lane] = g_idx[b*12 + lane];
    __syncwarp();
    if (lane == 0) {
        int u = 0;
        for (int j = 0; j < 12; j++) {
            int v = sidx[w][j], q = -1;
            for (int t = 0; t < u; t++)
                if (sidx[w][scol[w][t]] == v) { q = t; break; }
            if (q < 0) { q = u; scol[w][u] = j; smult[w][u] = 0; u++; }
            sgrp[w][j] = q; smult[w][q]++;
        }
        su[w] = u;
    }
    __syncwarp();

    {
        double ls = 0.0;
        const float* zr = g_z + b * 768;
        for (int t = lane; t < 768; t += 32) {
            int j = t >> 6, i = t & 63;
            float a = emb[(size_t)sidx[w][j]*64 + i];
            float z = zr[t];
            double df = (double)a - (double)z;
            ls += df*df;
            sA[w][j][i] = __fadd_rn(z, __fsub_rn(a, z));
        }
#pragma unroll
        for (int o = 16; o; o >>= 1) ls += __shfl_down_sync(0xffffffffu, ls, o);
        if (lane == 0) wls[w] = ls;
    }
    for (int t = lane; t < 64; t += 32) sx[w][t] = x[b*64 + t];
    __syncwarp();

    const int u = su[w];
    const int npair = u*(u+1)/2;
    for (int t = lane; t < npair + u; t += 32) {
        if (t < npair) {
            int qa = 0, rem = t;
            while (rem >= u - qa) { rem -= (u - qa); qa++; }
            int qb = qa + rem;
            const float* ca = sA[w][scol[w][qa]];
            const float* cb = sA[w][scol[w][qb]];
            float s = 0.0f;
            for (int k = 0; k < 64; k++) s = __fmaf_rn(ca[k], cb[k], s);
            sG[w][qa][qb] = s; sG[w][qb][qa] = s;
        } else {
            int q2 = t - npair;
            const float* ca = sA[w][scol[w][q2]];
            float s = 0.0f;
            for (int k = 0; k < 64; k++) s = __fmaf_rn(ca[k], sx[w][k], s);
            sr[w][q2] = s;
        }
    }
    __syncwarp();

    // fp32 Cholesky (cond(G) small; coeff err ~1e-5 << 1e-3 budget)
    for (int p = 0; p < u; p++) {
        if (lane == 0) sG[w][p][p] = sqrtf(sG[w][p][p]);
        __syncwarp();
        float lpp = sG[w][p][p];
        if (lane > p && lane < u) sG[w][lane][p] /= lpp;
        __syncwarp();
        int m = u - p - 1;
        int tot = m*(m+1)/2;
        for (int t = lane; t < tot; t += 32) {
            int a = 0, rem = t;
            while (rem >= m - a) { rem -= (m - a); a++; }
            int j = p + 1 + a;
            int i = j + rem;
            sG[w][i][j] -= sG[w][i][p]*sG[w][j][p];
        }
        __syncwarp();
    }
    if (lane == 0) {
        for (int p = 0; p < u; p++) {
            float s = sr[w][p];
            for (int t = 0; t < p; t++) s -= sG[w][p][t]*sy[w][t];
            sy[w][p] = s / sG[w][p][p];
        }
        for (int p = u - 1; p >= 0; p--) {
            float s = sy[w][p];
            for (int t = p + 1; t < u; t++) s -= sG[w][t][p]*sy[w][t];
            sy[w][p] = s / sG[w][p][p];
        }
    }
    __syncwarp();
    if (lane < 12) {
        int q2 = sgrp[w][lane];
        float c = sy[w][q2] / (float)smult[w][q2];
        out[OFF_COEFF + b*12 + lane] = c;
        sc[w][lane] = c;
    }
    __syncwarp();
    for (int i = lane; i < 64; i += 32) {
        float s = 0.0f;
#pragma unroll
        for (int j = 0; j < 12; j++) s = __fmaf_rn(sA[w][j][i], sc[w][j], s);
        out[OFF_XHAT + b*64 + i] = s;
    }

    __syncthreads();
    if (threadIdx.x == 0) {
        double s = 0.0;
        for (int k = 0; k < 8; k++) s += wls[k];
        g_lossp[blockIdx.x] = s;
    }
}

// ======================= scalars: loss, perplexity =======================
__global__ void k_final(float* __restrict__ out) {
    __shared__ double red[256];
    const int tid = threadIdx.x;
    double s = 0.0;
    for (int k = tid; k < NE; k += 256) {
        double p = (double)g_counts[k] / (double)BP;
        s += p * log(p + 1e-10);
    }
    red[tid] = s; __syncthreads();
    for (int o = 128; o; o >>= 1) { if (tid < o) red[tid] += red[tid + o]; __syncthreads(); }
    double perp = exp(-red[0]);
    __syncthreads();

    double ls = 0.0;
    for (int k = tid; k < 2048; k += 256) ls += g_lossp[k];
    red[tid] = ls; __syncthreads();
    for (int o = 128; o; o >>= 1) { if (tid < o) red[tid] += red[tid + o]; __syncthreads(); }

    if (tid == 0) {
        out[OFF_PERP] = (float)perp;
        out[OFF_LOSS] = (float)(red[0] * 1.25 / ((double)BP * 64.0));
    }
}

// ======================= launch =======================
extern "C" void kernel_launch(void* const* d_in, const int* in_sizes, int n_in,
                              void* d_out, int out_size) {
    const float* x      = (const float*)d_in[0];
    const float* enc_w1 = (const float*)d_in[1];
    const float* enc_b1 = (const float*)d_in[2];
    const float* res_w  = (const float*)d_in[3];
    const float* res_b  = (const float*)d_in[4];
    const float* res_g  = (const float*)d_in[5];
    const float* res_bt = (const float*)d_in[6];
    const float* enc_w2 = (const float*)d_in[7];
    const float* enc_b2 = (const float*)d_in[8];
    const float* emb    = (const float*)d_in[9];
    float* out = (float*)d_out;

    cudaFuncSetAttribute(k_exact, cudaFuncAttributeMaxDynamicSharedMemorySize, EX_SMEM);

    k_init<<<(BP + 255)/256, 256>>>();
    k_enorm<<<NE/128, 128>>>(emb);

    // encoder: Linear(64->512) -> 2x shared ResBlock -> Linear(512->768)
    k_gemm<0><<<dim3(4, 128), 256>>>(x, enc_w1, enc_b1, DENC, INDIM);
    for (int r = 0; r < 2; r++) {
        k_gemm<1><<<dim3(4, 128), 256>>>(nullptr, res_w, res_b, DENC, DENC);
        k_ln<<<BSZ, 128>>>(res_g, res_bt);
    }
    k_gemm<2><<<dim3(6, 128), 256>>>(nullptr, enc_w2, enc_b2, ZDIM, DENC);

    k_tc<<<BP/128, 256>>>();
    k_flag<<<BP/256, 256>>>();
    k_items<<<1, 32>>>();
    k_exact<<<296, 256, EX_SMEM>>>(emb);
    k_extract<<<(BP + 255)/256, 256>>>(out);
    k_solve<<<BSZ/8, 256>>>(emb, x, out);
    k_final<<<1, 256>>>(out);
}

// round 16
// speedup vs baseline: 2.3741x; 1.1153x over previous
#include <cuda_runtime.h>
#include <math.h>
#include <stdint.h>

// -------- problem constants --------
#define BSZ   16384
#define INDIM 64
#define DENC  512
#define NE    2048
#define PBAS  12
#define BP    (BSZ*PBAS)          /* 196608 */
#define ZDIM  (INDIM*PBAS)        /* 768    */

// output layout: [loss, x_hat(B*64), perplexity, idx(BP), coeff(BP)]
#define OFF_LOSS  0
#define OFF_XHAT  1
#define OFF_PERP  (1 + BSZ*INDIM)
#define OFF_IDX   (OFF_PERP + 1)
#define OFF_COEFF (OFF_IDX + BP)

// -------- device scratch (static; referenced ONLY from device code) --------
__device__ __align__(16) float    g_h[BSZ*DENC];
__device__ __align__(16) float    g_t[BSZ*DENC];
__device__ __align__(16) float    g_z[BSZ*ZDIM];
__device__ __align__(16) float    g_enorm[NE];
__device__ __align__(16) unsigned g_ebf[NE*32];      // emb bf16x2 words, pair-permuted
__device__ __align__(16) float    g_cmin[(size_t)BP*16];
__device__ int      g_lcnt[16];
__device__ int      g_list[16*BP];
__device__ int      g_ibase[17];
__device__ int      g_wq;
__device__ unsigned g_me;
__device__ unsigned long long g_key[BP];
__device__ int      g_idx[BP];
__device__ int      g_counts[NE];
__device__ double   g_lossp[2048];

// packed dual-FMA: two independent rn fmas per instruction (bit-exact per lane)
__device__ __forceinline__ void fma2(unsigned long long& acc,
                                     unsigned long long a, unsigned long long b) {
    asm("fma.rn.f32x2 %0, %1, %2, %0;" : "+l"(acc) : "l"(a), "l"(b));
}
__device__ __forceinline__ unsigned long long dup2(float a) {
    unsigned long long d;
    asm("mov.b64 %0, {%1, %1};" : "=l"(d) : "f"(a));
    return d;
}
__device__ __forceinline__ float2 u2f(unsigned long long u) {
    float2 f;
    asm("mov.b64 {%0, %1}, %2;" : "=f"(f.x), "=f"(f.y) : "l"(u));
    return f;
}

// ======================= init =======================
__global__ void k_init() {
    int t = blockIdx.x * blockDim.x + threadIdx.x;
    if (t < NE) g_counts[t] = 0;
    if (t < BP) g_key[t] = 0xFFFFFFFFFFFFFFFFull;
    if (t < 16) g_lcnt[t] = 0;
    if (t == 16) g_me = 0u;
    if (t == 17) g_wq = 0;
}

// ======================= GEMM: C = A(MxK)@B(KxN) + bias (f32x2) ============
template<int MODE>
__global__ __launch_bounds__(256, 2)
void k_gemm(const float* __restrict__ Ain, const float* __restrict__ Bm,
            const float* __restrict__ bias, int N, int K) {
    const float* A = (MODE == 0) ? Ain : g_h;
    float*       C = (MODE == 0) ? g_h : ((MODE == 1) ? g_t : g_z);

    __shared__ __align__(16) float sA[32][132];
    __shared__ __align__(16) float sB[32][132];
    const int tid = threadIdx.x;
    const int tx = tid & 15, ty = tid >> 4;
    const int m0 = blockIdx.y * 128;
    const int n0 = blockIdx.x * 128;

    const int ra  = tid >> 3;
    const int kq  = (tid & 7) << 2;
    const int rb  = tid >> 5;
    const int cq  = (tid & 31) << 2;

    unsigned long long acc2[8][4];
#pragma unroll
    for (int i = 0; i < 8; i++)
#pragma unroll
        for (int j = 0; j < 4; j++) acc2[i][j] = 0ull;

    for (int kt = 0; kt < K; kt += 32) {
#pragma unroll
        for (int p = 0; p < 4; p++) {
            const float4 v = *(const float4*)(A + (size_t)(m0 + p*32 + ra) * K + kt + kq);
            int m = p*32 + ra;
            sA[kq+0][m] = v.x; sA[kq+1][m] = v.y;
            sA[kq+2][m] = v.z; sA[kq+3][m] = v.w;
        }
#pragma unroll
        for (int p = 0; p < 4; p++) {
            const float4 v = *(const float4*)(Bm + (size_t)(kt + p*8 + rb) * N + n0 + cq);
            *(float4*)(&sB[p*8 + rb][cq]) = v;
        }
        __syncthreads();
#pragma unroll 8
        for (int kk = 0; kk < 32; kk++) {
            float a[8];
            *(float4*)(a)     = *(const float4*)(&sA[kk][ty*8]);
            *(float4*)(a + 4) = *(const float4*)(&sA[kk][ty*8 + 4]);
            unsigned long long bp[4];
#pragma unroll
            for (int j = 0; j < 4; j++)
                bp[j] = *(const unsigned long long*)(&sB[kk][tx*8 + 2*j]);
#pragma unroll
            for (int i = 0; i < 8; i++) {
                unsigned long long ap = dup2(a[i]);
#pragma unroll
                for (int j = 0; j < 4; j++)
                    fma2(acc2[i][j], ap, bp[j]);
            }
        }
        __syncthreads();
    }
#pragma unroll
    for (int i = 0; i < 8; i++) {
        int m = m0 + ty*8 + i;
#pragma unroll
        for (int j = 0; j < 4; j++) {
            int n = n0 + tx*8 + 2*j;
            float2 v = u2f(acc2[i][j]);
            C[(size_t)m * N + n]     = __fadd_rn(v.x, bias[n]);
            C[(size_t)m * N + n + 1] = __fadd_rn(v.y, bias[n + 1]);
        }
    }
}

// ======================= h = h + relu(LN(t)*g + beta) =======================
__global__ void k_ln(const float* __restrict__ gw, const float* __restrict__ bw) {
    __shared__ float red[128];
    const int row = blockIdx.x, tid = threadIdx.x;
    const float* tr = g_t + (size_t)row * DENC;
    float*       hr = g_h + (size_t)row * DENC;

    float v[4], hv[4];
#pragma unroll
    for (int c = 0; c < 4; c++) { v[c] = tr[tid + c*128]; hv[c] = hr[tid + c*128]; }

    float s = (v[0] + v[1]) + (v[2] + v[3]);
    red[tid] = s; __syncthreads();
#pragma unroll
    for (int o = 64; o > 0; o >>= 1) { if (tid < o) red[tid] += red[tid + o]; __syncthreads(); }
    float mu = red[0] * (1.0f / 512.0f);
    __syncthreads();

    float s2 = 0.0f;
#pragma unroll
    for (int c = 0; c < 4; c++) { float d = v[c] - mu; s2 = __fadd_rn(s2, __fmul_rn(d, d)); }
    red[tid] = s2; __syncthreads();
#pragma unroll
    for (int o = 64; o > 0; o >>= 1) { if (tid < o) red[tid] += red[tid + o]; __syncthreads(); }
    float var  = red[0] * (1.0f / 512.0f);
    float rstd = 1.0f / sqrtf(__fadd_rn(var, 1e-5f));

#pragma unroll
    for (int c = 0; c < 4; c++) {
        int col = tid + c*128;
        float o = __fadd_rn(__fmul_rn(__fmul_rn(__fsub_rn(v[c], mu), rstd), gw[col]), bw[col]);
        hr[col] = __fadd_rn(hv[c], fmaxf(o, 0.0f));
    }
}

// ======================= codebook norms + permuted bf16 copy ================
// Word-permutation: word w -> (w>>3)*8 + (w&3)*2 + ((w&7)>>2), so the mma B
// fragment word pair (ks*8+t, ks*8+t+4) lands adjacent -> one LDS.64.
__global__ void k_enorm(const float* __restrict__ emb) {
    int k = blockIdx.x * blockDim.x + threadIdx.x;
    if (k < NE) {
        const float* e = emb + (size_t)k * 64;
        float s = 0.0f;
        for (int i = 0; i < 64; i++) s = __fadd_rn(s, __fmul_rn(e[i], e[i]));
        g_enorm[k] = s;
        atomicMax(&g_me, __float_as_uint(sqrtf(s)));
        unsigned short* eb = (unsigned short*)g_ebf;
        for (int i = 0; i < 64; i++) {
            unsigned short u;
            asm("cvt.rn.bf16.f32 %0, %1;" : "=h"(u) : "f"(e[i]));
            int w = i >> 1;
            int pw = ((w >> 3) << 3) + ((w & 3) << 1) + ((w & 7) >> 2);
            eb[(size_t)k*64 + pw*2 + (i & 1)] = u;
        }
    }
}

// ======================= bf16 tensor-core screening pass =======================
// 128 z-rows vs all 2048 codes; s = en - 2*dot_bf16; per-(row, 128-chunk) min.
// m16n8k16 bf16: half the instructions of tf32 k8 on the HMMA fallback path.
#define WZ 34
#define WE 36
__global__ __launch_bounds__(256, 4)
void k_tc() {
    __shared__ unsigned sZb[128*WZ];
    __shared__ unsigned sEb[128*WE];
    __shared__ float    sen[128];
    const int tid = threadIdx.x;
    const int lane = tid & 31, wid = tid >> 5;
    const int g = lane >> 2, t = lane & 3;
    const int m0 = blockIdx.x * 128;

    const int r = tid >> 1, hw = (tid & 1) * 16;   // row, half-offset in words

    {   // load + cvt z rows to bf16x2 words (natural k order)
        const float4* src = (const float4*)(g_z + (size_t)(m0 + r) * 64 + hw*2);
#pragma unroll
        for (int j = 0; j < 8; j++) {
            float4 v = src[j];
            unsigned w0, w1;
            asm("cvt.rn.bf16x2.f32 %0, %1, %2;" : "=r"(w0) : "f"(v.y), "f"(v.x));
            asm("cvt.rn.bf16x2.f32 %0, %1, %2;" : "=r"(w1) : "f"(v.w), "f"(v.z));
            sZb[r*WZ + hw + j*2]     = w0;
            sZb[r*WZ + hw + j*2 + 1] = w1;
        }
    }
    __syncthreads();

    // A fragments held in regs: 4 k16-blocks x 4 regs
    unsigned Af[4][4];
    const int rlo = wid*16 + g, rhi = rlo + 8;
#pragma unroll
    for (int ks = 0; ks < 4; ks++) {
        Af[ks][0] = sZb[rlo*WZ + ks*8 + t];
        Af[ks][1] = sZb[rhi*WZ + ks*8 + t];
        Af[ks][2] = sZb[rlo*WZ + ks*8 + t + 4];
        Af[ks][3] = sZb[rhi*WZ + ks*8 + t + 4];
    }

    for (int ch = 0; ch < 16; ch++) {
        __syncthreads();
        {   // copy permuted e chunk words + en
            const uint4* src = (const uint4*)(g_ebf + (size_t)(ch*128 + r)*32 + hw);
#pragma unroll
            for (int j = 0; j < 4; j++) {
                uint4 v = src[j];
                int w = hw + j*4;
                sEb[r*WE + w]   = v.x; sEb[r*WE + w+1] = v.y;
                sEb[r*WE + w+2] = v.z; sEb[r*WE + w+3] = v.w;
            }
            if (tid < 128) sen[tid] = g_enorm[ch*128 + tid];
        }
        __syncthreads();

        float mlo = __int_as_float(0x7f800000), mhi = mlo;
#pragma unroll
        for (int nt = 0; nt < 16; nt += 2) {
            float a0[4] = {0.f, 0.f, 0.f, 0.f};
            float a1[4] = {0.f, 0.f, 0.f, 0.f};
#pragma unroll
            for (int ks = 0; ks < 4; ks++) {
                uint2 b0 = *(const uint2*)(&sEb[(nt*8 + g)*WE + ks*8 + 2*t]);
                uint2 b1 = *(const uint2*)(&sEb[((nt+1)*8 + g)*WE + ks*8 + 2*t]);
                asm("mma.sync.aligned.m16n8k16.row.col.f32.bf16.bf16.f32 "
                    "{%0,%1,%2,%3}, {%4,%5,%6,%7}, {%8,%9}, {%0,%1,%2,%3};"
                    : "+f"(a0[0]), "+f"(a0[1]), "+f"(a0[2]), "+f"(a0[3])
                    : "r"(Af[ks][0]), "r"(Af[ks][1]), "r"(Af[ks][2]), "r"(Af[ks][3]),
                      "r"(b0.x), "r"(b0.y));
                asm("mma.sync.aligned.m16n8k16.row.col.f32.bf16.bf16.f32 "
                    "{%0,%1,%2,%3}, {%4,%5,%6,%7}, {%8,%9}, {%0,%1,%2,%3};"
                    : "+f"(a1[0]), "+f"(a1[1]), "+f"(a1[2]), "+f"(a1[3])
                    : "r"(Af[ks][0]), "r"(Af[ks][1]), "r"(Af[ks][2]), "r"(Af[ks][3]),
                      "r"(b1.x), "r"(b1.y));
            }
            float2 e0 = *(const float2*)&sen[nt*8 + 2*t];
            float2 e1 = *(const float2*)&sen[(nt+1)*8 + 2*t];
            float s;
            s = e0.x - 2.0f*a0[0]; if (s < mlo) mlo = s;
            s = e0.y - 2.0f*a0[1]; if (s < mlo) mlo = s;
            s = e0.x - 2.0f*a0[2]; if (s < mhi) mhi = s;
            s = e0.y - 2.0f*a0[3]; if (s < mhi) mhi = s;
            s = e1.x - 2.0f*a1[0]; if (s < mlo) mlo = s;
            s = e1.y - 2.0f*a1[1]; if (s < mlo) mlo = s;
            s = e1.x - 2.0f*a1[2]; if (s < mhi) mhi = s;
            s = e1.y - 2.0f*a1[3]; if (s < mhi) mhi = s;
        }
#pragma unroll
        for (int o = 1; o <= 2; o <<= 1) {
            float x = __shfl_xor_sync(0xffffffffu, mlo, o, 32); if (x < mlo) mlo = x;
            float y = __shfl_xor_sync(0xffffffffu, mhi, o, 32); if (y < mhi) mhi = y;
        }
        if (t == 0) {
            g_cmin[(size_t)(m0 + rlo)*16 + ch] = mlo;
            g_cmin[(size_t)(m0 + rhi)*16 + ch] = mhi;
        }
    }
}

// ======================= flag chunks within margin of row min ===============
// bf16 sound bound: |err| <= 2^-7 * ||z|| * max||e|| per side -> need 2B = 2^-6.
// Use 1/32 = 2^-5 (2x worst-case headroom, same ratio as proven tf32 config).
__global__ void k_flag() {
    int row = blockIdx.x * blockDim.x + threadIdx.x;
    if (row >= BP) return;
    const float4* zr = (const float4*)(g_z + (size_t)row * 64);
    float zn = 0.0f;
#pragma unroll
    for (int j = 0; j < 16; j++) {
        float4 v = zr[j];
        zn += v.x*v.x + v.y*v.y + v.z*v.z + v.w*v.w;
    }
    float c[16];
    float m = __int_as_float(0x7f800000);
#pragma unroll
    for (int ch = 0; ch < 16; ch++) {
        c[ch] = g_cmin[(size_t)row*16 + ch];
        if (c[ch] < m) m = c[ch];
    }
    float me = __uint_as_float(g_me);
    float thr = m + sqrtf(zn)*me*(1.0f/32.0f) + zn*2e-6f + 1e-7f;
#pragma unroll
    for (int ch = 0; ch < 16; ch++) {
        if (c[ch] <= thr) {
            int p = atomicAdd(&g_lcnt[ch], 1);
            g_list[ch*BP + p] = row;
        }
    }
}

// ======================= build work-item prefix =======================
__global__ void k_items() {
    if (threadIdx.x == 0) {
        int acc = 0;
        for (int ch = 0; ch < 16; ch++) {
            g_ibase[ch] = acc;
            acc += (g_lcnt[ch] + 127) >> 7;
        }
        g_ibase[16] = acc;
    }
}

// ======================= exact pass: persistent CTAs + work queue ===========
// Bit-exact reference sequence: d = fl(fl(zn+en) - 2*dot), k-ascending fmaf,
// lowest-index tie-break, u64 atomicMin merge.
#define DN 132
#define EX_SMEM ((64*DN*2 + 256)*4 + 128*4)
__global__ __launch_bounds__(256, 2)
void k_exact(const float* __restrict__ emb) {
    extern __shared__ __align__(16) float smd[];
    float* sZ = smd;
    float* sE = smd + 64*DN;
    float* zn = sE + 64*DN;
    float* en = zn + 128;
    int* srows = (int*)(en + 128);

    __shared__ int sbase[17];
    __shared__ int sitem;

    const int tid = threadIdx.x;
    const int tx = tid & 15, ty = tid >> 4;
    if (tid < 17) sbase[tid] = g_ibase[tid];

    for (;;) {
        if (tid == 0) sitem = atomicAdd(&g_wq, 1);
        __syncthreads();
        const int item = sitem;
        if (item >= sbase[16]) return;

        int ch = 0;
#pragma unroll
        for (int c = 1; c < 16; c++) if (sbase[c] <= item) ch = c;
        const int grp = item - sbase[ch];
        const int cnt = g_lcnt[ch];

        if (tid < 128) {
            int ii = grp*128 + tid;
            srows[tid] = g_list[ch*BP + (ii < cnt ? ii : grp*128)];
        }
        __syncthreads();

        const int c0 = ch * 128;
        const int r4 = tid >> 2, q = tid & 3;
#pragma unroll
        for (int p = 0; p < 2; p++) {
            int r = p*64 + r4;
            const float4* srcz = (const float4*)(g_z + (size_t)srows[r] * 64) + q*4;
            const float4* srce = (const float4*)(emb + (size_t)(c0 + r) * 64) + q*4;
#pragma unroll
            for (int s = 0; s < 4; s++) {
                float4 v = srcz[s];
                int k = q*16 + s*4;
                sZ[(k+0)*DN + r] = v.x; sZ[(k+1)*DN + r] = v.y;
                sZ[(k+2)*DN + r] = v.z; sZ[(k+3)*DN + r] = v.w;
                float4 w = srce[s];
                sE[(k+0)*DN + r] = w.x; sE[(k+1)*DN + r] = w.y;
                sE[(k+2)*DN + r] = w.z; sE[(k+3)*DN + r] = w.w;
            }
        }
        if (tid < 128) en[tid] = g_enorm[c0 + tid];
        __syncthreads();
        if (tid < 128) {
            float s = 0.0f;
            for (int k = 0; k < 64; k++) {
                float zv = sZ[k*DN + tid];
                s = __fadd_rn(s, __fmul_rn(zv, zv));
            }
            zn[tid] = s;
        }
        __syncthreads();

        float acc[8][8];
#pragma unroll
        for (int i = 0; i < 8; i++)
#pragma unroll
            for (int j = 0; j < 8; j++) acc[i][j] = 0.0f;

#pragma unroll 8
        for (int kk = 0; kk < 64; kk++) {
            float a[8], b[8];
            *(float4*)(a)     = *(const float4*)(sZ + kk*DN + ty*8);
            *(float4*)(a + 4) = *(const float4*)(sZ + kk*DN + ty*8 + 4);
            *(float4*)(b)     = *(const float4*)(sE + kk*DN + tx*8);
            *(float4*)(b + 4) = *(const float4*)(sE + kk*DN + tx*8 + 4);
#pragma unroll
            for (int i = 0; i < 8; i++)
#pragma unroll
                for (int j = 0; j < 8; j++)
                    acc[i][j] = __fmaf_rn(a[i], b[j], acc[i][j]);
        }

        float enr[8];
#pragma unroll
        for (int j = 0; j < 8; j++) enr[j] = en[tx*8 + j];
#pragma unroll
        for (int i = 0; i < 8; i++) {
            float znr = zn[ty*8 + i];
            float bd = __int_as_float(0x7f800000); int bi = 0;
#pragma unroll
            for (int j = 0; j < 8; j++) {
                float S = __fadd_rn(znr, enr[j]);
                float d = __fsub_rn(S, __fmul_rn(2.0f, acc[i][j]));
                if (d < bd) { bd = d; bi = c0 + tx*8 + j; }
            }
#pragma unroll
            for (int o = 8; o > 0; o >>= 1) {
                float od = __shfl_xor_sync(0xffffffffu, bd, o, 32);
                int   oi = __shfl_xor_sync(0xffffffffu, bi, o, 32);
                if (od < bd || (od == bd && oi < bi)) { bd = od; bi = oi; }
            }
            if (tx == 0) {
                unsigned long long key =
                    ((unsigned long long)__float_as_uint(bd) << 32) | (unsigned)bi;
                atomicMin(&g_key[srows[ty*8 + i]], key);
            }
        }
        __syncthreads();
    }
}

// ======================= key -> idx, counts, out =======================
__global__ void k_extract(float* __restrict__ out) {
    int t = blockIdx.x * blockDim.x + threadIdx.x;
    if (t < BP) {
        int w = (int)(g_key[t] & 0xFFFFFFFFull);
        g_idx[t] = w;
        out[OFF_IDX + t] = (float)w;
        atomicAdd(&g_counts[w], 1);
    }
}

// ======================= per-block pinv solve (warp per block, fp32) ========
__global__ __launch_bounds__(256)
void k_solve(const float* __restrict__ emb, const float* __restrict__ x,
             float* __restrict__ out) {
    __shared__ float  sA[8][12][64];
    __shared__ float  sx[8][64];
    __shared__ float  sG[8][12][12];
    __shared__ float  sr[8][12];
    __shared__ float  sy[8][12];
    __shared__ float  sc[8][12];
    __shared__ int    sidx[8][12], sgrp[8][12], smult[8][12], scol[8][12];
    __shared__ int    su[8];
    __shared__ double wls[8];

    const int lane = threadIdx.x & 31;
    const int w    = threadIdx.x >> 5;
    const size_t b = (size_t)blockIdx.x * 8 + w;

    if (lane < 12) sidx[w][lane] = g_idx[b*12 + lane];
    __syncwarp();
    if (lane == 0) {
        int u = 0;
        for (int j = 0; j < 12; j++) {
            int v = sidx[w][j], q = -1;
            for (int t = 0; t < u; t++)
                if (sidx[w][scol[w][t]] == v) { q = t; break; }
            if (q < 0) { q = u; scol[w][u] = j; smult[w][u] = 0; u++; }
            sgrp[w][j] = q; smult[w][q]++;
        }
        su[w] = u;
    }
    __syncwarp();

    {
        double ls = 0.0;
        const float* zr = g_z + b * 768;
        for (int t = lane; t < 768; t += 32) {
            int j = t >> 6, i = t & 63;
            float a = emb[(size_t)sidx[w][j]*64 + i];
            float z = zr[t];
            double df = (double)a - (double)z;
            ls += df*df;
            sA[w][j][i] = __fadd_rn(z, __fsub_rn(a, z));
        }
#pragma unroll
        for (int o = 16; o; o >>= 1) ls += __shfl_down_sync(0xffffffffu, ls, o);
        if (lane == 0) wls[w] = ls;
    }
    for (int t = lane; t < 64; t += 32) sx[w][t] = x[b*64 + t];
    __syncwarp();

    const int u = su[w];
    const int npair = u*(u+1)/2;
    for (int t = lane; t < npair + u; t += 32) {
        if (t < npair) {
            int qa = 0, rem = t;
            while (rem >= u - qa) { rem -= (u - qa); qa++; }
            int qb = qa + rem;
            const float* ca = sA[w][scol[w][qa]];
            const float* cb = sA[w][scol[w][qb]];
            float s = 0.0f;
            for (int k = 0; k < 64; k++) s = __fmaf_rn(ca[k], cb[k], s);
            sG[w][qa][qb] = s; sG[w][qb][qa] = s;
        } else {
            int q2 = t - npair;
            const float* ca = sA[w][scol[w][q2]];
            float s = 0.0f;
            for (int k = 0; k < 64; k++) s = __fmaf_rn(ca[k], sx[w][k], s);
            sr[w][q2] = s;
        }
    }
    __syncwarp();

    for (int p = 0; p < u; p++) {
        if (lane == 0) sG[w][p][p] = sqrtf(sG[w][p][p]);
        __syncwarp();
        float lpp = sG[w][p][p];
        if (lane > p && lane < u) sG[w][lane][p] /= lpp;
        __syncwarp();
        int m = u - p - 1;
        int tot = m*(m+1)/2;
        for (int t = lane; t < tot; t += 32) {
            int a = 0, rem = t;
            while (rem >= m - a) { rem -= (m - a); a++; }
            int j = p + 1 + a;
            int i = j + rem;
            sG[w][i][j] -= sG[w][i][p]*sG[w][j][p];
        }
        __syncwarp();
    }
    if (lane == 0) {
        for (int p = 0; p < u; p++) {
            float s = sr[w][p];
            for (int t = 0; t < p; t++) s -= sG[w][p][t]*sy[w][t];
            sy[w][p] = s / sG[w][p][p];
        }
        for (int p = u - 1; p >= 0; p--) {
            float s = sy[w][p];
            for (int t = p + 1; t < u; t++) s -= sG[w][t][p]*sy[w][t];
            sy[w][p] = s / sG[w][p][p];
        }
    }
    __syncwarp();
    if (lane < 12) {
        int q2 = sgrp[w][lane];
        float c = sy[w][q2] / (float)smult[w][q2];
        out[OFF_COEFF + b*12 + lane] = c;
        sc[w][lane] = c;
    }
    __syncwarp();
    for (int i = lane; i < 64; i += 32) {
        float s = 0.0f;
#pragma unroll
        for (int j = 0; j < 12; j++) s = __fmaf_rn(sA[w][j][i], sc[w][j], s);
        out[OFF_XHAT + b*64 + i] = s;
    }

    __syncthreads();
    if (threadIdx.x == 0) {
        double s = 0.0;
        for (int k = 0; k < 8; k++) s += wls[k];
        g_lossp[blockIdx.x] = s;
    }
}

// ======================= scalars: loss, perplexity =======================
__global__ void k_final(float* __restrict__ out) {
    __shared__ double red[256];
    const int tid = threadIdx.x;
    double s = 0.0;
    for (int k = tid; k < NE; k += 256) {
        double p = (double)g_counts[k] / (double)BP;
        s += p * log(p + 1e-10);
    }
    red[tid] = s; __syncthreads();
    for (int o = 128; o; o >>= 1) { if (tid < o) red[tid] += red[tid + o]; __syncthreads(); }
    double perp = exp(-red[0]);
    __syncthreads();

    double ls = 0.0;
    for (int k = tid; k < 2048; k += 256) ls += g_lossp[k];
    red[tid] = ls; __syncthreads();
    for (int o = 128; o; o >>= 1) { if (tid < o) red[tid] += red[tid + o]; __syncthreads(); }

    if (tid == 0) {
        out[OFF_PERP] = (float)perp;
        out[OFF_LOSS] = (float)(red[0] * 1.25 / ((double)BP * 64.0));
    }
}

// ======================= launch =======================
extern "C" void kernel_launch(void* const* d_in, const int* in_sizes, int n_in,
                              void* d_out, int out_size) {
    const float* x      = (const float*)d_in[0];
    const float* enc_w1 = (const float*)d_in[1];
    const float* enc_b1 = (const float*)d_in[2];
    const float* res_w  = (const float*)d_in[3];
    const float* res_b  = (const float*)d_in[4];
    const float* res_g  = (const float*)d_in[5];
    const float* res_bt = (const float*)d_in[6];
    const float* enc_w2 = (const float*)d_in[7];
    const float* enc_b2 = (const float*)d_in[8];
    const float* emb    = (const float*)d_in[9];
    float* out = (float*)d_out;

    cudaFuncSetAttribute(k_exact, cudaFuncAttributeMaxDynamicSharedMemorySize, EX_SMEM);

    k_init<<<(BP + 255)/256, 256>>>();
    k_enorm<<<NE/128, 128>>>(emb);

    // encoder: Linear(64->512) -> 2x shared ResBlock -> Linear(512->768)
    k_gemm<0><<<dim3(4, 128), 256>>>(x, enc_w1, enc_b1, DENC, INDIM);
    for (int r = 0; r < 2; r++) {
        k_gemm<1><<<dim3(4, 128), 256>>>(nullptr, res_w, res_b, DENC, DENC);
        k_ln<<<BSZ, 128>>>(res_g, res_bt);
    }
    k_gemm<2><<<dim3(6, 128), 256>>>(nullptr, enc_w2, enc_b2, ZDIM, DENC);

    k_tc<<<BP/128, 256>>>();
    k_flag<<<BP/256, 256>>>();
    k_items<<<1, 32>>>();
    k_exact<<<296, 256, EX_SMEM>>>(emb);
    k_extract<<<(BP + 255)/256, 256>>>(out);
    k_solve<<<BSZ/8, 256>>>(emb, x, out);
    k_final<<<1, 256>>>(out);
}

// round 17
// speedup vs baseline: 2.4073x; 1.0140x over previous
#include <cuda_runtime.h>
#include <math.h>
#include <stdint.h>

// -------- problem constants --------
#define BSZ   16384
#define INDIM 64
#define DENC  512
#define NE    2048
#define PBAS  12
#define BP    (BSZ*PBAS)          /* 196608 */
#define ZDIM  (INDIM*PBAS)        /* 768    */

// output layout: [loss, x_hat(B*64), perplexity, idx(BP), coeff(BP)]
#define OFF_LOSS  0
#define OFF_XHAT  1
#define OFF_PERP  (1 + BSZ*INDIM)
#define OFF_IDX   (OFF_PERP + 1)
#define OFF_COEFF (OFF_IDX + BP)

// -------- device scratch (static; referenced ONLY from device code) --------
__device__ __align__(16) float    g_h[BSZ*DENC];
__device__ __align__(16) float    g_t[BSZ*DENC];
__device__ __align__(16) float    g_z[BSZ*ZDIM];
__device__ __align__(16) float    g_enorm[NE];
__device__ __align__(16) unsigned g_ebf[NE*32];      // emb bf16x2 words, pair-permuted
__device__ __align__(16) float    g_cmin[(size_t)BP*16];
__device__ int      g_lcnt[16];
__device__ int      g_list[16*BP];
__device__ int      g_ibase[17];
__device__ int      g_wq;
__device__ unsigned g_me;
__device__ unsigned long long g_key[BP];
__device__ int      g_counts[NE];
__device__ double   g_lossp[2048];

// packed dual-FMA: two independent rn fmas per instruction (bit-exact per lane)
__device__ __forceinline__ void fma2(unsigned long long& acc,
                                     unsigned long long a, unsigned long long b) {
    asm("fma.rn.f32x2 %0, %1, %2, %0;" : "+l"(acc) : "l"(a), "l"(b));
}
__device__ __forceinline__ unsigned long long dup2(float a) {
    unsigned long long d;
    asm("mov.b64 %0, {%1, %1};" : "=l"(d) : "f"(a));
    return d;
}
__device__ __forceinline__ float2 u2f(unsigned long long u) {
    float2 f;
    asm("mov.b64 {%0, %1}, %2;" : "=f"(f.x), "=f"(f.y) : "l"(u));
    return f;
}

// ======================= setup: init state + codebook norms/bf16 ============
// Word-permutation: word w -> (w>>3)*8 + (w&3)*2 + ((w&7)>>2), so the mma B
// fragment word pair (ks*8+t, ks*8+t+4) lands adjacent -> one LDS.64.
__global__ void k_setup(const float* __restrict__ emb) {
    int t = blockIdx.x * blockDim.x + threadIdx.x;
    if (t < BP) g_key[t] = 0xFFFFFFFFFFFFFFFFull;
    if (t < NE) {
        g_counts[t] = 0;
        const float* e = emb + (size_t)t * 64;
        float s = 0.0f;
        for (int i = 0; i < 64; i++) s = __fadd_rn(s, __fmul_rn(e[i], e[i]));
        g_enorm[t] = s;
        atomicMax(&g_me, __float_as_uint(sqrtf(s)));
        unsigned short* eb = (unsigned short*)g_ebf;
        for (int i = 0; i < 64; i++) {
            unsigned short u;
            asm("cvt.rn.bf16.f32 %0, %1;" : "=h"(u) : "f"(e[i]));
            int w = i >> 1;
            int pw = ((w >> 3) << 3) + ((w & 3) << 1) + ((w & 7) >> 2);
            eb[(size_t)t*64 + pw*2 + (i & 1)] = u;
        }
    }
    if (t < 16) g_lcnt[t] = 0;
    if (t == 17) g_wq = 0;
}

// ======================= GEMM: C = A(MxK)@B(KxN) + bias (f32x2) ============
template<int MODE>
__global__ __launch_bounds__(256, 2)
void k_gemm(const float* __restrict__ Ain, const float* __restrict__ Bm,
            const float* __restrict__ bias, int N, int K) {
    const float* A = (MODE == 0) ? Ain : g_h;
    float*       C = (MODE == 0) ? g_h : ((MODE == 1) ? g_t : g_z);

    __shared__ __align__(16) float sA[32][132];
    __shared__ __align__(16) float sB[32][132];
    const int tid = threadIdx.x;
    const int tx = tid & 15, ty = tid >> 4;
    const int m0 = blockIdx.y * 128;
    const int n0 = blockIdx.x * 128;

    const int ra  = tid >> 3;
    const int kq  = (tid & 7) << 2;
    const int rb  = tid >> 5;
    const int cq  = (tid & 31) << 2;

    unsigned long long acc2[8][4];
#pragma unroll
    for (int i = 0; i < 8; i++)
#pragma unroll
        for (int j = 0; j < 4; j++) acc2[i][j] = 0ull;

    for (int kt = 0; kt < K; kt += 32) {
#pragma unroll
        for (int p = 0; p < 4; p++) {
            const float4 v = *(const float4*)(A + (size_t)(m0 + p*32 + ra) * K + kt + kq);
            int m = p*32 + ra;
            sA[kq+0][m] = v.x; sA[kq+1][m] = v.y;
            sA[kq+2][m] = v.z; sA[kq+3][m] = v.w;
        }
#pragma unroll
        for (int p = 0; p < 4; p++) {
            const float4 v = *(const float4*)(Bm + (size_t)(kt + p*8 + rb) * N + n0 + cq);
            *(float4*)(&sB[p*8 + rb][cq]) = v;
        }
        __syncthreads();
#pragma unroll 8
        for (int kk = 0; kk < 32; kk++) {
            float a[8];
            *(float4*)(a)     = *(const float4*)(&sA[kk][ty*8]);
            *(float4*)(a + 4) = *(const float4*)(&sA[kk][ty*8 + 4]);
            unsigned long long bp[4];
#pragma unroll
            for (int j = 0; j < 4; j++)
                bp[j] = *(const unsigned long long*)(&sB[kk][tx*8 + 2*j]);
#pragma unroll
            for (int i = 0; i < 8; i++) {
                unsigned long long ap = dup2(a[i]);
#pragma unroll
                for (int j = 0; j < 4; j++)
                    fma2(acc2[i][j], ap, bp[j]);
            }
        }
        __syncthreads();
    }
#pragma unroll
    for (int i = 0; i < 8; i++) {
        int m = m0 + ty*8 + i;
#pragma unroll
        for (int j = 0; j < 4; j++) {
            int n = n0 + tx*8 + 2*j;
            float2 v = u2f(acc2[i][j]);
            C[(size_t)m * N + n]     = __fadd_rn(v.x, bias[n]);
            C[(size_t)m * N + n + 1] = __fadd_rn(v.y, bias[n + 1]);
        }
    }
}

// ======================= h = h + relu(LN(t)*g + beta) =======================
__global__ void k_ln(const float* __restrict__ gw, const float* __restrict__ bw) {
    __shared__ float red[128];
    const int row = blockIdx.x, tid = threadIdx.x;
    const float* tr = g_t + (size_t)row * DENC;
    float*       hr = g_h + (size_t)row * DENC;

    float v[4], hv[4];
#pragma unroll
    for (int c = 0; c < 4; c++) { v[c] = tr[tid + c*128]; hv[c] = hr[tid + c*128]; }

    float s = (v[0] + v[1]) + (v[2] + v[3]);
    red[tid] = s; __syncthreads();
#pragma unroll
    for (int o = 64; o > 0; o >>= 1) { if (tid < o) red[tid] += red[tid + o]; __syncthreads(); }
    float mu = red[0] * (1.0f / 512.0f);
    __syncthreads();

    float s2 = 0.0f;
#pragma unroll
    for (int c = 0; c < 4; c++) { float d = v[c] - mu; s2 = __fadd_rn(s2, __fmul_rn(d, d)); }
    red[tid] = s2; __syncthreads();
#pragma unroll
    for (int o = 64; o > 0; o >>= 1) { if (tid < o) red[tid] += red[tid + o]; __syncthreads(); }
    float var  = red[0] * (1.0f / 512.0f);
    float rstd = 1.0f / sqrtf(__fadd_rn(var, 1e-5f));

#pragma unroll
    for (int c = 0; c < 4; c++) {
        int col = tid + c*128;
        float o = __fadd_rn(__fmul_rn(__fmul_rn(__fsub_rn(v[c], mu), rstd), gw[col]), bw[col]);
        hr[col] = __fadd_rn(hv[c], fmaxf(o, 0.0f));
    }
}

// ======================= bf16 tensor-core screening pass =======================
// 128 z-rows vs all 2048 codes; s = en - 2*dot_bf16; per-(row, 128-chunk) min.
// Double-buffered E chunks: next chunk held in regs during mma, 1 barrier/chunk.
#define WZ 34
#define WE 36
__global__ __launch_bounds__(256, 4)
void k_tc() {
    __shared__ unsigned sZb[128*WZ];
    __shared__ unsigned sEb[2][128*WE];
    __shared__ float    sen[2][128];
    const int tid = threadIdx.x;
    const int lane = tid & 31, wid = tid >> 5;
    const int g = lane >> 2, t = lane & 3;
    const int m0 = blockIdx.x * 128;

    const int r = tid >> 1, hw = (tid & 1) * 16;   // row, half-offset in words

    {   // load + cvt z rows to bf16x2 words (natural k order)
        const float4* src = (const float4*)(g_z + (size_t)(m0 + r) * 64 + hw*2);
#pragma unroll
        for (int j = 0; j < 8; j++) {
            float4 v = src[j];
            unsigned w0, w1;
            asm("cvt.rn.bf16x2.f32 %0, %1, %2;" : "=r"(w0) : "f"(v.y), "f"(v.x));
            asm("cvt.rn.bf16x2.f32 %0, %1, %2;" : "=r"(w1) : "f"(v.w), "f"(v.z));
            sZb[r*WZ + hw + j*2]     = w0;
            sZb[r*WZ + hw + j*2 + 1] = w1;
        }
    }
    {   // preload chunk 0 into buf 0
        const uint4* src = (const uint4*)(g_ebf + (size_t)(0*128 + r)*32 + hw);
#pragma unroll
        for (int j = 0; j < 4; j++) {
            uint4 v = src[j];
            int w = hw + j*4;
            sEb[0][r*WE + w]   = v.x; sEb[0][r*WE + w+1] = v.y;
            sEb[0][r*WE + w+2] = v.z; sEb[0][r*WE + w+3] = v.w;
        }
        if (tid < 128) sen[0][tid] = g_enorm[tid];
    }
    __syncthreads();

    // A fragments held in regs: 4 k16-blocks x 4 regs
    unsigned Af[4][4];
    const int rlo = wid*16 + g, rhi = rlo + 8;
#pragma unroll
    for (int ks = 0; ks < 4; ks++) {
        Af[ks][0] = sZb[rlo*WZ + ks*8 + t];
        Af[ks][1] = sZb[rhi*WZ + ks*8 + t];
        Af[ks][2] = sZb[rlo*WZ + ks*8 + t + 4];
        Af[ks][3] = sZb[rhi*WZ + ks*8 + t + 4];
    }

    for (int ch = 0; ch < 16; ch++) {
        const int cur = ch & 1;
        // prefetch next chunk into regs (LDG latency overlaps the mma below)
        uint4 vn[4]; float enn = 0.0f;
        if (ch < 15) {
            const uint4* src = (const uint4*)(g_ebf + (size_t)((ch+1)*128 + r)*32 + hw);
#pragma unroll
            for (int j = 0; j < 4; j++) vn[j] = src[j];
            if (tid < 128) enn = g_enorm[(ch+1)*128 + tid];
        }

        float mlo = __int_as_float(0x7f800000), mhi = mlo;
#pragma unroll
        for (int nt = 0; nt < 16; nt += 2) {
            float a0[4] = {0.f, 0.f, 0.f, 0.f};
            float a1[4] = {0.f, 0.f, 0.f, 0.f};
#pragma unroll
            for (int ks = 0; ks < 4; ks++) {
                uint2 b0 = *(const uint2*)(&sEb[cur][(nt*8 + g)*WE + ks*8 + 2*t]);
                uint2 b1 = *(const uint2*)(&sEb[cur][((nt+1)*8 + g)*WE + ks*8 + 2*t]);
                asm("mma.sync.aligned.m16n8k16.row.col.f32.bf16.bf16.f32 "
                    "{%0,%1,%2,%3}, {%4,%5,%6,%7}, {%8,%9}, {%0,%1,%2,%3};"
                    : "+f"(a0[0]), "+f"(a0[1]), "+f"(a0[2]), "+f"(a0[3])
                    : "r"(Af[ks][0]), "r"(Af[ks][1]), "r"(Af[ks][2]), "r"(Af[ks][3]),
                      "r"(b0.x), "r"(b0.y));
                asm("mma.sync.aligned.m16n8k16.row.col.f32.bf16.bf16.f32 "
                    "{%0,%1,%2,%3}, {%4,%5,%6,%7}, {%8,%9}, {%0,%1,%2,%3};"
                    : "+f"(a1[0]), "+f"(a1[1]), "+f"(a1[2]), "+f"(a1[3])
                    : "r"(Af[ks][0]), "r"(Af[ks][1]), "r"(Af[ks][2]), "r"(Af[ks][3]),
                      "r"(b1.x), "r"(b1.y));
            }
            float2 e0 = *(const float2*)&sen[cur][nt*8 + 2*t];
            float2 e1 = *(const float2*)&sen[cur][(nt+1)*8 + 2*t];
            float s;
            s = e0.x - 2.0f*a0[0]; if (s < mlo) mlo = s;
            s = e0.y - 2.0f*a0[1]; if (s < mlo) mlo = s;
            s = e0.x - 2.0f*a0[2]; if (s < mhi) mhi = s;
            s = e0.y - 2.0f*a0[3]; if (s < mhi) mhi = s;
            s = e1.x - 2.0f*a1[0]; if (s < mlo) mlo = s;
            s = e1.y - 2.0f*a1[1]; if (s < mlo) mlo = s;
            s = e1.x - 2.0f*a1[2]; if (s < mhi) mhi = s;
            s = e1.y - 2.0f*a1[3]; if (s < mhi) mhi = s;
        }
#pragma unroll
        for (int o = 1; o <= 2; o <<= 1) {
            float x = __shfl_xor_sync(0xffffffffu, mlo, o, 32); if (x < mlo) mlo = x;
            float y = __shfl_xor_sync(0xffffffffu, mhi, o, 32); if (y < mhi) mhi = y;
        }
        if (t == 0) {
            g_cmin[(size_t)(m0 + rlo)*16 + ch] = mlo;
            g_cmin[(size_t)(m0 + rhi)*16 + ch] = mhi;
        }

        // store prefetched chunk into the other buffer
        if (ch < 15) {
#pragma unroll
            for (int j = 0; j < 4; j++) {
                int w = hw + j*4;
                sEb[cur^1][r*WE + w]   = vn[j].x; sEb[cur^1][r*WE + w+1] = vn[j].y;
                sEb[cur^1][r*WE + w+2] = vn[j].z; sEb[cur^1][r*WE + w+3] = vn[j].w;
            }
            if (tid < 128) sen[cur^1][tid] = enn;
            __syncthreads();
        }
    }
}

// ======================= flag chunks within margin of row min ===============
// bf16 sound bound: |err| <= 2^-7 * ||z|| * max||e|| per side -> need 2B = 2^-6.
// Use 1/32 = 2^-5 (2x worst-case headroom, validated zero-flip in R16).
__global__ void k_flag() {
    int row = blockIdx.x * blockDim.x + threadIdx.x;
    if (row >= BP) return;
    const float4* zr = (const float4*)(g_z + (size_t)row * 64);
    float zn = 0.0f;
#pragma unroll
    for (int j = 0; j < 16; j++) {
        float4 v = zr[j];
        zn += v.x*v.x + v.y*v.y + v.z*v.z + v.w*v.w;
    }
    float c[16];
    const float4* cm = (const float4*)(g_cmin + (size_t)row*16);
#pragma unroll
    for (int j = 0; j < 4; j++) {
        float4 v = cm[j];
        c[j*4]   = v.x; c[j*4+1] = v.y; c[j*4+2] = v.z; c[j*4+3] = v.w;
    }
    float m = __int_as_float(0x7f800000);
#pragma unroll
    for (int ch = 0; ch < 16; ch++) if (c[ch] < m) m = c[ch];
    float me = __uint_as_float(g_me);
    float thr = m + sqrtf(zn)*me*(1.0f/32.0f) + zn*2e-6f + 1e-7f;
#pragma unroll
    for (int ch = 0; ch < 16; ch++) {
        if (c[ch] <= thr) {
            int p = atomicAdd(&g_lcnt[ch], 1);
            g_list[ch*BP + p] = row;
        }
    }
}

// ======================= build work-item prefix =======================
__global__ void k_items() {
    if (threadIdx.x == 0) {
        int acc = 0;
        for (int ch = 0; ch < 16; ch++) {
            g_ibase[ch] = acc;
            acc += (g_lcnt[ch] + 127) >> 7;
        }
        g_ibase[16] = acc;
    }
}

// ======================= exact pass: persistent CTAs + work queue ===========
// Bit-exact reference sequence: d = fl(fl(zn+en) - 2*dot), k-ascending fmaf,
// lowest-index tie-break, u64 atomicMin merge.
#define DN 132
#define EX_SMEM ((64*DN*2 + 256)*4 + 128*4)
__global__ __launch_bounds__(256, 2)
void k_exact(const float* __restrict__ emb) {
    extern __shared__ __align__(16) float smd[];
    float* sZ = smd;
    float* sE = smd + 64*DN;
    float* zn = sE + 64*DN;
    float* en = zn + 128;
    int* srows = (int*)(en + 128);

    __shared__ int sbase[17];
    __shared__ int sitem;

    const int tid = threadIdx.x;
    const int tx = tid & 15, ty = tid >> 4;
    if (tid < 17) sbase[tid] = g_ibase[tid];

    for (;;) {
        if (tid == 0) sitem = atomicAdd(&g_wq, 1);
        __syncthreads();
        const int item = sitem;
        if (item >= sbase[16]) return;

        int ch = 0;
#pragma unroll
        for (int c = 1; c < 16; c++) if (sbase[c] <= item) ch = c;
        const int grp = item - sbase[ch];
        const int cnt = g_lcnt[ch];

        if (tid < 128) {
            int ii = grp*128 + tid;
            srows[tid] = g_list[ch*BP + (ii < cnt ? ii : grp*128)];
        }
        __syncthreads();

        const int c0 = ch * 128;
        const int r4 = tid >> 2, q = tid & 3;
#pragma unroll
        for (int p = 0; p < 2; p++) {
            int r = p*64 + r4;
            const float4* srcz = (const float4*)(g_z + (size_t)srows[r] * 64) + q*4;
            const float4* srce = (const float4*)(emb + (size_t)(c0 + r) * 64) + q*4;
#pragma unroll
            for (int s = 0; s < 4; s++) {
                float4 v = srcz[s];
                int k = q*16 + s*4;
                sZ[(k+0)*DN + r] = v.x; sZ[(k+1)*DN + r] = v.y;
                sZ[(k+2)*DN + r] = v.z; sZ[(k+3)*DN + r] = v.w;
                float4 w = srce[s];
                sE[(k+0)*DN + r] = w.x; sE[(k+1)*DN + r] = w.y;
                sE[(k+2)*DN + r] = w.z; sE[(k+3)*DN + r] = w.w;
            }
        }
        if (tid < 128) en[tid] = g_enorm[c0 + tid];
        __syncthreads();
        if (tid < 128) {
            float s = 0.0f;
            for (int k = 0; k < 64; k++) {
                float zv = sZ[k*DN + tid];
                s = __fadd_rn(s, __fmul_rn(zv, zv));
            }
            zn[tid] = s;
        }
        __syncthreads();

        float acc[8][8];
#pragma unroll
        for (int i = 0; i < 8; i++)
#pragma unroll
            for (int j = 0; j < 8; j++) acc[i][j] = 0.0f;

#pragma unroll 8
        for (int kk = 0; kk < 64; kk++) {
            float a[8], b[8];
            *(float4*)(a)     = *(const float4*)(sZ + kk*DN + ty*8);
            *(float4*)(a + 4) = *(const float4*)(sZ + kk*DN + ty*8 + 4);
            *(float4*)(b)     = *(const float4*)(sE + kk*DN + tx*8);
            *(float4*)(b + 4) = *(const float4*)(sE + kk*DN + tx*8 + 4);
#pragma unroll
            for (int i = 0; i < 8; i++)
#pragma unroll
                for (int j = 0; j < 8; j++)
                    acc[i][j] = __fmaf_rn(a[i], b[j], acc[i][j]);
        }

        float enr[8];
#pragma unroll
        for (int j = 0; j < 8; j++) enr[j] = en[tx*8 + j];
#pragma unroll
        for (int i = 0; i < 8; i++) {
            float znr = zn[ty*8 + i];
            float bd = __int_as_float(0x7f800000); int bi = 0;
#pragma unroll
            for (int j = 0; j < 8; j++) {
                float S = __fadd_rn(znr, enr[j]);
                float d = __fsub_rn(S, __fmul_rn(2.0f, acc[i][j]));
                if (d < bd) { bd = d; bi = c0 + tx*8 + j; }
            }
#pragma unroll
            for (int o = 8; o > 0; o >>= 1) {
                float od = __shfl_xor_sync(0xffffffffu, bd, o, 32);
                int   oi = __shfl_xor_sync(0xffffffffu, bi, o, 32);
                if (od < bd || (od == bd && oi < bi)) { bd = od; bi = oi; }
            }
            if (tx == 0) {
                unsigned long long key =
                    ((unsigned long long)__float_as_uint(bd) << 32) | (unsigned)bi;
                atomicMin(&g_key[srows[ty*8 + i]], key);
            }
        }
        __syncthreads();
    }
}

// ======================= per-block pinv solve + idx/counts emit =============
// fp32 normal equations; warp-parallel dedup (match.any) and triangular solves.
__global__ __launch_bounds__(256)
void k_solve(const float* __restrict__ emb, const float* __restrict__ x,
             float* __restrict__ out) {
    __shared__ float  sA[8][12][64];
    __shared__ float  sx[8][64];
    __shared__ float  sG[8][12][12];
    __shared__ float  sr[8][12];
    __shared__ float  sy[8][12];
    __shared__ float  sc[8][12];
    __shared__ int    sidx[8][12], sgrp[8][12], smult[8][12], scol[8][12];
    __shared__ int    su[8];
    __shared__ double wls[8];

    const int lane = threadIdx.x & 31;
    const int w    = threadIdx.x >> 5;
    const size_t b = (size_t)blockIdx.x * 8 + w;

    // read keys -> idx; emit out idx + counts (absorbed from k_extract)
    int myidx;
    if (lane < 12) {
        unsigned long long key = g_key[b*12 + lane];
        myidx = (int)(key & 0xFFFFFFFFull);
        sidx[w][lane] = myidx;
        out[OFF_IDX + b*12 + lane] = (float)myidx;
        atomicAdd(&g_counts[myidx], 1);
    } else {
        myidx = (int)(0x80000000u | lane);   // unique sentinel per lane
    }

    // parallel dedup: match.any groups equal indices
    unsigned mmask   = __match_any_sync(0xffffffffu, myidx);
    int      leader  = __ffs(mmask) - 1;
    unsigned leaders = __ballot_sync(0xffffffffu, leader == lane) & 0xFFFu;
    if (lane < 12) {
        int q = __popc(leaders & ((1u << leader) - 1u));
        sgrp[w][lane] = q;
        if (leader == lane) {
            scol[w][q]  = lane;
            smult[w][q] = __popc(mmask);
        }
        if (lane == 0) su[w] = __popc(leaders);
    }
    __syncwarp();

    // gather: STE columns A = fl(z + fl(zq - z)); loss from pre-STE zq vs z
    {
        double ls = 0.0;
        const float* zr = g_z + b * 768;
        for (int t = lane; t < 768; t += 32) {
            int j = t >> 6, i = t & 63;
            float a = emb[(size_t)sidx[w][j]*64 + i];
            float z = zr[t];
            double df = (double)a - (double)z;
            ls += df*df;
            sA[w][j][i] = __fadd_rn(z, __fsub_rn(a, z));
        }
#pragma unroll
        for (int o = 16; o; o >>= 1) ls += __shfl_down_sync(0xffffffffu, ls, o);
        if (lane == 0) wls[w] = ls;
    }
    for (int t = lane; t < 64; t += 32) sx[w][t] = x[b*64 + t];
    __syncwarp();

    const int u = su[w];
    const int npair = u*(u+1)/2;
    for (int t = lane; t < npair + u; t += 32) {
        if (t < npair) {
            int qa = 0, rem = t;
            while (rem >= u - qa) { rem -= (u - qa); qa++; }
            int qb = qa + rem;
            const float* ca = sA[w][scol[w][qa]];
            const float* cb = sA[w][scol[w][qb]];
            float s = 0.0f;
            for (int k = 0; k < 64; k++) s = __fmaf_rn(ca[k], cb[k], s);
            sG[w][qa][qb] = s; sG[w][qb][qa] = s;
        } else {
            int q2 = t - npair;
            const float* ca = sA[w][scol[w][q2]];
            float s = 0.0f;
            for (int k = 0; k < 64; k++) s = __fmaf_rn(ca[k], sx[w][k], s);
            sr[w][q2] = s;
        }
    }
    __syncwarp();

    // fp32 Cholesky (lower, in place)
    for (int p = 0; p < u; p++) {
        if (lane == 0) sG[w][p][p] = sqrtf(sG[w][p][p]);
        __syncwarp();
        float lpp = sG[w][p][p];
        if (lane > p && lane < u) sG[w][lane][p] /= lpp;
        __syncwarp();
        int m = u - p - 1;
        int tot = m*(m+1)/2;
        for (int t = lane; t < tot; t += 32) {
            int a = 0, rem = t;
            while (rem >= m - a) { rem -= (m - a); a++; }
            int j = p + 1 + a;
            int i = j + rem;
            sG[w][i][j] -= sG[w][i][p]*sG[w][j][p];
        }
        __syncwarp();
    }
    // lane-parallel triangular solves
    for (int p = 0; p < u; p++) {
        float c = (lane < p) ? sG[w][p][lane]*sy[w][lane] : 0.0f;
#pragma unroll
        for (int o = 8; o > 0; o >>= 1) c += __shfl_xor_sync(0xffffffffu, c, o, 16);
        if (lane == 0) sy[w][p] = (sr[w][p] - c) / sG[w][p][p];
        __syncwarp();
    }
    for (int p = u - 1; p >= 0; p--) {
        float c = (lane > p && lane < u) ? sG[w][lane][p]*sy[w][lane] : 0.0f;
#pragma unroll
        for (int o = 8; o > 0; o >>= 1) c += __shfl_xor_sync(0xffffffffu, c, o, 16);
        if (lane == 0) sy[w][p] = (sy[w][p] - c) / sG[w][p][p];
        __syncwarp();
    }
    // min-norm split across duplicates -> coeff
    if (lane < 12) {
        int q2 = sgrp[w][lane];
        float c = sy[w][q2] / (float)smult[w][q2];
        out[OFF_COEFF + b*12 + lane] = c;
        sc[w][lane] = c;
    }
    __syncwarp();
    // x_hat = A @ coeff (fp32)
    for (int i = lane; i < 64; i += 32) {
        float s = 0.0f;
#pragma unroll
        for (int j = 0; j < 12; j++) s = __fmaf_rn(sA[w][j][i], sc[w][j], s);
        out[OFF_XHAT + b*64 + i] = s;
    }

    __syncthreads();
    if (threadIdx.x == 0) {
        double s = 0.0;
        for (int k = 0; k < 8; k++) s += wls[k];
        g_lossp[blockIdx.x] = s;
    }
}

// ======================= scalars: loss, perplexity =======================
__global__ void k_final(float* __restrict__ out) {
    __shared__ double red[256];
    const int tid = threadIdx.x;
    double s = 0.0;
    for (int k = tid; k < NE; k += 256) {
        double p = (double)g_counts[k] / (double)BP;
        s += p * log(p + 1e-10);
    }
    red[tid] = s; __syncthreads();
    for (int o = 128; o; o >>= 1) { if (tid < o) red[tid] += red[tid + o]; __syncthreads(); }
    double perp = exp(-red[0]);
    __syncthreads();

    double ls = 0.0;
    for (int k = tid; k < 2048; k += 256) ls += g_lossp[k];
    red[tid] = ls; __syncthreads();
    for (int o = 128; o; o >>= 1) { if (tid < o) red[tid] += red[tid + o]; __syncthreads(); }

    if (tid == 0) {
        out[OFF_PERP] = (float)perp;
        out[OFF_LOSS] = (float)(red[0] * 1.25 / ((double)BP * 64.0));
    }
}

// ======================= launch =======================
extern "C" void kernel_launch(void* const* d_in, const int* in_sizes, int n_in,
                              void* d_out, int out_size) {
    const float* x      = (const float*)d_in[0];
    const float* enc_w1 = (const float*)d_in[1];
    const float* enc_b1 = (const float*)d_in[2];
    const float* res_w  = (const float*)d_in[3];
    const float* res_b  = (const float*)d_in[4];
    const float* res_g  = (const float*)d_in[5];
    const float* res_bt = (const float*)d_in[6];
    const float* enc_w2 = (const float*)d_in[7];
    const float* enc_b2 = (const float*)d_in[8];
    const float* emb    = (const float*)d_in[9];
    float* out = (float*)d_out;

    cudaFuncSetAttribute(k_exact, cudaFuncAttributeMaxDynamicSharedMemorySize, EX_SMEM);

    k_setup<<<(BP + 255)/256, 256>>>(emb);

    // encoder: Linear(64->512) -> 2x shared ResBlock -> Linear(512->768)
    k_gemm<0><<<dim3(4, 128), 256>>>(x, enc_w1, enc_b1, DENC, INDIM);
    for (int r = 0; r < 2; r++) {
        k_gemm<1><<<dim3(4, 128), 256>>>(nullptr, res_w, res_b, DENC, DENC);
        k_ln<<<BSZ, 128>>>(res_g, res_bt);
    }
    k_gemm<2><<<dim3(6, 128), 256>>>(nullptr, enc_w2, enc_b2, ZDIM, DENC);

    k_tc<<<BP/128, 256>>>();
    k_flag<<<BP/256, 256>>>();
    k_items<<<1, 32>>>();
    k_exact<<<296, 256, EX_SMEM>>>(emb);
    k_solve<<<BSZ/8, 256>>>(emb, x, out);
    k_final<<<1, 256>>>(out);
}